// round 6
// baseline (speedup 1.0000x reference)
#include <cuda_runtime.h>
#include <cuda_bf16.h>
#include <math.h>
#include <stdint.h>

#define N_NODES 50000
#define N_EDGES 800000
#define IN_F 256
#define OUT_F 32
#define NHEAD 8
#define EDGE_F 32
#define N_ETYPES 8
#define NEG_SLOPE 0.1f

#define HD (NHEAD * OUT_F)            // 256
#define OUT_ELEMS (N_NODES * HD)
#define ATT_ELEMS (N_EDGES * NHEAD)
#define SCAN_NB ((N_NODES + 1023) / 1024)

// ---------------- scratch ----------------
__device__ float     g_h[N_NODES * HD];
__device__ float     g_hl[N_NODES * NHEAD];
__device__ float     g_hr[N_NODES * NHEAD];
__device__ float     g_z[N_NODES * NHEAD];
__device__ float     g_sex[N_EDGES * NHEAD];   // exp(leaky(s)) at SORTED positions
__device__ float     g_he[N_ETYPES * NHEAD];
__device__ int       g_deg[N_NODES];
__device__ int       g_off[N_NODES];
__device__ int       g_wptr[N_NODES];
__device__ int       g_bsum[SCAN_NB];
__device__ int       g_pos[N_EDGES];           // edge -> sorted position
__device__ int       g_srow[N_EDGES];          // sorted position -> source node (row)
__device__ __nv_bfloat16 g_wh[HD * IN_F];
__device__ __nv_bfloat16 g_wl[HD * IN_F];

// ---------------- K_wprep ----------------
__global__ void k_wprep(const float* __restrict__ W) {
    int idx = blockIdx.x * blockDim.x + threadIdx.x;
    if (idx >= HD * IN_F) return;
    int n = idx >> 8, k = idx & 255;
    float w = W[k * HD + n];
    __nv_bfloat16 h = __float2bfloat16(w);
    float r = w - __bfloat162float(h);
    g_wh[n * IN_F + k] = h;
    g_wl[n * IN_F + k] = __float2bfloat16(r);
}

// ---------------- K1: he[t][h] ----------------
__global__ void k_he(const float* __restrict__ edge_emb,
                     const float* __restrict__ W_e,
                     const float* __restrict__ a_e) {
    int tid = threadIdx.x;
    if (tid >= N_ETYPES * NHEAD) return;
    int t = tid >> 3, h = tid & 7;
    float acc = 0.0f;
    for (int f = 0; f < EDGE_F; f++) {
        float ev = 0.0f;
        for (int k = 0; k < EDGE_F; k++)
            ev += edge_emb[t * EDGE_F + k] * W_e[k * (EDGE_F * NHEAD) + h * EDGE_F + f];
        acc += a_e[h * EDGE_F + f] * ev;
    }
    g_he[t * NHEAD + h] = acc;
}

// ---------------- K2: bf16 split-precision mma.sync GEMM + fused dots ----------
#define XPAD 40
#define WPAD 40
#define OFF_XH 0
#define OFF_XL (OFF_XH + 64 * XPAD)
#define OFF_WH (OFF_XL + 64 * XPAD)
#define OFF_WL (OFF_WH + 256 * WPAD)
#define SM_HALVES (OFF_WL + 256 * WPAD)

__device__ __forceinline__ void mma_bf16(float* d, uint32_t a0, uint32_t a1,
                                         uint32_t a2, uint32_t a3,
                                         uint32_t b0, uint32_t b1) {
    asm volatile(
        "mma.sync.aligned.m16n8k16.row.col.f32.bf16.bf16.f32 "
        "{%0,%1,%2,%3}, {%4,%5,%6,%7}, {%8,%9}, {%0,%1,%2,%3};"
        : "+f"(d[0]), "+f"(d[1]), "+f"(d[2]), "+f"(d[3])
        : "r"(a0), "r"(a1), "r"(a2), "r"(a3), "r"(b0), "r"(b1));
}
__device__ __forceinline__ float nanfix(float v) { return isnan(v) ? 0.0f : v; }

__global__ __launch_bounds__(256) void k_gemm_mma(const float* __restrict__ x,
                                                  const float* __restrict__ a_l,
                                                  const float* __restrict__ a_r) {
    extern __shared__ __align__(16) uint16_t sm[];
    uint16_t* sXh = sm + OFF_XH;
    uint16_t* sXl = sm + OFF_XL;
    uint16_t* sWh = sm + OFF_WH;
    uint16_t* sWl = sm + OFF_WL;

    int tid = threadIdx.x;
    int lane = tid & 31;
    int wid = tid >> 5;
    int warp_m = wid & 3;
    int warp_n = wid >> 2;
    int m0 = blockIdx.x * 64;

    float acc[16][4];
#pragma unroll
    for (int t = 0; t < 16; t++)
#pragma unroll
        for (int j = 0; j < 4; j++) acc[t][j] = 0.0f;

    for (int ks = 0; ks < 8; ks++) {
        int k0 = ks * 32;
        __syncthreads();
        {
            int r = tid >> 2, q = tid & 3;
            int gm = m0 + r;
            float v[8];
            if (gm < N_NODES) {
                const float4* src = reinterpret_cast<const float4*>(x + gm * IN_F + k0 + q * 8);
                float4 f0 = src[0], f1 = src[1];
                v[0] = f0.x; v[1] = f0.y; v[2] = f0.z; v[3] = f0.w;
                v[4] = f1.x; v[5] = f1.y; v[6] = f1.z; v[7] = f1.w;
            } else {
#pragma unroll
                for (int j = 0; j < 8; j++) v[j] = 0.0f;
            }
            uint32_t hi[4], lo[4];
#pragma unroll
            for (int j = 0; j < 4; j++) {
                __nv_bfloat16 h0 = __float2bfloat16(v[2 * j]);
                __nv_bfloat16 h1 = __float2bfloat16(v[2 * j + 1]);
                hi[j] = (uint32_t)__bfloat16_as_ushort(h0) |
                        ((uint32_t)__bfloat16_as_ushort(h1) << 16);
                __nv_bfloat16 l0 = __float2bfloat16(v[2 * j] - __bfloat162float(h0));
                __nv_bfloat16 l1 = __float2bfloat16(v[2 * j + 1] - __bfloat162float(h1));
                lo[j] = (uint32_t)__bfloat16_as_ushort(l0) |
                        ((uint32_t)__bfloat16_as_ushort(l1) << 16);
            }
            *reinterpret_cast<uint4*>(&sXh[r * XPAD + q * 8]) = make_uint4(hi[0], hi[1], hi[2], hi[3]);
            *reinterpret_cast<uint4*>(&sXl[r * XPAD + q * 8]) = make_uint4(lo[0], lo[1], lo[2], lo[3]);
        }
        {
            const uint4* ph = reinterpret_cast<const uint4*>(g_wh + tid * IN_F + k0);
            const uint4* pl = reinterpret_cast<const uint4*>(g_wl + tid * IN_F + k0);
#pragma unroll
            for (int j = 0; j < 4; j++) {
                *reinterpret_cast<uint4*>(&sWh[tid * WPAD + j * 8]) = ph[j];
                *reinterpret_cast<uint4*>(&sWl[tid * WPAD + j * 8]) = pl[j];
            }
        }
        __syncthreads();
#pragma unroll
        for (int kin = 0; kin < 32; kin += 16) {
            int c = (lane & 3) * 2 + kin;
            int ra = (warp_m * 16 + (lane >> 2)) * XPAD;
            uint32_t ah0 = *reinterpret_cast<uint32_t*>(&sXh[ra + c]);
            uint32_t ah1 = *reinterpret_cast<uint32_t*>(&sXh[ra + 8 * XPAD + c]);
            uint32_t ah2 = *reinterpret_cast<uint32_t*>(&sXh[ra + c + 8]);
            uint32_t ah3 = *reinterpret_cast<uint32_t*>(&sXh[ra + 8 * XPAD + c + 8]);
            uint32_t al0 = *reinterpret_cast<uint32_t*>(&sXl[ra + c]);
            uint32_t al1 = *reinterpret_cast<uint32_t*>(&sXl[ra + 8 * XPAD + c]);
            uint32_t al2 = *reinterpret_cast<uint32_t*>(&sXl[ra + c + 8]);
            uint32_t al3 = *reinterpret_cast<uint32_t*>(&sXl[ra + 8 * XPAD + c + 8]);
#pragma unroll
            for (int t = 0; t < 16; t++) {
                int nb = (warp_n * 128 + t * 8 + (lane >> 2)) * WPAD + (lane & 3) * 2 + kin;
                uint32_t bh0 = *reinterpret_cast<uint32_t*>(&sWh[nb]);
                uint32_t bh1 = *reinterpret_cast<uint32_t*>(&sWh[nb + 8]);
                uint32_t bl0 = *reinterpret_cast<uint32_t*>(&sWl[nb]);
                uint32_t bl1 = *reinterpret_cast<uint32_t*>(&sWl[nb + 8]);
                mma_bf16(acc[t], ah0, ah1, ah2, ah3, bh0, bh1);
                mma_bf16(acc[t], ah0, ah1, ah2, ah3, bl0, bl1);
                mma_bf16(acc[t], al0, al1, al2, al3, bh0, bh1);
            }
        }
    }

    int r = lane >> 2;
    int gr0 = m0 + warp_m * 16 + r;
    int gr1 = gr0 + 8;
    bool ok0 = (gr0 < N_NODES), ok1 = (gr1 < N_NODES);
    float dl0[4] = {0, 0, 0, 0}, dl1[4] = {0, 0, 0, 0};
    float dr0[4] = {0, 0, 0, 0}, dr1[4] = {0, 0, 0, 0};
#pragma unroll
    for (int t = 0; t < 16; t++) {
        int n = warp_n * 128 + t * 8 + (lane & 3) * 2;
        float v0 = nanfix(acc[t][0]), v1 = nanfix(acc[t][1]);
        float v2 = nanfix(acc[t][2]), v3 = nanfix(acc[t][3]);
        float alv0 = __ldg(&a_l[n]), alv1 = __ldg(&a_l[n + 1]);
        float arv0 = __ldg(&a_r[n]), arv1 = __ldg(&a_r[n + 1]);
        int hh = t >> 2;
        dl0[hh] += v0 * alv0 + v1 * alv1;
        dr0[hh] += v0 * arv0 + v1 * arv1;
        dl1[hh] += v2 * alv0 + v3 * alv1;
        dr1[hh] += v2 * arv0 + v3 * arv1;
        if (ok0) *reinterpret_cast<float2*>(&g_h[gr0 * HD + n]) = make_float2(v0, v1);
        if (ok1) *reinterpret_cast<float2*>(&g_h[gr1 * HD + n]) = make_float2(v2, v3);
    }
#pragma unroll
    for (int hh = 0; hh < 4; hh++) {
#pragma unroll
        for (int o = 1; o <= 2; o <<= 1) {
            dl0[hh] += __shfl_xor_sync(0xffffffffu, dl0[hh], o);
            dl1[hh] += __shfl_xor_sync(0xffffffffu, dl1[hh], o);
            dr0[hh] += __shfl_xor_sync(0xffffffffu, dr0[hh], o);
            dr1[hh] += __shfl_xor_sync(0xffffffffu, dr1[hh], o);
        }
    }
    if ((lane & 3) == 0) {
#pragma unroll
        for (int hh = 0; hh < 4; hh++) {
            int head = warp_n * 4 + hh;
            if (ok0) { g_hl[gr0 * NHEAD + head] = dl0[hh]; g_hr[gr0 * NHEAD + head] = dr0[hh]; }
            if (ok1) { g_hl[gr1 * NHEAD + head] = dl1[hh]; g_hr[gr1 * NHEAD + head] = dr1[hh]; }
        }
    }
}

// ---------------- CSR build ----------------
__global__ void k_zero_deg() {
    int i = blockIdx.x * blockDim.x + threadIdx.x;
    if (i < N_NODES) g_deg[i] = 0;
}
__global__ void k_hist(const int* __restrict__ col) {
    int e = blockIdx.x * blockDim.x + threadIdx.x;
    if (e < N_EDGES) atomicAdd(&g_deg[__ldg(&col[e])], 1);
}
__global__ __launch_bounds__(1024) void k_scan1() {
    __shared__ int sh[1024];
    int t = threadIdx.x;
    int idx = blockIdx.x * 1024 + t;
    int v = (idx < N_NODES) ? g_deg[idx] : 0;
    sh[t] = v;
    __syncthreads();
#pragma unroll
    for (int off = 1; off < 1024; off <<= 1) {
        int add = (t >= off) ? sh[t - off] : 0;
        __syncthreads();
        sh[t] += add;
        __syncthreads();
    }
    if (idx < N_NODES) g_off[idx] = sh[t] - v;
    if (t == 1023) g_bsum[blockIdx.x] = sh[t];
}
__global__ void k_scan2() {
    __shared__ int sh[64];
    int t = threadIdx.x;
    int v = (t < SCAN_NB) ? g_bsum[t] : 0;
    sh[t] = v;
    __syncthreads();
#pragma unroll
    for (int off = 1; off < 64; off <<= 1) {
        int add = (t >= off) ? sh[t - off] : 0;
        __syncthreads();
        sh[t] += add;
        __syncthreads();
    }
    if (t < SCAN_NB) g_bsum[t] = sh[t] - v;
}
__global__ __launch_bounds__(1024) void k_scan3() {
    int idx = blockIdx.x * 1024 + threadIdx.x;
    if (idx < N_NODES) {
        int o = g_off[idx] + g_bsum[idx >> 10];
        g_off[idx] = o;
        g_wptr[idx] = o;
    }
}
__global__ void k_scatter(const int* __restrict__ col, const int* __restrict__ row) {
    int e = blockIdx.x * blockDim.x + threadIdx.x;
    if (e >= N_EDGES) return;
    int c = __ldg(&col[e]);
    int pos = atomicAdd(&g_wptr[c], 1);
    g_pos[e] = pos;
    g_srow[pos] = __ldg(&row[e]);
}

// ---------------- K4: exp logits written at sorted positions ----------------
__global__ void k_edge(const int* __restrict__ row,
                       const int* __restrict__ col,
                       const int* __restrict__ tp) {
    int idx = blockIdx.x * blockDim.x + threadIdx.x;
    if (idx >= N_EDGES * NHEAD) return;
    int e = idx >> 3, h = idx & 7;
    int r = __ldg(&row[e]);
    int c = __ldg(&col[e]);
    int t = __ldg(&tp[e]);
    int pos = __ldg(&g_pos[e]);
    float s = g_hl[r * NHEAD + h] + g_hr[c * NHEAD + h] + g_he[t * NHEAD + h];
    s = (s > 0.0f) ? s : NEG_SLOPE * s;
    g_sex[pos * NHEAD + h] = __expf(s);
}

// ---------------- K5: per-node gather + normalize (sorted, chain depth 2) -------
__global__ __launch_bounds__(256) void k_aggregate(float* __restrict__ out) {
    int tid = threadIdx.x;
    int n = blockIdx.x * 4 + (tid >> 6);
    if (n >= N_NODES) return;
    int i = tid & 63;
    int head = i >> 3;

    int base = g_off[n];
    int deg = g_deg[n];
    const float4* h4 = reinterpret_cast<const float4*>(g_h);

    float4 acc = make_float4(0.f, 0.f, 0.f, 0.f);
    float zacc = 0.f;
    int k = 0;
    for (; k + 2 <= deg; k += 2) {
        int r0 = __ldg(&g_srow[base + k]);
        int r1 = __ldg(&g_srow[base + k + 1]);
        float ex0 = __ldg(&g_sex[(base + k) * NHEAD + head]);
        float ex1 = __ldg(&g_sex[(base + k + 1) * NHEAD + head]);
        float4 v0 = h4[r0 * 64 + i];
        float4 v1 = h4[r1 * 64 + i];
        acc.x += ex0 * v0.x + ex1 * v1.x;
        acc.y += ex0 * v0.y + ex1 * v1.y;
        acc.z += ex0 * v0.z + ex1 * v1.z;
        acc.w += ex0 * v0.w + ex1 * v1.w;
        zacc += ex0 + ex1;
    }
    if (k < deg) {
        int r0 = __ldg(&g_srow[base + k]);
        float ex0 = __ldg(&g_sex[(base + k) * NHEAD + head]);
        float4 v0 = h4[r0 * 64 + i];
        acc.x += ex0 * v0.x; acc.y += ex0 * v0.y;
        acc.z += ex0 * v0.z; acc.w += ex0 * v0.w;
        zacc += ex0;
    }
    float inv = (deg > 0) ? (1.0f / zacc) : 0.0f;
    reinterpret_cast<float4*>(out)[n * 64 + i] =
        make_float4(acc.x * inv, acc.y * inv, acc.z * inv, acc.w * inv);
    if ((i & 7) == 0) g_z[n * NHEAD + head] = zacc;
}

// ---------------- K6: att output (original edge order) ----------------
__global__ void k_attout(const int* __restrict__ col, float* __restrict__ attOut) {
    int idx = blockIdx.x * blockDim.x + threadIdx.x;
    if (idx >= N_EDGES * NHEAD) return;
    int e = idx >> 3, h = idx & 7;
    int c = __ldg(&col[e]);
    int pos = __ldg(&g_pos[e]);
    attOut[idx] = g_sex[pos * NHEAD + h] / g_z[c * NHEAD + h];
}

// ---------------- launch ---------------------------------------------------------
extern "C" void kernel_launch(void* const* d_in, const int* in_sizes, int n_in,
                              void* d_out, int out_size) {
    const float* x        = (const float*)d_in[0];
    const float* W        = (const float*)d_in[1];
    const float* W_e      = (const float*)d_in[2];
    const float* edge_emb = (const float*)d_in[3];
    const float* a_l      = (const float*)d_in[4];
    const float* a_r      = (const float*)d_in[5];
    const float* a_e      = (const float*)d_in[6];
    const int*   row      = (const int*)d_in[7];
    const int*   col      = (const int*)d_in[8];
    const int*   tp       = (const int*)d_in[9];

    float* out = (float*)d_out;
    float* attOut = (out_size >= OUT_ELEMS + ATT_ELEMS) ? out + OUT_ELEMS : nullptr;

    static cudaStream_t s1 = nullptr;
    static cudaEvent_t evFork = nullptr, evCsr = nullptr;
    static int inited = 0;
    if (!inited) {
        cudaFuncSetAttribute(k_gemm_mma, cudaFuncAttributeMaxDynamicSharedMemorySize,
                             SM_HALVES * 2);
        cudaStreamCreateWithFlags(&s1, cudaStreamNonBlocking);
        cudaEventCreateWithFlags(&evFork, cudaEventDisableTiming);
        cudaEventCreateWithFlags(&evCsr, cudaEventDisableTiming);
        inited = 1;
    }

    // fork: CSR build on s1, GEMM path on default stream
    cudaEventRecord(evFork, 0);
    cudaStreamWaitEvent(s1, evFork, 0);

    k_zero_deg<<<(N_NODES + 255) / 256, 256, 0, s1>>>();
    k_hist<<<(N_EDGES + 255) / 256, 256, 0, s1>>>(col);
    k_scan1<<<SCAN_NB, 1024, 0, s1>>>();
    k_scan2<<<1, 64, 0, s1>>>();
    k_scan3<<<SCAN_NB, 1024, 0, s1>>>();
    k_scatter<<<(N_EDGES + 255) / 256, 256, 0, s1>>>(col, row);
    cudaEventRecord(evCsr, s1);

    k_wprep<<<(HD * IN_F + 255) / 256, 256>>>(W);
    k_he<<<1, 64>>>(edge_emb, W_e, a_e);
    k_gemm_mma<<<(N_NODES + 63) / 64, 256, SM_HALVES * 2>>>(x, a_l, a_r);

    // join: edge kernel needs both branches
    cudaStreamWaitEvent(0, evCsr, 0);
    k_edge<<<(N_EDGES * NHEAD + 255) / 256, 256>>>(row, col, tp);
    k_aggregate<<<(N_NODES + 3) / 4, 256>>>(out);
    if (attOut)
        k_attout<<<(N_EDGES * NHEAD + 255) / 256, 256>>>(col, attOut);
}

// round 7
// speedup vs baseline: 1.3854x; 1.3854x over previous
#include <cuda_runtime.h>
#include <cuda_bf16.h>
#include <math.h>
#include <stdint.h>

#define N_NODES 50000
#define N_EDGES 800000
#define IN_F 256
#define OUT_F 32
#define NHEAD 8
#define EDGE_F 32
#define N_ETYPES 8
#define NEG_SLOPE 0.1f

#define HD (NHEAD * OUT_F)            // 256
#define OUT_ELEMS (N_NODES * HD)
#define ATT_ELEMS (N_EDGES * NHEAD)
#define SCAN_NB ((N_NODES + 1023) / 1024)

// ---------------- scratch ----------------
__device__ float     g_h[N_NODES * HD];
__device__ float     g_hl[N_NODES * NHEAD];
__device__ float     g_hr[N_NODES * NHEAD];
__device__ float     g_z[N_NODES * NHEAD];
__device__ float     g_s[N_EDGES * NHEAD];     // exp(leaky(s)) in EDGE order
__device__ float     g_he[N_ETYPES * NHEAD];
__device__ int       g_deg[N_NODES];
__device__ int       g_off[N_NODES];
__device__ int       g_wptr[N_NODES];
__device__ int       g_bsum[SCAN_NB];
__device__ int       g_eidx[N_EDGES];          // sorted pos -> edge id
__device__ int       g_srow[N_EDGES];          // sorted pos -> source node
__device__ __nv_bfloat16 g_wh[HD * IN_F];
__device__ __nv_bfloat16 g_wl[HD * IN_F];

// ---------------- K_wprep ----------------
__global__ void k_wprep(const float* __restrict__ W) {
    int idx = blockIdx.x * blockDim.x + threadIdx.x;
    if (idx >= HD * IN_F) return;
    int n = idx >> 8, k = idx & 255;
    float w = W[k * HD + n];
    __nv_bfloat16 h = __float2bfloat16(w);
    float r = w - __bfloat162float(h);
    g_wh[n * IN_F + k] = h;
    g_wl[n * IN_F + k] = __float2bfloat16(r);
}

// ---------------- K1: he[t][h] ----------------
__global__ void k_he(const float* __restrict__ edge_emb,
                     const float* __restrict__ W_e,
                     const float* __restrict__ a_e) {
    int tid = threadIdx.x;
    if (tid >= N_ETYPES * NHEAD) return;
    int t = tid >> 3, h = tid & 7;
    float acc = 0.0f;
    for (int f = 0; f < EDGE_F; f++) {
        float ev = 0.0f;
        for (int k = 0; k < EDGE_F; k++)
            ev += edge_emb[t * EDGE_F + k] * W_e[k * (EDGE_F * NHEAD) + h * EDGE_F + f];
        acc += a_e[h * EDGE_F + f] * ev;
    }
    g_he[t * NHEAD + h] = acc;
}

// ---------------- K2: bf16 split-precision mma.sync GEMM + fused dots ----------
#define XPAD 40
#define WPAD 40
#define OFF_XH 0
#define OFF_XL (OFF_XH + 64 * XPAD)
#define OFF_WH (OFF_XL + 64 * XPAD)
#define OFF_WL (OFF_WH + 256 * WPAD)
#define SM_HALVES (OFF_WL + 256 * WPAD)

__device__ __forceinline__ void mma_bf16(float* d, uint32_t a0, uint32_t a1,
                                         uint32_t a2, uint32_t a3,
                                         uint32_t b0, uint32_t b1) {
    asm volatile(
        "mma.sync.aligned.m16n8k16.row.col.f32.bf16.bf16.f32 "
        "{%0,%1,%2,%3}, {%4,%5,%6,%7}, {%8,%9}, {%0,%1,%2,%3};"
        : "+f"(d[0]), "+f"(d[1]), "+f"(d[2]), "+f"(d[3])
        : "r"(a0), "r"(a1), "r"(a2), "r"(a3), "r"(b0), "r"(b1));
}
__device__ __forceinline__ float nanfix(float v) { return isnan(v) ? 0.0f : v; }

__global__ __launch_bounds__(256) void k_gemm_mma(const float* __restrict__ x,
                                                  const float* __restrict__ a_l,
                                                  const float* __restrict__ a_r) {
    extern __shared__ __align__(16) uint16_t sm[];
    uint16_t* sXh = sm + OFF_XH;
    uint16_t* sXl = sm + OFF_XL;
    uint16_t* sWh = sm + OFF_WH;
    uint16_t* sWl = sm + OFF_WL;

    int tid = threadIdx.x;
    int lane = tid & 31;
    int wid = tid >> 5;
    int warp_m = wid & 3;
    int warp_n = wid >> 2;
    int m0 = blockIdx.x * 64;

    float acc[16][4];
#pragma unroll
    for (int t = 0; t < 16; t++)
#pragma unroll
        for (int j = 0; j < 4; j++) acc[t][j] = 0.0f;

    for (int ks = 0; ks < 8; ks++) {
        int k0 = ks * 32;
        __syncthreads();
        {
            int r = tid >> 2, q = tid & 3;
            int gm = m0 + r;
            float v[8];
            if (gm < N_NODES) {
                const float4* src = reinterpret_cast<const float4*>(x + gm * IN_F + k0 + q * 8);
                float4 f0 = src[0], f1 = src[1];
                v[0] = f0.x; v[1] = f0.y; v[2] = f0.z; v[3] = f0.w;
                v[4] = f1.x; v[5] = f1.y; v[6] = f1.z; v[7] = f1.w;
            } else {
#pragma unroll
                for (int j = 0; j < 8; j++) v[j] = 0.0f;
            }
            uint32_t hi[4], lo[4];
#pragma unroll
            for (int j = 0; j < 4; j++) {
                __nv_bfloat16 h0 = __float2bfloat16(v[2 * j]);
                __nv_bfloat16 h1 = __float2bfloat16(v[2 * j + 1]);
                hi[j] = (uint32_t)__bfloat16_as_ushort(h0) |
                        ((uint32_t)__bfloat16_as_ushort(h1) << 16);
                __nv_bfloat16 l0 = __float2bfloat16(v[2 * j] - __bfloat162float(h0));
                __nv_bfloat16 l1 = __float2bfloat16(v[2 * j + 1] - __bfloat162float(h1));
                lo[j] = (uint32_t)__bfloat16_as_ushort(l0) |
                        ((uint32_t)__bfloat16_as_ushort(l1) << 16);
            }
            *reinterpret_cast<uint4*>(&sXh[r * XPAD + q * 8]) = make_uint4(hi[0], hi[1], hi[2], hi[3]);
            *reinterpret_cast<uint4*>(&sXl[r * XPAD + q * 8]) = make_uint4(lo[0], lo[1], lo[2], lo[3]);
        }
        {
            const uint4* ph = reinterpret_cast<const uint4*>(g_wh + tid * IN_F + k0);
            const uint4* pl = reinterpret_cast<const uint4*>(g_wl + tid * IN_F + k0);
#pragma unroll
            for (int j = 0; j < 4; j++) {
                *reinterpret_cast<uint4*>(&sWh[tid * WPAD + j * 8]) = ph[j];
                *reinterpret_cast<uint4*>(&sWl[tid * WPAD + j * 8]) = pl[j];
            }
        }
        __syncthreads();
#pragma unroll
        for (int kin = 0; kin < 32; kin += 16) {
            int c = (lane & 3) * 2 + kin;
            int ra = (warp_m * 16 + (lane >> 2)) * XPAD;
            uint32_t ah0 = *reinterpret_cast<uint32_t*>(&sXh[ra + c]);
            uint32_t ah1 = *reinterpret_cast<uint32_t*>(&sXh[ra + 8 * XPAD + c]);
            uint32_t ah2 = *reinterpret_cast<uint32_t*>(&sXh[ra + c + 8]);
            uint32_t ah3 = *reinterpret_cast<uint32_t*>(&sXh[ra + 8 * XPAD + c + 8]);
            uint32_t al0 = *reinterpret_cast<uint32_t*>(&sXl[ra + c]);
            uint32_t al1 = *reinterpret_cast<uint32_t*>(&sXl[ra + 8 * XPAD + c]);
            uint32_t al2 = *reinterpret_cast<uint32_t*>(&sXl[ra + c + 8]);
            uint32_t al3 = *reinterpret_cast<uint32_t*>(&sXl[ra + 8 * XPAD + c + 8]);
#pragma unroll
            for (int t = 0; t < 16; t++) {
                int nb = (warp_n * 128 + t * 8 + (lane >> 2)) * WPAD + (lane & 3) * 2 + kin;
                uint32_t bh0 = *reinterpret_cast<uint32_t*>(&sWh[nb]);
                uint32_t bh1 = *reinterpret_cast<uint32_t*>(&sWh[nb + 8]);
                uint32_t bl0 = *reinterpret_cast<uint32_t*>(&sWl[nb]);
                uint32_t bl1 = *reinterpret_cast<uint32_t*>(&sWl[nb + 8]);
                mma_bf16(acc[t], ah0, ah1, ah2, ah3, bh0, bh1);
                mma_bf16(acc[t], ah0, ah1, ah2, ah3, bl0, bl1);
                mma_bf16(acc[t], al0, al1, al2, al3, bh0, bh1);
            }
        }
    }

    int r = lane >> 2;
    int gr0 = m0 + warp_m * 16 + r;
    int gr1 = gr0 + 8;
    bool ok0 = (gr0 < N_NODES), ok1 = (gr1 < N_NODES);
    float dl0[4] = {0, 0, 0, 0}, dl1[4] = {0, 0, 0, 0};
    float dr0[4] = {0, 0, 0, 0}, dr1[4] = {0, 0, 0, 0};
#pragma unroll
    for (int t = 0; t < 16; t++) {
        int n = warp_n * 128 + t * 8 + (lane & 3) * 2;
        float v0 = nanfix(acc[t][0]), v1 = nanfix(acc[t][1]);
        float v2 = nanfix(acc[t][2]), v3 = nanfix(acc[t][3]);
        float alv0 = __ldg(&a_l[n]), alv1 = __ldg(&a_l[n + 1]);
        float arv0 = __ldg(&a_r[n]), arv1 = __ldg(&a_r[n + 1]);
        int hh = t >> 2;
        dl0[hh] += v0 * alv0 + v1 * alv1;
        dr0[hh] += v0 * arv0 + v1 * arv1;
        dl1[hh] += v2 * alv0 + v3 * alv1;
        dr1[hh] += v2 * arv0 + v3 * arv1;
        if (ok0) *reinterpret_cast<float2*>(&g_h[gr0 * HD + n]) = make_float2(v0, v1);
        if (ok1) *reinterpret_cast<float2*>(&g_h[gr1 * HD + n]) = make_float2(v2, v3);
    }
#pragma unroll
    for (int hh = 0; hh < 4; hh++) {
#pragma unroll
        for (int o = 1; o <= 2; o <<= 1) {
            dl0[hh] += __shfl_xor_sync(0xffffffffu, dl0[hh], o);
            dl1[hh] += __shfl_xor_sync(0xffffffffu, dl1[hh], o);
            dr0[hh] += __shfl_xor_sync(0xffffffffu, dr0[hh], o);
            dr1[hh] += __shfl_xor_sync(0xffffffffu, dr1[hh], o);
        }
    }
    if ((lane & 3) == 0) {
#pragma unroll
        for (int hh = 0; hh < 4; hh++) {
            int head = warp_n * 4 + hh;
            if (ok0) { g_hl[gr0 * NHEAD + head] = dl0[hh]; g_hr[gr0 * NHEAD + head] = dr0[hh]; }
            if (ok1) { g_hl[gr1 * NHEAD + head] = dl1[hh]; g_hr[gr1 * NHEAD + head] = dr1[hh]; }
        }
    }
}

// ---------------- CSR build ----------------
__global__ void k_zero_deg() {
    int i = blockIdx.x * blockDim.x + threadIdx.x;
    if (i < N_NODES) g_deg[i] = 0;
}
__global__ void k_hist(const int* __restrict__ col) {
    int e = blockIdx.x * blockDim.x + threadIdx.x;
    if (e < N_EDGES) atomicAdd(&g_deg[__ldg(&col[e])], 1);
}
__global__ __launch_bounds__(1024) void k_scan1() {
    __shared__ int sh[1024];
    int t = threadIdx.x;
    int idx = blockIdx.x * 1024 + t;
    int v = (idx < N_NODES) ? g_deg[idx] : 0;
    sh[t] = v;
    __syncthreads();
#pragma unroll
    for (int off = 1; off < 1024; off <<= 1) {
        int add = (t >= off) ? sh[t - off] : 0;
        __syncthreads();
        sh[t] += add;
        __syncthreads();
    }
    if (idx < N_NODES) g_off[idx] = sh[t] - v;
    if (t == 1023) g_bsum[blockIdx.x] = sh[t];
}
__global__ void k_scan2() {
    __shared__ int sh[64];
    int t = threadIdx.x;
    int v = (t < SCAN_NB) ? g_bsum[t] : 0;
    sh[t] = v;
    __syncthreads();
#pragma unroll
    for (int off = 1; off < 64; off <<= 1) {
        int add = (t >= off) ? sh[t - off] : 0;
        __syncthreads();
        sh[t] += add;
        __syncthreads();
    }
    if (t < SCAN_NB) g_bsum[t] = sh[t] - v;
}
__global__ __launch_bounds__(1024) void k_scan3() {
    int idx = blockIdx.x * 1024 + threadIdx.x;
    if (idx < N_NODES) {
        int o = g_off[idx] + g_bsum[idx >> 10];
        g_off[idx] = o;
        g_wptr[idx] = o;
    }
}
__global__ void k_scatter(const int* __restrict__ col, const int* __restrict__ row) {
    int e = blockIdx.x * blockDim.x + threadIdx.x;
    if (e >= N_EDGES) return;
    int c = __ldg(&col[e]);
    int pos = atomicAdd(&g_wptr[c], 1);
    g_eidx[pos] = e;
    g_srow[pos] = __ldg(&row[e]);
}

// ---------------- K4: ex = exp(leaky(hl[row]+hr[col]+he[tp])), edge order -------
__global__ void k_edge(const int* __restrict__ row,
                       const int* __restrict__ col,
                       const int* __restrict__ tp) {
    int idx = blockIdx.x * blockDim.x + threadIdx.x;
    if (idx >= N_EDGES * NHEAD) return;
    int e = idx >> 3, h = idx & 7;
    int r = __ldg(&row[e]);
    int c = __ldg(&col[e]);
    int t = __ldg(&tp[e]);
    float s = g_hl[r * NHEAD + h] + g_hr[c * NHEAD + h] + g_he[t * NHEAD + h];
    s = (s > 0.0f) ? s : NEG_SLOPE * s;
    g_s[idx] = __expf(s);
}

// ---------------- K5: per-node gather + normalize (unroll 4, chain depth 2) -----
__global__ __launch_bounds__(256) void k_aggregate(float* __restrict__ out) {
    int tid = threadIdx.x;
    int n = blockIdx.x * 4 + (tid >> 6);
    if (n >= N_NODES) return;
    int i = tid & 63;
    int head = i >> 3;

    int base = g_off[n];
    int deg = g_deg[n];
    const float4* h4 = reinterpret_cast<const float4*>(g_h);

    float4 acc = make_float4(0.f, 0.f, 0.f, 0.f);
    float zacc = 0.f;
    int k = 0;
    for (; k + 4 <= deg; k += 4) {
        int e0 = __ldg(&g_eidx[base + k]);
        int e1 = __ldg(&g_eidx[base + k + 1]);
        int e2 = __ldg(&g_eidx[base + k + 2]);
        int e3 = __ldg(&g_eidx[base + k + 3]);
        int r0 = __ldg(&g_srow[base + k]);
        int r1 = __ldg(&g_srow[base + k + 1]);
        int r2 = __ldg(&g_srow[base + k + 2]);
        int r3 = __ldg(&g_srow[base + k + 3]);
        float ex0 = __ldg(&g_s[e0 * NHEAD + head]);
        float ex1 = __ldg(&g_s[e1 * NHEAD + head]);
        float ex2 = __ldg(&g_s[e2 * NHEAD + head]);
        float ex3 = __ldg(&g_s[e3 * NHEAD + head]);
        float4 v0 = h4[r0 * 64 + i];
        float4 v1 = h4[r1 * 64 + i];
        float4 v2 = h4[r2 * 64 + i];
        float4 v3 = h4[r3 * 64 + i];
        acc.x += ex0 * v0.x + ex1 * v1.x + ex2 * v2.x + ex3 * v3.x;
        acc.y += ex0 * v0.y + ex1 * v1.y + ex2 * v2.y + ex3 * v3.y;
        acc.z += ex0 * v0.z + ex1 * v1.z + ex2 * v2.z + ex3 * v3.z;
        acc.w += ex0 * v0.w + ex1 * v1.w + ex2 * v2.w + ex3 * v3.w;
        zacc += (ex0 + ex1) + (ex2 + ex3);
    }
    for (; k < deg; k++) {
        int e0 = __ldg(&g_eidx[base + k]);
        int r0 = __ldg(&g_srow[base + k]);
        float ex0 = __ldg(&g_s[e0 * NHEAD + head]);
        float4 v0 = h4[r0 * 64 + i];
        acc.x += ex0 * v0.x; acc.y += ex0 * v0.y;
        acc.z += ex0 * v0.z; acc.w += ex0 * v0.w;
        zacc += ex0;
    }
    float inv = (deg > 0) ? (1.0f / zacc) : 0.0f;
    reinterpret_cast<float4*>(out)[n * 64 + i] =
        make_float4(acc.x * inv, acc.y * inv, acc.z * inv, acc.w * inv);
    if ((i & 7) == 0) g_z[n * NHEAD + head] = zacc;
}

// ---------------- K6: att output (edge order) ----------------
__global__ void k_attout(const int* __restrict__ col, float* __restrict__ attOut) {
    int idx = blockIdx.x * blockDim.x + threadIdx.x;
    if (idx >= N_EDGES * NHEAD) return;
    int e = idx >> 3, h = idx & 7;
    int c = __ldg(&col[e]);
    attOut[idx] = g_s[idx] / g_z[c * NHEAD + h];
}

// ---------------- launch ---------------------------------------------------------
extern "C" void kernel_launch(void* const* d_in, const int* in_sizes, int n_in,
                              void* d_out, int out_size) {
    const float* x        = (const float*)d_in[0];
    const float* W        = (const float*)d_in[1];
    const float* W_e      = (const float*)d_in[2];
    const float* edge_emb = (const float*)d_in[3];
    const float* a_l      = (const float*)d_in[4];
    const float* a_r      = (const float*)d_in[5];
    const float* a_e      = (const float*)d_in[6];
    const int*   row      = (const int*)d_in[7];
    const int*   col      = (const int*)d_in[8];
    const int*   tp       = (const int*)d_in[9];

    float* out = (float*)d_out;
    float* attOut = (out_size >= OUT_ELEMS + ATT_ELEMS) ? out + OUT_ELEMS : nullptr;

    static int inited = 0;
    if (!inited) {
        cudaFuncSetAttribute(k_gemm_mma, cudaFuncAttributeMaxDynamicSharedMemorySize,
                             SM_HALVES * 2);
        inited = 1;
    }

    k_wprep<<<(HD * IN_F + 255) / 256, 256>>>(W);
    k_he<<<1, 64>>>(edge_emb, W_e, a_e);
    k_gemm_mma<<<(N_NODES + 63) / 64, 256, SM_HALVES * 2>>>(x, a_l, a_r);

    k_zero_deg<<<(N_NODES + 255) / 256, 256>>>();
    k_hist<<<(N_EDGES + 255) / 256, 256>>>(col);
    k_scan1<<<SCAN_NB, 1024>>>();
    k_scan2<<<1, 64>>>();
    k_scan3<<<SCAN_NB, 1024>>>();
    k_scatter<<<(N_EDGES + 255) / 256, 256>>>(col, row);

    k_edge<<<(N_EDGES * NHEAD + 255) / 256, 256>>>(row, col, tp);
    k_aggregate<<<(N_NODES + 3) / 4, 256>>>(out);
    if (attOut)
        k_attout<<<(N_EDGES * NHEAD + 255) / 256, 256>>>(col, attOut);
}

// round 8
// speedup vs baseline: 1.4386x; 1.0384x over previous
#include <cuda_runtime.h>
#include <cuda_bf16.h>
#include <cuda_fp16.h>
#include <math.h>
#include <stdint.h>

#define N_NODES 50000
#define N_EDGES 800000
#define IN_F 256
#define OUT_F 32
#define NHEAD 8
#define EDGE_F 32
#define N_ETYPES 8
#define NEG_SLOPE 0.1f

#define HD (NHEAD * OUT_F)            // 256
#define OUT_ELEMS (N_NODES * HD)
#define ATT_ELEMS (N_EDGES * NHEAD)
#define SCAN_NB ((N_NODES + 1023) / 1024)

// ---------------- scratch ----------------
__device__ __half    g_h16[N_NODES * HD];      // h in fp16 (only consumer: aggregation)
__device__ float     g_hl[N_NODES * NHEAD];
__device__ float     g_hr[N_NODES * NHEAD];
__device__ float     g_z[N_NODES * NHEAD];
__device__ float     g_s[N_EDGES * NHEAD];     // exp(leaky(s)) in EDGE order
__device__ float     g_he[N_ETYPES * NHEAD];
__device__ int       g_deg[N_NODES];
__device__ int       g_off[N_NODES];
__device__ int       g_wptr[N_NODES];
__device__ int       g_bsum[SCAN_NB];
__device__ int       g_eidx[N_EDGES];          // sorted pos -> edge id
__device__ int       g_srow[N_EDGES];          // sorted pos -> source node
__device__ __nv_bfloat16 g_wh[HD * IN_F];
__device__ __nv_bfloat16 g_wl[HD * IN_F];

// ---------------- K_wprep (+ zero deg) ----------------
__global__ void k_wprep(const float* __restrict__ W) {
    int idx = blockIdx.x * blockDim.x + threadIdx.x;
    if (idx < N_NODES) g_deg[idx] = 0;
    if (idx >= HD * IN_F) return;
    int n = idx >> 8, k = idx & 255;
    float w = W[k * HD + n];
    __nv_bfloat16 h = __float2bfloat16(w);
    float r = w - __bfloat162float(h);
    g_wh[n * IN_F + k] = h;
    g_wl[n * IN_F + k] = __float2bfloat16(r);
}

// ---------------- K1: he[t][h] ----------------
__global__ void k_he(const float* __restrict__ edge_emb,
                     const float* __restrict__ W_e,
                     const float* __restrict__ a_e) {
    int tid = threadIdx.x;
    if (tid >= N_ETYPES * NHEAD) return;
    int t = tid >> 3, h = tid & 7;
    float acc = 0.0f;
    for (int f = 0; f < EDGE_F; f++) {
        float ev = 0.0f;
        for (int k = 0; k < EDGE_F; k++)
            ev += edge_emb[t * EDGE_F + k] * W_e[k * (EDGE_F * NHEAD) + h * EDGE_F + f];
        acc += a_e[h * EDGE_F + f] * ev;
    }
    g_he[t * NHEAD + h] = acc;
}

// ---------------- K2: bf16 split-precision mma.sync GEMM + fused dots ----------
#define XPAD 40
#define WPAD 40
#define OFF_XH 0
#define OFF_XL (OFF_XH + 64 * XPAD)
#define OFF_WH (OFF_XL + 64 * XPAD)
#define OFF_WL (OFF_WH + 256 * WPAD)
#define SM_HALVES (OFF_WL + 256 * WPAD)

__device__ __forceinline__ void mma_bf16(float* d, uint32_t a0, uint32_t a1,
                                         uint32_t a2, uint32_t a3,
                                         uint32_t b0, uint32_t b1) {
    asm volatile(
        "mma.sync.aligned.m16n8k16.row.col.f32.bf16.bf16.f32 "
        "{%0,%1,%2,%3}, {%4,%5,%6,%7}, {%8,%9}, {%0,%1,%2,%3};"
        : "+f"(d[0]), "+f"(d[1]), "+f"(d[2]), "+f"(d[3])
        : "r"(a0), "r"(a1), "r"(a2), "r"(a3), "r"(b0), "r"(b1));
}
__device__ __forceinline__ float nanfix(float v) { return isnan(v) ? 0.0f : v; }

__global__ __launch_bounds__(256) void k_gemm_mma(const float* __restrict__ x,
                                                  const float* __restrict__ a_l,
                                                  const float* __restrict__ a_r) {
    extern __shared__ __align__(16) uint16_t sm[];
    uint16_t* sXh = sm + OFF_XH;
    uint16_t* sXl = sm + OFF_XL;
    uint16_t* sWh = sm + OFF_WH;
    uint16_t* sWl = sm + OFF_WL;

    int tid = threadIdx.x;
    int lane = tid & 31;
    int wid = tid >> 5;
    int warp_m = wid & 3;
    int warp_n = wid >> 2;
    int m0 = blockIdx.x * 64;

    float acc[16][4];
#pragma unroll
    for (int t = 0; t < 16; t++)
#pragma unroll
        for (int j = 0; j < 4; j++) acc[t][j] = 0.0f;

    for (int ks = 0; ks < 8; ks++) {
        int k0 = ks * 32;
        __syncthreads();
        {
            int r = tid >> 2, q = tid & 3;
            int gm = m0 + r;
            float v[8];
            if (gm < N_NODES) {
                const float4* src = reinterpret_cast<const float4*>(x + gm * IN_F + k0 + q * 8);
                float4 f0 = src[0], f1 = src[1];
                v[0] = f0.x; v[1] = f0.y; v[2] = f0.z; v[3] = f0.w;
                v[4] = f1.x; v[5] = f1.y; v[6] = f1.z; v[7] = f1.w;
            } else {
#pragma unroll
                for (int j = 0; j < 8; j++) v[j] = 0.0f;
            }
            uint32_t hi[4], lo[4];
#pragma unroll
            for (int j = 0; j < 4; j++) {
                __nv_bfloat16 h0 = __float2bfloat16(v[2 * j]);
                __nv_bfloat16 h1 = __float2bfloat16(v[2 * j + 1]);
                hi[j] = (uint32_t)__bfloat16_as_ushort(h0) |
                        ((uint32_t)__bfloat16_as_ushort(h1) << 16);
                __nv_bfloat16 l0 = __float2bfloat16(v[2 * j] - __bfloat162float(h0));
                __nv_bfloat16 l1 = __float2bfloat16(v[2 * j + 1] - __bfloat162float(h1));
                lo[j] = (uint32_t)__bfloat16_as_ushort(l0) |
                        ((uint32_t)__bfloat16_as_ushort(l1) << 16);
            }
            *reinterpret_cast<uint4*>(&sXh[r * XPAD + q * 8]) = make_uint4(hi[0], hi[1], hi[2], hi[3]);
            *reinterpret_cast<uint4*>(&sXl[r * XPAD + q * 8]) = make_uint4(lo[0], lo[1], lo[2], lo[3]);
        }
        {
            const uint4* ph = reinterpret_cast<const uint4*>(g_wh + tid * IN_F + k0);
            const uint4* pl = reinterpret_cast<const uint4*>(g_wl + tid * IN_F + k0);
#pragma unroll
            for (int j = 0; j < 4; j++) {
                *reinterpret_cast<uint4*>(&sWh[tid * WPAD + j * 8]) = ph[j];
                *reinterpret_cast<uint4*>(&sWl[tid * WPAD + j * 8]) = pl[j];
            }
        }
        __syncthreads();
#pragma unroll
        for (int kin = 0; kin < 32; kin += 16) {
            int c = (lane & 3) * 2 + kin;
            int ra = (warp_m * 16 + (lane >> 2)) * XPAD;
            uint32_t ah0 = *reinterpret_cast<uint32_t*>(&sXh[ra + c]);
            uint32_t ah1 = *reinterpret_cast<uint32_t*>(&sXh[ra + 8 * XPAD + c]);
            uint32_t ah2 = *reinterpret_cast<uint32_t*>(&sXh[ra + c + 8]);
            uint32_t ah3 = *reinterpret_cast<uint32_t*>(&sXh[ra + 8 * XPAD + c + 8]);
            uint32_t al0 = *reinterpret_cast<uint32_t*>(&sXl[ra + c]);
            uint32_t al1 = *reinterpret_cast<uint32_t*>(&sXl[ra + 8 * XPAD + c]);
            uint32_t al2 = *reinterpret_cast<uint32_t*>(&sXl[ra + c + 8]);
            uint32_t al3 = *reinterpret_cast<uint32_t*>(&sXl[ra + 8 * XPAD + c + 8]);
#pragma unroll
            for (int t = 0; t < 16; t++) {
                int nb = (warp_n * 128 + t * 8 + (lane >> 2)) * WPAD + (lane & 3) * 2 + kin;
                uint32_t bh0 = *reinterpret_cast<uint32_t*>(&sWh[nb]);
                uint32_t bh1 = *reinterpret_cast<uint32_t*>(&sWh[nb + 8]);
                uint32_t bl0 = *reinterpret_cast<uint32_t*>(&sWl[nb]);
                uint32_t bl1 = *reinterpret_cast<uint32_t*>(&sWl[nb + 8]);
                mma_bf16(acc[t], ah0, ah1, ah2, ah3, bh0, bh1);
                mma_bf16(acc[t], ah0, ah1, ah2, ah3, bl0, bl1);
                mma_bf16(acc[t], al0, al1, al2, al3, bh0, bh1);
            }
        }
    }

    int r = lane >> 2;
    int gr0 = m0 + warp_m * 16 + r;
    int gr1 = gr0 + 8;
    bool ok0 = (gr0 < N_NODES), ok1 = (gr1 < N_NODES);
    float dl0[4] = {0, 0, 0, 0}, dl1[4] = {0, 0, 0, 0};
    float dr0[4] = {0, 0, 0, 0}, dr1[4] = {0, 0, 0, 0};
#pragma unroll
    for (int t = 0; t < 16; t++) {
        int n = warp_n * 128 + t * 8 + (lane & 3) * 2;
        float v0 = nanfix(acc[t][0]), v1 = nanfix(acc[t][1]);
        float v2 = nanfix(acc[t][2]), v3 = nanfix(acc[t][3]);
        float alv0 = __ldg(&a_l[n]), alv1 = __ldg(&a_l[n + 1]);
        float arv0 = __ldg(&a_r[n]), arv1 = __ldg(&a_r[n + 1]);
        int hh = t >> 2;
        dl0[hh] += v0 * alv0 + v1 * alv1;
        dr0[hh] += v0 * arv0 + v1 * arv1;
        dl1[hh] += v2 * alv0 + v3 * alv1;
        dr1[hh] += v2 * arv0 + v3 * arv1;
        if (ok0) *reinterpret_cast<__half2*>(&g_h16[gr0 * HD + n]) = __floats2half2_rn(v0, v1);
        if (ok1) *reinterpret_cast<__half2*>(&g_h16[gr1 * HD + n]) = __floats2half2_rn(v2, v3);
    }
#pragma unroll
    for (int hh = 0; hh < 4; hh++) {
#pragma unroll
        for (int o = 1; o <= 2; o <<= 1) {
            dl0[hh] += __shfl_xor_sync(0xffffffffu, dl0[hh], o);
            dl1[hh] += __shfl_xor_sync(0xffffffffu, dl1[hh], o);
            dr0[hh] += __shfl_xor_sync(0xffffffffu, dr0[hh], o);
            dr1[hh] += __shfl_xor_sync(0xffffffffu, dr1[hh], o);
        }
    }
    if ((lane & 3) == 0) {
#pragma unroll
        for (int hh = 0; hh < 4; hh++) {
            int head = warp_n * 4 + hh;
            if (ok0) { g_hl[gr0 * NHEAD + head] = dl0[hh]; g_hr[gr0 * NHEAD + head] = dr0[hh]; }
            if (ok1) { g_hl[gr1 * NHEAD + head] = dl1[hh]; g_hr[gr1 * NHEAD + head] = dr1[hh]; }
        }
    }
}

// ---------------- CSR build ----------------
__global__ void k_hist(const int* __restrict__ col) {
    int e = blockIdx.x * blockDim.x + threadIdx.x;
    if (e < N_EDGES) atomicAdd(&g_deg[__ldg(&col[e])], 1);
}
__global__ __launch_bounds__(1024) void k_scan1() {
    __shared__ int sh[1024];
    int t = threadIdx.x;
    int idx = blockIdx.x * 1024 + t;
    int v = (idx < N_NODES) ? g_deg[idx] : 0;
    sh[t] = v;
    __syncthreads();
#pragma unroll
    for (int off = 1; off < 1024; off <<= 1) {
        int add = (t >= off) ? sh[t - off] : 0;
        __syncthreads();
        sh[t] += add;
        __syncthreads();
    }
    if (idx < N_NODES) g_off[idx] = sh[t] - v;
    if (t == 1023) g_bsum[blockIdx.x] = sh[t];
}
// scan of block sums folded in: each block redundantly sums bsum[0..bid-1]
__global__ __launch_bounds__(1024) void k_scan23() {
    __shared__ int s_base;
    int t = threadIdx.x;
    int bid = blockIdx.x;
    if (t < 32) {
        int v = 0;
        for (int j = t; j < SCAN_NB; j += 32)
            if (j < bid) v += g_bsum[j];
#pragma unroll
        for (int o = 16; o; o >>= 1) v += __shfl_xor_sync(0xffffffffu, v, o);
        if (t == 0) s_base = v;
    }
    __syncthreads();
    int idx = bid * 1024 + t;
    if (idx < N_NODES) {
        int o = g_off[idx] + s_base;
        g_off[idx] = o;
        g_wptr[idx] = o;
    }
}
__global__ void k_scatter(const int* __restrict__ col, const int* __restrict__ row) {
    int e = blockIdx.x * blockDim.x + threadIdx.x;
    if (e >= N_EDGES) return;
    int c = __ldg(&col[e]);
    int pos = atomicAdd(&g_wptr[c], 1);
    g_eidx[pos] = e;
    g_srow[pos] = __ldg(&row[e]);
}

// ---------------- K4: ex = exp(leaky(hl[row]+hr[col]+he[tp])), edge order -------
__global__ void k_edge(const int* __restrict__ row,
                       const int* __restrict__ col,
                       const int* __restrict__ tp) {
    int idx = blockIdx.x * blockDim.x + threadIdx.x;
    if (idx >= N_EDGES * NHEAD) return;
    int e = idx >> 3, h = idx & 7;
    int r = __ldg(&row[e]);
    int c = __ldg(&col[e]);
    int t = __ldg(&tp[e]);
    float s = g_hl[r * NHEAD + h] + g_hr[c * NHEAD + h] + g_he[t * NHEAD + h];
    s = (s > 0.0f) ? s : NEG_SLOPE * s;
    g_s[idx] = __expf(s);
}

// ---------------- K5: per-node gather (fp16 h) + normalize ----------------
__global__ __launch_bounds__(256) void k_aggregate(float* __restrict__ out) {
    int tid = threadIdx.x;
    int n = blockIdx.x * 4 + (tid >> 6);
    if (n >= N_NODES) return;
    int i = tid & 63;             // 4-float slot within the 256-float row
    int head = i >> 3;

    int base = g_off[n];
    int deg = g_deg[n];
    const uint2* h2 = reinterpret_cast<const uint2*>(g_h16);   // 4 halves per uint2

    float4 acc = make_float4(0.f, 0.f, 0.f, 0.f);
    float zacc = 0.f;
    int k = 0;
    for (; k + 4 <= deg; k += 4) {
        int e0 = __ldg(&g_eidx[base + k]);
        int e1 = __ldg(&g_eidx[base + k + 1]);
        int e2 = __ldg(&g_eidx[base + k + 2]);
        int e3 = __ldg(&g_eidx[base + k + 3]);
        int r0 = __ldg(&g_srow[base + k]);
        int r1 = __ldg(&g_srow[base + k + 1]);
        int r2 = __ldg(&g_srow[base + k + 2]);
        int r3 = __ldg(&g_srow[base + k + 3]);
        float ex0 = __ldg(&g_s[e0 * NHEAD + head]);
        float ex1 = __ldg(&g_s[e1 * NHEAD + head]);
        float ex2 = __ldg(&g_s[e2 * NHEAD + head]);
        float ex3 = __ldg(&g_s[e3 * NHEAD + head]);
        uint2 u0 = h2[r0 * 64 + i];
        uint2 u1 = h2[r1 * 64 + i];
        uint2 u2 = h2[r2 * 64 + i];
        uint2 u3 = h2[r3 * 64 + i];
        float2 a0 = __half22float2(*reinterpret_cast<__half2*>(&u0.x));
        float2 b0 = __half22float2(*reinterpret_cast<__half2*>(&u0.y));
        float2 a1 = __half22float2(*reinterpret_cast<__half2*>(&u1.x));
        float2 b1 = __half22float2(*reinterpret_cast<__half2*>(&u1.y));
        float2 a2 = __half22float2(*reinterpret_cast<__half2*>(&u2.x));
        float2 b2 = __half22float2(*reinterpret_cast<__half2*>(&u2.y));
        float2 a3 = __half22float2(*reinterpret_cast<__half2*>(&u3.x));
        float2 b3 = __half22float2(*reinterpret_cast<__half2*>(&u3.y));
        acc.x += ex0 * a0.x + ex1 * a1.x + ex2 * a2.x + ex3 * a3.x;
        acc.y += ex0 * a0.y + ex1 * a1.y + ex2 * a2.y + ex3 * a3.y;
        acc.z += ex0 * b0.x + ex1 * b1.x + ex2 * b2.x + ex3 * b3.x;
        acc.w += ex0 * b0.y + ex1 * b1.y + ex2 * b2.y + ex3 * b3.y;
        zacc += (ex0 + ex1) + (ex2 + ex3);
    }
    for (; k < deg; k++) {
        int e0 = __ldg(&g_eidx[base + k]);
        int r0 = __ldg(&g_srow[base + k]);
        float ex0 = __ldg(&g_s[e0 * NHEAD + head]);
        uint2 u0 = h2[r0 * 64 + i];
        float2 a0 = __half22float2(*reinterpret_cast<__half2*>(&u0.x));
        float2 b0 = __half22float2(*reinterpret_cast<__half2*>(&u0.y));
        acc.x += ex0 * a0.x; acc.y += ex0 * a0.y;
        acc.z += ex0 * b0.x; acc.w += ex0 * b0.y;
        zacc += ex0;
    }
    float inv = (deg > 0) ? (1.0f / zacc) : 0.0f;
    reinterpret_cast<float4*>(out)[n * 64 + i] =
        make_float4(acc.x * inv, acc.y * inv, acc.z * inv, acc.w * inv);
    if ((i & 7) == 0) g_z[n * NHEAD + head] = zacc;
}

// ---------------- K6: att output (edge order) ----------------
__global__ void k_attout(const int* __restrict__ col, float* __restrict__ attOut) {
    int idx = blockIdx.x * blockDim.x + threadIdx.x;
    if (idx >= N_EDGES * NHEAD) return;
    int e = idx >> 3, h = idx & 7;
    int c = __ldg(&col[e]);
    attOut[idx] = g_s[idx] / g_z[c * NHEAD + h];
}

// ---------------- launch ---------------------------------------------------------
extern "C" void kernel_launch(void* const* d_in, const int* in_sizes, int n_in,
                              void* d_out, int out_size) {
    const float* x        = (const float*)d_in[0];
    const float* W        = (const float*)d_in[1];
    const float* W_e      = (const float*)d_in[2];
    const float* edge_emb = (const float*)d_in[3];
    const float* a_l      = (const float*)d_in[4];
    const float* a_r      = (const float*)d_in[5];
    const float* a_e      = (const float*)d_in[6];
    const int*   row      = (const int*)d_in[7];
    const int*   col      = (const int*)d_in[8];
    const int*   tp       = (const int*)d_in[9];

    float* out = (float*)d_out;
    float* attOut = (out_size >= OUT_ELEMS + ATT_ELEMS) ? out + OUT_ELEMS : nullptr;

    static int inited = 0;
    if (!inited) {
        cudaFuncSetAttribute(k_gemm_mma, cudaFuncAttributeMaxDynamicSharedMemorySize,
                             SM_HALVES * 2);
        inited = 1;
    }

    k_wprep<<<(HD * IN_F + 255) / 256, 256>>>(W);
    k_he<<<1, 64>>>(edge_emb, W_e, a_e);
    k_hist<<<(N_EDGES + 255) / 256, 256>>>(col);
    k_scan1<<<SCAN_NB, 1024>>>();
    k_scan23<<<SCAN_NB, 1024>>>();
    k_scatter<<<(N_EDGES + 255) / 256, 256>>>(col, row);

    k_gemm_mma<<<(N_NODES + 63) / 64, 256, SM_HALVES * 2>>>(x, a_l, a_r);

    k_edge<<<(N_EDGES * NHEAD + 255) / 256, 256>>>(row, col, tp);
    k_aggregate<<<(N_NODES + 3) / 4, 256>>>(out);
    if (attOut)
        k_attout<<<(N_EDGES * NHEAD + 255) / 256, 256>>>(col, attOut);
}

// round 9
// speedup vs baseline: 1.5191x; 1.0560x over previous
#include <cuda_runtime.h>
#include <cuda_bf16.h>
#include <cuda_fp16.h>
#include <math.h>
#include <stdint.h>

#define N_NODES 50000
#define N_EDGES 800000
#define IN_F 256
#define OUT_F 32
#define NHEAD 8
#define EDGE_F 32
#define N_ETYPES 8
#define NEG_SLOPE 0.1f

#define HD (NHEAD * OUT_F)            // 256
#define OUT_ELEMS (N_NODES * HD)
#define ATT_ELEMS (N_EDGES * NHEAD)
#define SCAN_NB ((N_NODES + 1023) / 1024)

// ---------------- scratch ----------------
__device__ __half    g_h16[N_NODES * HD];      // h in fp16 (consumer: aggregation)
__device__ float     g_hl[N_NODES * NHEAD];
__device__ float     g_hr[N_NODES * NHEAD];
__device__ float     g_z[N_NODES * NHEAD];
__device__ float     g_he[N_ETYPES * NHEAD];
__device__ int       g_deg[N_NODES];
__device__ int       g_off[N_NODES];
__device__ int       g_wptr[N_NODES];
__device__ int       g_bsum[SCAN_NB];
__device__ int       g_srow[N_EDGES];          // sorted pos -> source node
__device__ int       g_stp[N_EDGES];           // sorted pos -> edge type
__device__ __nv_bfloat16 g_wh[HD * IN_F];
__device__ __nv_bfloat16 g_wl[HD * IN_F];

// ---------------- K_wprep (+ zero deg) ----------------
__global__ void k_wprep(const float* __restrict__ W) {
    int idx = blockIdx.x * blockDim.x + threadIdx.x;
    if (idx < N_NODES) g_deg[idx] = 0;
    if (idx >= HD * IN_F) return;
    int n = idx >> 8, k = idx & 255;
    float w = W[k * HD + n];
    __nv_bfloat16 h = __float2bfloat16(w);
    float r = w - __bfloat162float(h);
    g_wh[n * IN_F + k] = h;
    g_wl[n * IN_F + k] = __float2bfloat16(r);
}

// ---------------- K1: he[t][h] ----------------
__global__ void k_he(const float* __restrict__ edge_emb,
                     const float* __restrict__ W_e,
                     const float* __restrict__ a_e) {
    int tid = threadIdx.x;
    if (tid >= N_ETYPES * NHEAD) return;
    int t = tid >> 3, h = tid & 7;
    float acc = 0.0f;
    for (int f = 0; f < EDGE_F; f++) {
        float ev = 0.0f;
        for (int k = 0; k < EDGE_F; k++)
            ev += edge_emb[t * EDGE_F + k] * W_e[k * (EDGE_F * NHEAD) + h * EDGE_F + f];
        acc += a_e[h * EDGE_F + f] * ev;
    }
    g_he[t * NHEAD + h] = acc;
}

// ---------------- K2: bf16 split-precision mma.sync GEMM + fused dots ----------
#define XPAD 40
#define WPAD 40
#define OFF_XH 0
#define OFF_XL (OFF_XH + 64 * XPAD)
#define OFF_WH (OFF_XL + 64 * XPAD)
#define OFF_WL (OFF_WH + 256 * WPAD)
#define SM_HALVES (OFF_WL + 256 * WPAD)

__device__ __forceinline__ void mma_bf16(float* d, uint32_t a0, uint32_t a1,
                                         uint32_t a2, uint32_t a3,
                                         uint32_t b0, uint32_t b1) {
    asm volatile(
        "mma.sync.aligned.m16n8k16.row.col.f32.bf16.bf16.f32 "
        "{%0,%1,%2,%3}, {%4,%5,%6,%7}, {%8,%9}, {%0,%1,%2,%3};"
        : "+f"(d[0]), "+f"(d[1]), "+f"(d[2]), "+f"(d[3])
        : "r"(a0), "r"(a1), "r"(a2), "r"(a3), "r"(b0), "r"(b1));
}
__device__ __forceinline__ float nanfix(float v) { return isnan(v) ? 0.0f : v; }

__global__ __launch_bounds__(256) void k_gemm_mma(const float* __restrict__ x,
                                                  const float* __restrict__ a_l,
                                                  const float* __restrict__ a_r) {
    extern __shared__ __align__(16) uint16_t sm[];
    uint16_t* sXh = sm + OFF_XH;
    uint16_t* sXl = sm + OFF_XL;
    uint16_t* sWh = sm + OFF_WH;
    uint16_t* sWl = sm + OFF_WL;

    int tid = threadIdx.x;
    int lane = tid & 31;
    int wid = tid >> 5;
    int warp_m = wid & 3;
    int warp_n = wid >> 2;
    int m0 = blockIdx.x * 64;

    float acc[16][4];
#pragma unroll
    for (int t = 0; t < 16; t++)
#pragma unroll
        for (int j = 0; j < 4; j++) acc[t][j] = 0.0f;

    for (int ks = 0; ks < 8; ks++) {
        int k0 = ks * 32;
        __syncthreads();
        {
            int r = tid >> 2, q = tid & 3;
            int gm = m0 + r;
            float v[8];
            if (gm < N_NODES) {
                const float4* src = reinterpret_cast<const float4*>(x + gm * IN_F + k0 + q * 8);
                float4 f0 = src[0], f1 = src[1];
                v[0] = f0.x; v[1] = f0.y; v[2] = f0.z; v[3] = f0.w;
                v[4] = f1.x; v[5] = f1.y; v[6] = f1.z; v[7] = f1.w;
            } else {
#pragma unroll
                for (int j = 0; j < 8; j++) v[j] = 0.0f;
            }
            uint32_t hi[4], lo[4];
#pragma unroll
            for (int j = 0; j < 4; j++) {
                __nv_bfloat16 h0 = __float2bfloat16(v[2 * j]);
                __nv_bfloat16 h1 = __float2bfloat16(v[2 * j + 1]);
                hi[j] = (uint32_t)__bfloat16_as_ushort(h0) |
                        ((uint32_t)__bfloat16_as_ushort(h1) << 16);
                __nv_bfloat16 l0 = __float2bfloat16(v[2 * j] - __bfloat162float(h0));
                __nv_bfloat16 l1 = __float2bfloat16(v[2 * j + 1] - __bfloat162float(h1));
                lo[j] = (uint32_t)__bfloat16_as_ushort(l0) |
                        ((uint32_t)__bfloat16_as_ushort(l1) << 16);
            }
            *reinterpret_cast<uint4*>(&sXh[r * XPAD + q * 8]) = make_uint4(hi[0], hi[1], hi[2], hi[3]);
            *reinterpret_cast<uint4*>(&sXl[r * XPAD + q * 8]) = make_uint4(lo[0], lo[1], lo[2], lo[3]);
        }
        {
            const uint4* ph = reinterpret_cast<const uint4*>(g_wh + tid * IN_F + k0);
            const uint4* pl = reinterpret_cast<const uint4*>(g_wl + tid * IN_F + k0);
#pragma unroll
            for (int j = 0; j < 4; j++) {
                *reinterpret_cast<uint4*>(&sWh[tid * WPAD + j * 8]) = ph[j];
                *reinterpret_cast<uint4*>(&sWl[tid * WPAD + j * 8]) = pl[j];
            }
        }
        __syncthreads();
#pragma unroll
        for (int kin = 0; kin < 32; kin += 16) {
            int c = (lane & 3) * 2 + kin;
            int ra = (warp_m * 16 + (lane >> 2)) * XPAD;
            uint32_t ah0 = *reinterpret_cast<uint32_t*>(&sXh[ra + c]);
            uint32_t ah1 = *reinterpret_cast<uint32_t*>(&sXh[ra + 8 * XPAD + c]);
            uint32_t ah2 = *reinterpret_cast<uint32_t*>(&sXh[ra + c + 8]);
            uint32_t ah3 = *reinterpret_cast<uint32_t*>(&sXh[ra + 8 * XPAD + c + 8]);
            uint32_t al0 = *reinterpret_cast<uint32_t*>(&sXl[ra + c]);
            uint32_t al1 = *reinterpret_cast<uint32_t*>(&sXl[ra + 8 * XPAD + c]);
            uint32_t al2 = *reinterpret_cast<uint32_t*>(&sXl[ra + c + 8]);
            uint32_t al3 = *reinterpret_cast<uint32_t*>(&sXl[ra + 8 * XPAD + c + 8]);
#pragma unroll
            for (int t = 0; t < 16; t++) {
                int nb = (warp_n * 128 + t * 8 + (lane >> 2)) * WPAD + (lane & 3) * 2 + kin;
                uint32_t bh0 = *reinterpret_cast<uint32_t*>(&sWh[nb]);
                uint32_t bh1 = *reinterpret_cast<uint32_t*>(&sWh[nb + 8]);
                uint32_t bl0 = *reinterpret_cast<uint32_t*>(&sWl[nb]);
                uint32_t bl1 = *reinterpret_cast<uint32_t*>(&sWl[nb + 8]);
                mma_bf16(acc[t], ah0, ah1, ah2, ah3, bh0, bh1);
                mma_bf16(acc[t], ah0, ah1, ah2, ah3, bl0, bl1);
                mma_bf16(acc[t], al0, al1, al2, al3, bh0, bh1);
            }
        }
    }

    int r = lane >> 2;
    int gr0 = m0 + warp_m * 16 + r;
    int gr1 = gr0 + 8;
    bool ok0 = (gr0 < N_NODES), ok1 = (gr1 < N_NODES);
    float dl0[4] = {0, 0, 0, 0}, dl1[4] = {0, 0, 0, 0};
    float dr0[4] = {0, 0, 0, 0}, dr1[4] = {0, 0, 0, 0};
#pragma unroll
    for (int t = 0; t < 16; t++) {
        int n = warp_n * 128 + t * 8 + (lane & 3) * 2;
        float v0 = nanfix(acc[t][0]), v1 = nanfix(acc[t][1]);
        float v2 = nanfix(acc[t][2]), v3 = nanfix(acc[t][3]);
        float alv0 = __ldg(&a_l[n]), alv1 = __ldg(&a_l[n + 1]);
        float arv0 = __ldg(&a_r[n]), arv1 = __ldg(&a_r[n + 1]);
        int hh = t >> 2;
        dl0[hh] += v0 * alv0 + v1 * alv1;
        dr0[hh] += v0 * arv0 + v1 * arv1;
        dl1[hh] += v2 * alv0 + v3 * alv1;
        dr1[hh] += v2 * arv0 + v3 * arv1;
        if (ok0) *reinterpret_cast<__half2*>(&g_h16[gr0 * HD + n]) = __floats2half2_rn(v0, v1);
        if (ok1) *reinterpret_cast<__half2*>(&g_h16[gr1 * HD + n]) = __floats2half2_rn(v2, v3);
    }
#pragma unroll
    for (int hh = 0; hh < 4; hh++) {
#pragma unroll
        for (int o = 1; o <= 2; o <<= 1) {
            dl0[hh] += __shfl_xor_sync(0xffffffffu, dl0[hh], o);
            dl1[hh] += __shfl_xor_sync(0xffffffffu, dl1[hh], o);
            dr0[hh] += __shfl_xor_sync(0xffffffffu, dr0[hh], o);
            dr1[hh] += __shfl_xor_sync(0xffffffffu, dr1[hh], o);
        }
    }
    if ((lane & 3) == 0) {
#pragma unroll
        for (int hh = 0; hh < 4; hh++) {
            int head = warp_n * 4 + hh;
            if (ok0) { g_hl[gr0 * NHEAD + head] = dl0[hh]; g_hr[gr0 * NHEAD + head] = dr0[hh]; }
            if (ok1) { g_hl[gr1 * NHEAD + head] = dl1[hh]; g_hr[gr1 * NHEAD + head] = dr1[hh]; }
        }
    }
}

// ---------------- CSR build ----------------
__global__ void k_hist(const int* __restrict__ col) {
    int e = blockIdx.x * blockDim.x + threadIdx.x;
    if (e < N_EDGES) atomicAdd(&g_deg[__ldg(&col[e])], 1);
}
__global__ __launch_bounds__(1024) void k_scan1() {
    __shared__ int sh[1024];
    int t = threadIdx.x;
    int idx = blockIdx.x * 1024 + t;
    int v = (idx < N_NODES) ? g_deg[idx] : 0;
    sh[t] = v;
    __syncthreads();
#pragma unroll
    for (int off = 1; off < 1024; off <<= 1) {
        int add = (t >= off) ? sh[t - off] : 0;
        __syncthreads();
        sh[t] += add;
        __syncthreads();
    }
    if (idx < N_NODES) g_off[idx] = sh[t] - v;
    if (t == 1023) g_bsum[blockIdx.x] = sh[t];
}
__global__ __launch_bounds__(1024) void k_scan23() {
    __shared__ int s_base;
    int t = threadIdx.x;
    int bid = blockIdx.x;
    if (t < 32) {
        int v = 0;
        for (int j = t; j < SCAN_NB; j += 32)
            if (j < bid) v += g_bsum[j];
#pragma unroll
        for (int o = 16; o; o >>= 1) v += __shfl_xor_sync(0xffffffffu, v, o);
        if (t == 0) s_base = v;
    }
    __syncthreads();
    int idx = bid * 1024 + t;
    if (idx < N_NODES) {
        int o = g_off[idx] + s_base;
        g_off[idx] = o;
        g_wptr[idx] = o;
    }
}
__global__ void k_scatter(const int* __restrict__ col, const int* __restrict__ row,
                          const int* __restrict__ tp) {
    int e = blockIdx.x * blockDim.x + threadIdx.x;
    if (e >= N_EDGES) return;
    int c = __ldg(&col[e]);
    int pos = atomicAdd(&g_wptr[c], 1);
    g_srow[pos] = __ldg(&row[e]);
    g_stp[pos] = __ldg(&tp[e]);
}

// ---------------- K5: fused edge-softmax + gather + normalize ----------------
__device__ __forceinline__ float edge_ex(float hlv, float hrv, float hev) {
    float s = hlv + hrv + hev;
    s = (s > 0.0f) ? s : NEG_SLOPE * s;
    return __expf(s);
}

__global__ __launch_bounds__(256) void k_aggregate(float* __restrict__ out) {
    int tid = threadIdx.x;
    int n = blockIdx.x * 4 + (tid >> 6);
    if (n >= N_NODES) return;
    int i = tid & 63;             // 4-float slot within the 256-float row
    int head = i >> 3;

    int base = g_off[n];
    int deg = g_deg[n];
    const uint2* h2 = reinterpret_cast<const uint2*>(g_h16);
    float hrv = g_hr[n * NHEAD + head];

    float4 acc = make_float4(0.f, 0.f, 0.f, 0.f);
    float zacc = 0.f;
    int k = 0;
    for (; k + 4 <= deg; k += 4) {
        int r0 = __ldg(&g_srow[base + k]);
        int r1 = __ldg(&g_srow[base + k + 1]);
        int r2 = __ldg(&g_srow[base + k + 2]);
        int r3 = __ldg(&g_srow[base + k + 3]);
        int t0 = __ldg(&g_stp[base + k]);
        int t1 = __ldg(&g_stp[base + k + 1]);
        int t2 = __ldg(&g_stp[base + k + 2]);
        int t3 = __ldg(&g_stp[base + k + 3]);
        float hl0 = __ldg(&g_hl[r0 * NHEAD + head]);
        float hl1 = __ldg(&g_hl[r1 * NHEAD + head]);
        float hl2 = __ldg(&g_hl[r2 * NHEAD + head]);
        float hl3 = __ldg(&g_hl[r3 * NHEAD + head]);
        uint2 u0 = h2[r0 * 64 + i];
        uint2 u1 = h2[r1 * 64 + i];
        uint2 u2 = h2[r2 * 64 + i];
        uint2 u3 = h2[r3 * 64 + i];
        float ex0 = edge_ex(hl0, hrv, g_he[t0 * NHEAD + head]);
        float ex1 = edge_ex(hl1, hrv, g_he[t1 * NHEAD + head]);
        float ex2 = edge_ex(hl2, hrv, g_he[t2 * NHEAD + head]);
        float ex3 = edge_ex(hl3, hrv, g_he[t3 * NHEAD + head]);
        float2 a0 = __half22float2(*reinterpret_cast<__half2*>(&u0.x));
        float2 b0 = __half22float2(*reinterpret_cast<__half2*>(&u0.y));
        float2 a1 = __half22float2(*reinterpret_cast<__half2*>(&u1.x));
        float2 b1 = __half22float2(*reinterpret_cast<__half2*>(&u1.y));
        float2 a2 = __half22float2(*reinterpret_cast<__half2*>(&u2.x));
        float2 b2 = __half22float2(*reinterpret_cast<__half2*>(&u2.y));
        float2 a3 = __half22float2(*reinterpret_cast<__half2*>(&u3.x));
        float2 b3 = __half22float2(*reinterpret_cast<__half2*>(&u3.y));
        acc.x += ex0 * a0.x + ex1 * a1.x + ex2 * a2.x + ex3 * a3.x;
        acc.y += ex0 * a0.y + ex1 * a1.y + ex2 * a2.y + ex3 * a3.y;
        acc.z += ex0 * b0.x + ex1 * b1.x + ex2 * b2.x + ex3 * b3.x;
        acc.w += ex0 * b0.y + ex1 * b1.y + ex2 * b2.y + ex3 * b3.y;
        zacc += (ex0 + ex1) + (ex2 + ex3);
    }
    for (; k < deg; k++) {
        int r0 = __ldg(&g_srow[base + k]);
        int t0 = __ldg(&g_stp[base + k]);
        float ex0 = edge_ex(__ldg(&g_hl[r0 * NHEAD + head]), hrv,
                            g_he[t0 * NHEAD + head]);
        uint2 u0 = h2[r0 * 64 + i];
        float2 a0 = __half22float2(*reinterpret_cast<__half2*>(&u0.x));
        float2 b0 = __half22float2(*reinterpret_cast<__half2*>(&u0.y));
        acc.x += ex0 * a0.x; acc.y += ex0 * a0.y;
        acc.z += ex0 * b0.x; acc.w += ex0 * b0.y;
        zacc += ex0;
    }
    float inv = (deg > 0) ? (1.0f / zacc) : 0.0f;
    reinterpret_cast<float4*>(out)[n * 64 + i] =
        make_float4(acc.x * inv, acc.y * inv, acc.z * inv, acc.w * inv);
    if ((i & 7) == 0) g_z[n * NHEAD + head] = zacc;
}

// ---------------- K6: att output (edge order, recompute exp) ----------------
__global__ void k_attout(const int* __restrict__ row,
                         const int* __restrict__ col,
                         const int* __restrict__ tp,
                         float* __restrict__ attOut) {
    int idx = blockIdx.x * blockDim.x + threadIdx.x;
    if (idx >= N_EDGES * NHEAD) return;
    int e = idx >> 3, h = idx & 7;
    int r = __ldg(&row[e]);
    int c = __ldg(&col[e]);
    int t = __ldg(&tp[e]);
    float ex = edge_ex(g_hl[r * NHEAD + h], g_hr[c * NHEAD + h],
                       g_he[t * NHEAD + h]);
    attOut[idx] = ex / g_z[c * NHEAD + h];
}

// ---------------- launch ---------------------------------------------------------
extern "C" void kernel_launch(void* const* d_in, const int* in_sizes, int n_in,
                              void* d_out, int out_size) {
    const float* x        = (const float*)d_in[0];
    const float* W        = (const float*)d_in[1];
    const float* W_e      = (const float*)d_in[2];
    const float* edge_emb = (const float*)d_in[3];
    const float* a_l      = (const float*)d_in[4];
    const float* a_r      = (const float*)d_in[5];
    const float* a_e      = (const float*)d_in[6];
    const int*   row      = (const int*)d_in[7];
    const int*   col      = (const int*)d_in[8];
    const int*   tp       = (const int*)d_in[9];

    float* out = (float*)d_out;
    float* attOut = (out_size >= OUT_ELEMS + ATT_ELEMS) ? out + OUT_ELEMS : nullptr;

    static int inited = 0;
    if (!inited) {
        cudaFuncSetAttribute(k_gemm_mma, cudaFuncAttributeMaxDynamicSharedMemorySize,
                             SM_HALVES * 2);
        inited = 1;
    }

    k_wprep<<<(HD * IN_F + 255) / 256, 256>>>(W);
    k_he<<<1, 64>>>(edge_emb, W_e, a_e);
    k_hist<<<(N_EDGES + 255) / 256, 256>>>(col);
    k_scan1<<<SCAN_NB, 1024>>>();
    k_scan23<<<SCAN_NB, 1024>>>();
    k_scatter<<<(N_EDGES + 255) / 256, 256>>>(col, row, tp);

    k_gemm_mma<<<(N_NODES + 63) / 64, 256, SM_HALVES * 2>>>(x, a_l, a_r);

    k_aggregate<<<(N_NODES + 3) / 4, 256>>>(out);
    if (attOut)
        k_attout<<<(N_EDGES * NHEAD + 255) / 256, 256>>>(row, col, tp, attOut);
}

// round 10
// speedup vs baseline: 1.5536x; 1.0227x over previous
#include <cuda_runtime.h>
#include <cuda_bf16.h>
#include <cuda_fp16.h>
#include <math.h>
#include <stdint.h>

#define N_NODES 50000
#define N_EDGES 800000
#define IN_F 256
#define OUT_F 32
#define NHEAD 8
#define EDGE_F 32
#define N_ETYPES 8
#define NEG_SLOPE 0.1f

#define HD (NHEAD * OUT_F)            // 256
#define OUT_ELEMS (N_NODES * HD)
#define ATT_ELEMS (N_EDGES * NHEAD)
#define SCAN_NB ((N_NODES + 1023) / 1024)
#define PACK_MASK 0xFFFFF             // low 20 bits: node id; high bits: edge type

// ---------------- scratch ----------------
__device__ __half    g_h16[N_NODES * HD];
__device__ float     g_hl[N_NODES * NHEAD];
__device__ float     g_hr[N_NODES * NHEAD];
__device__ float     g_z[N_NODES * NHEAD];
__device__ float     g_he[N_ETYPES * NHEAD];
__device__ int       g_deg[N_NODES];
__device__ int       g_off[N_NODES];
__device__ int       g_wptr[N_NODES];
__device__ int       g_bsum[SCAN_NB];
__device__ int       g_spack[N_EDGES];         // sorted pos -> row | (tp<<20)
__device__ __nv_bfloat16 g_wh[HD * IN_F];
__device__ __nv_bfloat16 g_wl[HD * IN_F];

// ---------------- K_wprep (+ zero deg + he) ----------------
__global__ void k_wprep(const float* __restrict__ W,
                        const float* __restrict__ edge_emb,
                        const float* __restrict__ W_e,
                        const float* __restrict__ a_e) {
    int idx = blockIdx.x * blockDim.x + threadIdx.x;
    if (idx < N_NODES) g_deg[idx] = 0;
    // he: first 64 threads of block 0
    if (blockIdx.x == 0 && threadIdx.x < N_ETYPES * NHEAD) {
        int t = threadIdx.x >> 3, h = threadIdx.x & 7;
        float acc = 0.0f;
        for (int f = 0; f < EDGE_F; f++) {
            float ev = 0.0f;
            for (int k = 0; k < EDGE_F; k++)
                ev += edge_emb[t * EDGE_F + k] * W_e[k * (EDGE_F * NHEAD) + h * EDGE_F + f];
            acc += a_e[h * EDGE_F + f] * ev;
        }
        g_he[t * NHEAD + h] = acc;
    }
    if (idx >= HD * IN_F) return;
    int n = idx >> 8, k = idx & 255;
    float w = W[k * HD + n];
    __nv_bfloat16 h = __float2bfloat16(w);
    float r = w - __bfloat162float(h);
    g_wh[n * IN_F + k] = h;
    g_wl[n * IN_F + k] = __float2bfloat16(r);
}

// ---------------- K2: bf16 split-precision mma.sync GEMM + fused dots ----------
#define XPAD 40
#define WPAD 40
#define OFF_XH 0
#define OFF_XL (OFF_XH + 64 * XPAD)
#define OFF_WH (OFF_XL + 64 * XPAD)
#define OFF_WL (OFF_WH + 256 * WPAD)
#define SM_HALVES (OFF_WL + 256 * WPAD)

__device__ __forceinline__ void mma_bf16(float* d, uint32_t a0, uint32_t a1,
                                         uint32_t a2, uint32_t a3,
                                         uint32_t b0, uint32_t b1) {
    asm volatile(
        "mma.sync.aligned.m16n8k16.row.col.f32.bf16.bf16.f32 "
        "{%0,%1,%2,%3}, {%4,%5,%6,%7}, {%8,%9}, {%0,%1,%2,%3};"
        : "+f"(d[0]), "+f"(d[1]), "+f"(d[2]), "+f"(d[3])
        : "r"(a0), "r"(a1), "r"(a2), "r"(a3), "r"(b0), "r"(b1));
}
__device__ __forceinline__ float nanfix(float v) { return isnan(v) ? 0.0f : v; }
__device__ __forceinline__ uint32_t smem_u32(const void* p) {
    uint32_t a;
    asm("{ .reg .u64 t; cvta.to.shared.u64 t, %1; cvt.u32.u64 %0, t; }" : "=r"(a) : "l"(p));
    return a;
}
#define CP_ASYNC16(dst_u32, src_ptr) \
    asm volatile("cp.async.ca.shared.global [%0], [%1], 16;" :: "r"(dst_u32), "l"(src_ptr))
#define CP_COMMIT() asm volatile("cp.async.commit_group;")
#define CP_WAIT0()  asm volatile("cp.async.wait_group 0;")

__global__ __launch_bounds__(256) void k_gemm_mma(const float* __restrict__ x,
                                                  const float* __restrict__ a_l,
                                                  const float* __restrict__ a_r) {
    extern __shared__ __align__(16) uint16_t sm[];
    uint16_t* sXh = sm + OFF_XH;
    uint16_t* sXl = sm + OFF_XL;
    uint16_t* sWh = sm + OFF_WH;
    uint16_t* sWl = sm + OFF_WL;
    uint32_t sb = smem_u32(sm);

    int tid = threadIdx.x;
    int lane = tid & 31;
    int wid = tid >> 5;
    int warp_m = wid & 3;
    int warp_n = wid >> 2;
    int m0 = blockIdx.x * 64;

    float acc[16][4];
#pragma unroll
    for (int t = 0; t < 16; t++)
#pragma unroll
        for (int j = 0; j < 4; j++) acc[t][j] = 0.0f;

    for (int ks = 0; ks < 8; ks++) {
        int k0 = ks * 32;
        __syncthreads();
        // --- W stage via cp.async (pure 16B copies; overlaps with x convert) ---
        {
            uint32_t dWh = sb + (OFF_WH + tid * WPAD) * 2;
            uint32_t dWl = sb + (OFF_WL + tid * WPAD) * 2;
            const __nv_bfloat16* srch = g_wh + tid * IN_F + k0;
            const __nv_bfloat16* srcl = g_wl + tid * IN_F + k0;
#pragma unroll
            for (int j = 0; j < 4; j++) {
                CP_ASYNC16(dWh + j * 16, srch + j * 8);
                CP_ASYNC16(dWl + j * 16, srcl + j * 8);
            }
            CP_COMMIT();
        }
        // --- x stage: load fp32, split to bf16 hi/lo, store ---
        {
            int r = tid >> 2, q = tid & 3;
            int gm = m0 + r;
            float v[8];
            if (gm < N_NODES) {
                const float4* src = reinterpret_cast<const float4*>(x + gm * IN_F + k0 + q * 8);
                float4 f0 = src[0], f1 = src[1];
                v[0] = f0.x; v[1] = f0.y; v[2] = f0.z; v[3] = f0.w;
                v[4] = f1.x; v[5] = f1.y; v[6] = f1.z; v[7] = f1.w;
            } else {
#pragma unroll
                for (int j = 0; j < 8; j++) v[j] = 0.0f;
            }
            uint32_t hi[4], lo[4];
#pragma unroll
            for (int j = 0; j < 4; j++) {
                __nv_bfloat16 h0 = __float2bfloat16(v[2 * j]);
                __nv_bfloat16 h1 = __float2bfloat16(v[2 * j + 1]);
                hi[j] = (uint32_t)__bfloat16_as_ushort(h0) |
                        ((uint32_t)__bfloat16_as_ushort(h1) << 16);
                __nv_bfloat16 l0 = __float2bfloat16(v[2 * j] - __bfloat162float(h0));
                __nv_bfloat16 l1 = __float2bfloat16(v[2 * j + 1] - __bfloat162float(h1));
                lo[j] = (uint32_t)__bfloat16_as_ushort(l0) |
                        ((uint32_t)__bfloat16_as_ushort(l1) << 16);
            }
            *reinterpret_cast<uint4*>(&sXh[r * XPAD + q * 8]) = make_uint4(hi[0], hi[1], hi[2], hi[3]);
            *reinterpret_cast<uint4*>(&sXl[r * XPAD + q * 8]) = make_uint4(lo[0], lo[1], lo[2], lo[3]);
        }
        CP_WAIT0();
        __syncthreads();
#pragma unroll
        for (int kin = 0; kin < 32; kin += 16) {
            int c = (lane & 3) * 2 + kin;
            int ra = (warp_m * 16 + (lane >> 2)) * XPAD;
            uint32_t ah0 = *reinterpret_cast<uint32_t*>(&sXh[ra + c]);
            uint32_t ah1 = *reinterpret_cast<uint32_t*>(&sXh[ra + 8 * XPAD + c]);
            uint32_t ah2 = *reinterpret_cast<uint32_t*>(&sXh[ra + c + 8]);
            uint32_t ah3 = *reinterpret_cast<uint32_t*>(&sXh[ra + 8 * XPAD + c + 8]);
            uint32_t al0 = *reinterpret_cast<uint32_t*>(&sXl[ra + c]);
            uint32_t al1 = *reinterpret_cast<uint32_t*>(&sXl[ra + 8 * XPAD + c]);
            uint32_t al2 = *reinterpret_cast<uint32_t*>(&sXl[ra + c + 8]);
            uint32_t al3 = *reinterpret_cast<uint32_t*>(&sXl[ra + 8 * XPAD + c + 8]);
#pragma unroll
            for (int t = 0; t < 16; t++) {
                int nb = (warp_n * 128 + t * 8 + (lane >> 2)) * WPAD + (lane & 3) * 2 + kin;
                uint32_t bh0 = *reinterpret_cast<uint32_t*>(&sWh[nb]);
                uint32_t bh1 = *reinterpret_cast<uint32_t*>(&sWh[nb + 8]);
                uint32_t bl0 = *reinterpret_cast<uint32_t*>(&sWl[nb]);
                uint32_t bl1 = *reinterpret_cast<uint32_t*>(&sWl[nb + 8]);
                mma_bf16(acc[t], ah0, ah1, ah2, ah3, bh0, bh1);
                mma_bf16(acc[t], ah0, ah1, ah2, ah3, bl0, bl1);
                mma_bf16(acc[t], al0, al1, al2, al3, bh0, bh1);
            }
        }
    }

    int r = lane >> 2;
    int gr0 = m0 + warp_m * 16 + r;
    int gr1 = gr0 + 8;
    bool ok0 = (gr0 < N_NODES), ok1 = (gr1 < N_NODES);
    float dl0[4] = {0, 0, 0, 0}, dl1[4] = {0, 0, 0, 0};
    float dr0[4] = {0, 0, 0, 0}, dr1[4] = {0, 0, 0, 0};
#pragma unroll
    for (int t = 0; t < 16; t++) {
        int n = warp_n * 128 + t * 8 + (lane & 3) * 2;
        float v0 = nanfix(acc[t][0]), v1 = nanfix(acc[t][1]);
        float v2 = nanfix(acc[t][2]), v3 = nanfix(acc[t][3]);
        float alv0 = __ldg(&a_l[n]), alv1 = __ldg(&a_l[n + 1]);
        float arv0 = __ldg(&a_r[n]), arv1 = __ldg(&a_r[n + 1]);
        int hh = t >> 2;
        dl0[hh] += v0 * alv0 + v1 * alv1;
        dr0[hh] += v0 * arv0 + v1 * arv1;
        dl1[hh] += v2 * alv0 + v3 * alv1;
        dr1[hh] += v2 * arv0 + v3 * arv1;
        if (ok0) *reinterpret_cast<__half2*>(&g_h16[gr0 * HD + n]) = __floats2half2_rn(v0, v1);
        if (ok1) *reinterpret_cast<__half2*>(&g_h16[gr1 * HD + n]) = __floats2half2_rn(v2, v3);
    }
#pragma unroll
    for (int hh = 0; hh < 4; hh++) {
#pragma unroll
        for (int o = 1; o <= 2; o <<= 1) {
            dl0[hh] += __shfl_xor_sync(0xffffffffu, dl0[hh], o);
            dl1[hh] += __shfl_xor_sync(0xffffffffu, dl1[hh], o);
            dr0[hh] += __shfl_xor_sync(0xffffffffu, dr0[hh], o);
            dr1[hh] += __shfl_xor_sync(0xffffffffu, dr1[hh], o);
        }
    }
    if ((lane & 3) == 0) {
#pragma unroll
        for (int hh = 0; hh < 4; hh++) {
            int head = warp_n * 4 + hh;
            if (ok0) { g_hl[gr0 * NHEAD + head] = dl0[hh]; g_hr[gr0 * NHEAD + head] = dr0[hh]; }
            if (ok1) { g_hl[gr1 * NHEAD + head] = dl1[hh]; g_hr[gr1 * NHEAD + head] = dr1[hh]; }
        }
    }
}

// ---------------- CSR build ----------------
__global__ void k_hist(const int* __restrict__ col) {
    int e = blockIdx.x * blockDim.x + threadIdx.x;
    if (e < N_EDGES) atomicAdd(&g_deg[__ldg(&col[e])], 1);
}
__global__ __launch_bounds__(1024) void k_scan1() {
    __shared__ int sh[1024];
    int t = threadIdx.x;
    int idx = blockIdx.x * 1024 + t;
    int v = (idx < N_NODES) ? g_deg[idx] : 0;
    sh[t] = v;
    __syncthreads();
#pragma unroll
    for (int off = 1; off < 1024; off <<= 1) {
        int add = (t >= off) ? sh[t - off] : 0;
        __syncthreads();
        sh[t] += add;
        __syncthreads();
    }
    if (idx < N_NODES) g_off[idx] = sh[t] - v;
    if (t == 1023) g_bsum[blockIdx.x] = sh[t];
}
__global__ __launch_bounds__(1024) void k_scan23() {
    __shared__ int s_base;
    int t = threadIdx.x;
    int bid = blockIdx.x;
    if (t < 32) {
        int v = 0;
        for (int j = t; j < SCAN_NB; j += 32)
            if (j < bid) v += g_bsum[j];
#pragma unroll
        for (int o = 16; o; o >>= 1) v += __shfl_xor_sync(0xffffffffu, v, o);
        if (t == 0) s_base = v;
    }
    __syncthreads();
    int idx = bid * 1024 + t;
    if (idx < N_NODES) {
        int o = g_off[idx] + s_base;
        g_off[idx] = o;
        g_wptr[idx] = o;
    }
}
__global__ void k_scatter(const int* __restrict__ col, const int* __restrict__ row,
                          const int* __restrict__ tp) {
    int e = blockIdx.x * blockDim.x + threadIdx.x;
    if (e >= N_EDGES) return;
    int c = __ldg(&col[e]);
    int pos = atomicAdd(&g_wptr[c], 1);
    g_spack[pos] = __ldg(&row[e]) | (__ldg(&tp[e]) << 20);
}

// ---------------- K5: fused edge-softmax + gather + normalize ----------------
__device__ __forceinline__ float edge_ex(float hlv, float hrv, float hev) {
    float s = hlv + hrv + hev;
    s = (s > 0.0f) ? s : NEG_SLOPE * s;
    return __expf(s);
}

__global__ __launch_bounds__(256) void k_aggregate(float* __restrict__ out) {
    int tid = threadIdx.x;
    int n = blockIdx.x * 4 + (tid >> 6);
    if (n >= N_NODES) return;
    int i = tid & 63;
    int head = i >> 3;

    int base = g_off[n];
    int deg = g_deg[n];
    const uint2* h2 = reinterpret_cast<const uint2*>(g_h16);
    float hrv = g_hr[n * NHEAD + head];

    float4 acc = make_float4(0.f, 0.f, 0.f, 0.f);
    float zacc = 0.f;
    int k = 0;
    for (; k + 8 <= deg; k += 8) {
        int v[8];
#pragma unroll
        for (int j = 0; j < 8; j++) v[j] = __ldg(&g_spack[base + k + j]);
        int r[8];
#pragma unroll
        for (int j = 0; j < 8; j++) r[j] = v[j] & PACK_MASK;
        uint2 u[8];
#pragma unroll
        for (int j = 0; j < 8; j++) u[j] = h2[r[j] * 64 + i];
        float hl[8];
#pragma unroll
        for (int j = 0; j < 8; j++) hl[j] = __ldg(&g_hl[r[j] * NHEAD + head]);
        float ex[8];
#pragma unroll
        for (int j = 0; j < 8; j++)
            ex[j] = edge_ex(hl[j], hrv, g_he[(v[j] >> 20) * NHEAD + head]);
#pragma unroll
        for (int j = 0; j < 8; j++) {
            float2 a = __half22float2(*reinterpret_cast<__half2*>(&u[j].x));
            float2 b = __half22float2(*reinterpret_cast<__half2*>(&u[j].y));
            acc.x += ex[j] * a.x; acc.y += ex[j] * a.y;
            acc.z += ex[j] * b.x; acc.w += ex[j] * b.y;
            zacc += ex[j];
        }
    }
    for (; k < deg; k++) {
        int v0 = __ldg(&g_spack[base + k]);
        int r0 = v0 & PACK_MASK;
        float ex0 = edge_ex(__ldg(&g_hl[r0 * NHEAD + head]), hrv,
                            g_he[(v0 >> 20) * NHEAD + head]);
        uint2 u0 = h2[r0 * 64 + i];
        float2 a0 = __half22float2(*reinterpret_cast<__half2*>(&u0.x));
        float2 b0 = __half22float2(*reinterpret_cast<__half2*>(&u0.y));
        acc.x += ex0 * a0.x; acc.y += ex0 * a0.y;
        acc.z += ex0 * b0.x; acc.w += ex0 * b0.y;
        zacc += ex0;
    }
    float inv = (deg > 0) ? (1.0f / zacc) : 0.0f;
    reinterpret_cast<float4*>(out)[n * 64 + i] =
        make_float4(acc.x * inv, acc.y * inv, acc.z * inv, acc.w * inv);
    if ((i & 7) == 0) g_z[n * NHEAD + head] = zacc;
}

// ---------------- K6: att output (edge order, recompute exp) ----------------
__global__ void k_attout(const int* __restrict__ row,
                         const int* __restrict__ col,
                         const int* __restrict__ tp,
                         float* __restrict__ attOut) {
    int idx = blockIdx.x * blockDim.x + threadIdx.x;
    if (idx >= N_EDGES * NHEAD) return;
    int e = idx >> 3, h = idx & 7;
    int r = __ldg(&row[e]);
    int c = __ldg(&col[e]);
    int t = __ldg(&tp[e]);
    float ex = edge_ex(g_hl[r * NHEAD + h], g_hr[c * NHEAD + h],
                       g_he[t * NHEAD + h]);
    attOut[idx] = ex / g_z[c * NHEAD + h];
}

// ---------------- launch ---------------------------------------------------------
extern "C" void kernel_launch(void* const* d_in, const int* in_sizes, int n_in,
                              void* d_out, int out_size) {
    const float* x        = (const float*)d_in[0];
    const float* W        = (const float*)d_in[1];
    const float* W_e      = (const float*)d_in[2];
    const float* edge_emb = (const float*)d_in[3];
    const float* a_l      = (const float*)d_in[4];
    const float* a_r      = (const float*)d_in[5];
    const float* a_e      = (const float*)d_in[6];
    const int*   row      = (const int*)d_in[7];
    const int*   col      = (const int*)d_in[8];
    const int*   tp       = (const int*)d_in[9];

    float* out = (float*)d_out;
    float* attOut = (out_size >= OUT_ELEMS + ATT_ELEMS) ? out + OUT_ELEMS : nullptr;

    static int inited = 0;
    if (!inited) {
        cudaFuncSetAttribute(k_gemm_mma, cudaFuncAttributeMaxDynamicSharedMemorySize,
                             SM_HALVES * 2);
        inited = 1;
    }

    k_wprep<<<(HD * IN_F + 255) / 256, 256>>>(W, edge_emb, W_e, a_e);
    k_hist<<<(N_EDGES + 255) / 256, 256>>>(col);
    k_scan1<<<SCAN_NB, 1024>>>();
    k_scan23<<<SCAN_NB, 1024>>>();
    k_scatter<<<(N_EDGES + 255) / 256, 256>>>(col, row, tp);

    k_gemm_mma<<<(N_NODES + 63) / 64, 256, SM_HALVES * 2>>>(x, a_l, a_r);

    k_aggregate<<<(N_NODES + 3) / 4, 256>>>(out);
    if (attOut)
        k_attout<<<(N_EDGES * NHEAD + 255) / 256, 256>>>(row, col, tp, attOut);
}

// round 11
// speedup vs baseline: 1.9437x; 1.2511x over previous
#include <cuda_runtime.h>
#include <cuda_bf16.h>
#include <cuda_fp16.h>
#include <math.h>
#include <stdint.h>

#define N_NODES 50000
#define N_EDGES 800000
#define IN_F 256
#define OUT_F 32
#define NHEAD 8
#define EDGE_F 32
#define N_ETYPES 8
#define NEG_SLOPE 0.1f

#define HD (NHEAD * OUT_F)            // 256
#define OUT_ELEMS (N_NODES * HD)
#define ATT_ELEMS (N_EDGES * NHEAD)
#define SCAN_NB ((N_NODES + 1023) / 1024)
#define PACK_MASK 0xFFFFF

// ---------------- scratch ----------------
__device__ __half    g_h16[N_NODES * HD];
__device__ float     g_hl[N_NODES * NHEAD];
__device__ float     g_hr[N_NODES * NHEAD];
__device__ float     g_z[N_NODES * NHEAD];
__device__ float     g_he[N_ETYPES * NHEAD];
__device__ int       g_deg[N_NODES];
__device__ int       g_off[N_NODES];
__device__ int       g_wptr[N_NODES];
__device__ int       g_bsum[SCAN_NB];
__device__ int       g_spack[N_EDGES];         // sorted pos -> row | (tp<<20)
__device__ __nv_bfloat16 g_wh[HD * IN_F];
__device__ __nv_bfloat16 g_wl[HD * IN_F];

// ---------------- K_wprep (+ zero deg + he) ----------------
__global__ void k_wprep(const float* __restrict__ W,
                        const float* __restrict__ edge_emb,
                        const float* __restrict__ W_e,
                        const float* __restrict__ a_e) {
    int idx = blockIdx.x * blockDim.x + threadIdx.x;
    if (idx < N_NODES) g_deg[idx] = 0;
    if (blockIdx.x == 0 && threadIdx.x < N_ETYPES * NHEAD) {
        int t = threadIdx.x >> 3, h = threadIdx.x & 7;
        float acc = 0.0f;
        for (int f = 0; f < EDGE_F; f++) {
            float ev = 0.0f;
            for (int k = 0; k < EDGE_F; k++)
                ev += edge_emb[t * EDGE_F + k] * W_e[k * (EDGE_F * NHEAD) + h * EDGE_F + f];
            acc += a_e[h * EDGE_F + f] * ev;
        }
        g_he[t * NHEAD + h] = acc;
    }
    if (idx >= HD * IN_F) return;
    int n = idx >> 8, k = idx & 255;
    float w = W[k * HD + n];
    __nv_bfloat16 h = __float2bfloat16(w);
    float r = w - __bfloat162float(h);
    g_wh[n * IN_F + k] = h;
    g_wl[n * IN_F + k] = __float2bfloat16(r);
}

// ---------------- K2: bf16 split-precision mma.sync GEMM (M-tile 128) ----------
#define XPAD 40
#define WPAD 40
#define OFF_XH 0
#define OFF_XL (OFF_XH + 128 * XPAD)
#define OFF_WH (OFF_XL + 128 * XPAD)
#define OFF_WL (OFF_WH + 256 * WPAD)
#define SM_HALVES (OFF_WL + 256 * WPAD)   // 30720 halves = 61440 B

__device__ __forceinline__ void mma_bf16(float* d, uint32_t a0, uint32_t a1,
                                         uint32_t a2, uint32_t a3,
                                         uint32_t b0, uint32_t b1) {
    asm volatile(
        "mma.sync.aligned.m16n8k16.row.col.f32.bf16.bf16.f32 "
        "{%0,%1,%2,%3}, {%4,%5,%6,%7}, {%8,%9}, {%0,%1,%2,%3};"
        : "+f"(d[0]), "+f"(d[1]), "+f"(d[2]), "+f"(d[3])
        : "r"(a0), "r"(a1), "r"(a2), "r"(a3), "r"(b0), "r"(b1));
}
__device__ __forceinline__ float nanfix(float v) { return isnan(v) ? 0.0f : v; }
__device__ __forceinline__ uint32_t smem_u32(const void* p) {
    uint32_t a;
    asm("{ .reg .u64 t; cvta.to.shared.u64 t, %1; cvt.u32.u64 %0, t; }" : "=r"(a) : "l"(p));
    return a;
}
#define CP_ASYNC16(dst_u32, src_ptr) \
    asm volatile("cp.async.ca.shared.global [%0], [%1], 16;" :: "r"(dst_u32), "l"(src_ptr))
#define CP_COMMIT() asm volatile("cp.async.commit_group;")
#define CP_WAIT0()  asm volatile("cp.async.wait_group 0;")

__global__ __launch_bounds__(512) void k_gemm_mma(const float* __restrict__ x,
                                                  const float* __restrict__ a_l,
                                                  const float* __restrict__ a_r) {
    extern __shared__ __align__(16) uint16_t sm[];
    uint16_t* sXh = sm + OFF_XH;
    uint16_t* sXl = sm + OFF_XL;
    uint16_t* sWh = sm + OFF_WH;
    uint16_t* sWl = sm + OFF_WL;
    uint32_t sb = smem_u32(sm);

    int tid = threadIdx.x;
    int lane = tid & 31;
    int wid = tid >> 5;          // 0..15
    int warp_m = wid & 7;        // 8 M-slices of 16
    int warp_n = wid >> 3;       // 2 N-slices of 128
    int m0 = blockIdx.x * 128;

    float acc[16][4];
#pragma unroll
    for (int t = 0; t < 16; t++)
#pragma unroll
        for (int j = 0; j < 4; j++) acc[t][j] = 0.0f;

    for (int ks = 0; ks < 8; ks++) {
        int k0 = ks * 32;
        __syncthreads();
        // --- W stage via cp.async: 512 threads, n = tid>>1, half k-range each ---
        {
            int n = tid >> 1;
            int j0 = (tid & 1) * 2;
            uint32_t dWh = sb + (OFF_WH + n * WPAD) * 2;
            uint32_t dWl = sb + (OFF_WL + n * WPAD) * 2;
            const __nv_bfloat16* srch = g_wh + n * IN_F + k0;
            const __nv_bfloat16* srcl = g_wl + n * IN_F + k0;
#pragma unroll
            for (int j = 0; j < 2; j++) {
                CP_ASYNC16(dWh + (j0 + j) * 16, srch + (j0 + j) * 8);
                CP_ASYNC16(dWl + (j0 + j) * 16, srcl + (j0 + j) * 8);
            }
            CP_COMMIT();
        }
        // --- x stage: 512 threads, r = tid>>2 (0..127), 8 floats each ---
        {
            int r = tid >> 2, q = tid & 3;
            int gm = m0 + r;
            float v[8];
            if (gm < N_NODES) {
                const float4* src = reinterpret_cast<const float4*>(x + gm * IN_F + k0 + q * 8);
                float4 f0 = src[0], f1 = src[1];
                v[0] = f0.x; v[1] = f0.y; v[2] = f0.z; v[3] = f0.w;
                v[4] = f1.x; v[5] = f1.y; v[6] = f1.z; v[7] = f1.w;
            } else {
#pragma unroll
                for (int j = 0; j < 8; j++) v[j] = 0.0f;
            }
            uint32_t hi[4], lo[4];
#pragma unroll
            for (int j = 0; j < 4; j++) {
                __nv_bfloat16 h0 = __float2bfloat16(v[2 * j]);
                __nv_bfloat16 h1 = __float2bfloat16(v[2 * j + 1]);
                hi[j] = (uint32_t)__bfloat16_as_ushort(h0) |
                        ((uint32_t)__bfloat16_as_ushort(h1) << 16);
                __nv_bfloat16 l0 = __float2bfloat16(v[2 * j] - __bfloat162float(h0));
                __nv_bfloat16 l1 = __float2bfloat16(v[2 * j + 1] - __bfloat162float(h1));
                lo[j] = (uint32_t)__bfloat16_as_ushort(l0) |
                        ((uint32_t)__bfloat16_as_ushort(l1) << 16);
            }
            *reinterpret_cast<uint4*>(&sXh[r * XPAD + q * 8]) = make_uint4(hi[0], hi[1], hi[2], hi[3]);
            *reinterpret_cast<uint4*>(&sXl[r * XPAD + q * 8]) = make_uint4(lo[0], lo[1], lo[2], lo[3]);
        }
        CP_WAIT0();
        __syncthreads();
#pragma unroll
        for (int kin = 0; kin < 32; kin += 16) {
            int c = (lane & 3) * 2 + kin;
            int ra = (warp_m * 16 + (lane >> 2)) * XPAD;
            uint32_t ah0 = *reinterpret_cast<uint32_t*>(&sXh[ra + c]);
            uint32_t ah1 = *reinterpret_cast<uint32_t*>(&sXh[ra + 8 * XPAD + c]);
            uint32_t ah2 = *reinterpret_cast<uint32_t*>(&sXh[ra + c + 8]);
            uint32_t ah3 = *reinterpret_cast<uint32_t*>(&sXh[ra + 8 * XPAD + c + 8]);
            uint32_t al0 = *reinterpret_cast<uint32_t*>(&sXl[ra + c]);
            uint32_t al1 = *reinterpret_cast<uint32_t*>(&sXl[ra + 8 * XPAD + c]);
            uint32_t al2 = *reinterpret_cast<uint32_t*>(&sXl[ra + c + 8]);
            uint32_t al3 = *reinterpret_cast<uint32_t*>(&sXl[ra + 8 * XPAD + c + 8]);
#pragma unroll
            for (int t = 0; t < 16; t++) {
                int nb = (warp_n * 128 + t * 8 + (lane >> 2)) * WPAD + (lane & 3) * 2 + kin;
                uint32_t bh0 = *reinterpret_cast<uint32_t*>(&sWh[nb]);
                uint32_t bh1 = *reinterpret_cast<uint32_t*>(&sWh[nb + 8]);
                uint32_t bl0 = *reinterpret_cast<uint32_t*>(&sWl[nb]);
                uint32_t bl1 = *reinterpret_cast<uint32_t*>(&sWl[nb + 8]);
                mma_bf16(acc[t], ah0, ah1, ah2, ah3, bh0, bh1);
                mma_bf16(acc[t], ah0, ah1, ah2, ah3, bl0, bl1);
                mma_bf16(acc[t], al0, al1, al2, al3, bh0, bh1);
            }
        }
    }

    int r = lane >> 2;
    int gr0 = m0 + warp_m * 16 + r;
    int gr1 = gr0 + 8;
    bool ok0 = (gr0 < N_NODES), ok1 = (gr1 < N_NODES);
    float dl0[4] = {0, 0, 0, 0}, dl1[4] = {0, 0, 0, 0};
    float dr0[4] = {0, 0, 0, 0}, dr1[4] = {0, 0, 0, 0};
#pragma unroll
    for (int t = 0; t < 16; t++) {
        int n = warp_n * 128 + t * 8 + (lane & 3) * 2;
        float v0 = nanfix(acc[t][0]), v1 = nanfix(acc[t][1]);
        float v2 = nanfix(acc[t][2]), v3 = nanfix(acc[t][3]);
        float alv0 = __ldg(&a_l[n]), alv1 = __ldg(&a_l[n + 1]);
        float arv0 = __ldg(&a_r[n]), arv1 = __ldg(&a_r[n + 1]);
        int hh = t >> 2;
        dl0[hh] += v0 * alv0 + v1 * alv1;
        dr0[hh] += v0 * arv0 + v1 * arv1;
        dl1[hh] += v2 * alv0 + v3 * alv1;
        dr1[hh] += v2 * arv0 + v3 * arv1;
        if (ok0) *reinterpret_cast<__half2*>(&g_h16[gr0 * HD + n]) = __floats2half2_rn(v0, v1);
        if (ok1) *reinterpret_cast<__half2*>(&g_h16[gr1 * HD + n]) = __floats2half2_rn(v2, v3);
    }
#pragma unroll
    for (int hh = 0; hh < 4; hh++) {
#pragma unroll
        for (int o = 1; o <= 2; o <<= 1) {
            dl0[hh] += __shfl_xor_sync(0xffffffffu, dl0[hh], o);
            dl1[hh] += __shfl_xor_sync(0xffffffffu, dl1[hh], o);
            dr0[hh] += __shfl_xor_sync(0xffffffffu, dr0[hh], o);
            dr1[hh] += __shfl_xor_sync(0xffffffffu, dr1[hh], o);
        }
    }
    if ((lane & 3) == 0) {
#pragma unroll
        for (int hh = 0; hh < 4; hh++) {
            int head = warp_n * 4 + hh;
            if (ok0) { g_hl[gr0 * NHEAD + head] = dl0[hh]; g_hr[gr0 * NHEAD + head] = dr0[hh]; }
            if (ok1) { g_hl[gr1 * NHEAD + head] = dl1[hh]; g_hr[gr1 * NHEAD + head] = dr1[hh]; }
        }
    }
}

// ---------------- CSR build ----------------
__global__ void k_hist(const int* __restrict__ col) {
    int e = blockIdx.x * blockDim.x + threadIdx.x;
    if (e < N_EDGES) atomicAdd(&g_deg[__ldg(&col[e])], 1);
}
__global__ __launch_bounds__(1024) void k_scan1() {
    __shared__ int sh[1024];
    int t = threadIdx.x;
    int idx = blockIdx.x * 1024 + t;
    int v = (idx < N_NODES) ? g_deg[idx] : 0;
    sh[t] = v;
    __syncthreads();
#pragma unroll
    for (int off = 1; off < 1024; off <<= 1) {
        int add = (t >= off) ? sh[t - off] : 0;
        __syncthreads();
        sh[t] += add;
        __syncthreads();
    }
    if (idx < N_NODES) g_off[idx] = sh[t] - v;
    if (t == 1023) g_bsum[blockIdx.x] = sh[t];
}
__global__ __launch_bounds__(1024) void k_scan23() {
    __shared__ int s_base;
    int t = threadIdx.x;
    int bid = blockIdx.x;
    if (t < 32) {
        int v = 0;
        for (int j = t; j < SCAN_NB; j += 32)
            if (j < bid) v += g_bsum[j];
#pragma unroll
        for (int o = 16; o; o >>= 1) v += __shfl_xor_sync(0xffffffffu, v, o);
        if (t == 0) s_base = v;
    }
    __syncthreads();
    int idx = bid * 1024 + t;
    if (idx < N_NODES) {
        int o = g_off[idx] + s_base;
        g_off[idx] = o;
        g_wptr[idx] = o;
    }
}
__global__ void k_scatter(const int* __restrict__ col, const int* __restrict__ row,
                          const int* __restrict__ tp) {
    int e = blockIdx.x * blockDim.x + threadIdx.x;
    if (e >= N_EDGES) return;
    int c = __ldg(&col[e]);
    int pos = atomicAdd(&g_wptr[c], 1);
    g_spack[pos] = __ldg(&row[e]) | (__ldg(&tp[e]) << 20);
}

// ---------------- K5: fused edge-softmax + gather, WARP per node ----------------
__device__ __forceinline__ float edge_ex(float hlv, float hrv, float hev) {
    float s = hlv + hrv + hev;
    s = (s > 0.0f) ? s : NEG_SLOPE * s;
    return __expf(s);
}

__global__ __launch_bounds__(256) void k_aggregate(float* __restrict__ out) {
    int tid = threadIdx.x;
    int lane = tid & 31;
    int n = blockIdx.x * 8 + (tid >> 5);
    if (n >= N_NODES) return;
    int head = lane >> 2;               // lane owns halves [8*lane, 8*lane+8)

    int base = g_off[n];
    int deg = g_deg[n];
    const uint4* h4 = reinterpret_cast<const uint4*>(g_h16);  // 8 halves per uint4
    float hrv = g_hr[n * NHEAD + head];

    float acc[8];
#pragma unroll
    for (int j = 0; j < 8; j++) acc[j] = 0.0f;
    float zacc = 0.f;

    int k = 0;
    for (; k + 4 <= deg; k += 4) {
        int v[4];
#pragma unroll
        for (int j = 0; j < 4; j++) v[j] = __ldg(&g_spack[base + k + j]);
        int r[4];
#pragma unroll
        for (int j = 0; j < 4; j++) r[j] = v[j] & PACK_MASK;
        uint4 u[4];
#pragma unroll
        for (int j = 0; j < 4; j++) u[j] = h4[r[j] * 32 + lane];
        float hl[4];
#pragma unroll
        for (int j = 0; j < 4; j++) hl[j] = __ldg(&g_hl[r[j] * NHEAD + head]);
        float ex[4];
#pragma unroll
        for (int j = 0; j < 4; j++)
            ex[j] = edge_ex(hl[j], hrv, g_he[(v[j] >> 20) * NHEAD + head]);
#pragma unroll
        for (int j = 0; j < 4; j++) {
            float2 p0 = __half22float2(*reinterpret_cast<__half2*>(&u[j].x));
            float2 p1 = __half22float2(*reinterpret_cast<__half2*>(&u[j].y));
            float2 p2 = __half22float2(*reinterpret_cast<__half2*>(&u[j].z));
            float2 p3 = __half22float2(*reinterpret_cast<__half2*>(&u[j].w));
            acc[0] += ex[j] * p0.x; acc[1] += ex[j] * p0.y;
            acc[2] += ex[j] * p1.x; acc[3] += ex[j] * p1.y;
            acc[4] += ex[j] * p2.x; acc[5] += ex[j] * p2.y;
            acc[6] += ex[j] * p3.x; acc[7] += ex[j] * p3.y;
            zacc += ex[j];
        }
    }
    for (; k < deg; k++) {
        int v0 = __ldg(&g_spack[base + k]);
        int r0 = v0 & PACK_MASK;
        float ex0 = edge_ex(__ldg(&g_hl[r0 * NHEAD + head]), hrv,
                            g_he[(v0 >> 20) * NHEAD + head]);
        uint4 u0 = h4[r0 * 32 + lane];
        float2 p0 = __half22float2(*reinterpret_cast<__half2*>(&u0.x));
        float2 p1 = __half22float2(*reinterpret_cast<__half2*>(&u0.y));
        float2 p2 = __half22float2(*reinterpret_cast<__half2*>(&u0.z));
        float2 p3 = __half22float2(*reinterpret_cast<__half2*>(&u0.w));
        acc[0] += ex0 * p0.x; acc[1] += ex0 * p0.y;
        acc[2] += ex0 * p1.x; acc[3] += ex0 * p1.y;
        acc[4] += ex0 * p2.x; acc[5] += ex0 * p2.y;
        acc[6] += ex0 * p3.x; acc[7] += ex0 * p3.y;
        zacc += ex0;
    }
    float inv = (deg > 0) ? (1.0f / zacc) : 0.0f;
    float4* o4 = reinterpret_cast<float4*>(out) + n * 64 + lane * 2;
    o4[0] = make_float4(acc[0] * inv, acc[1] * inv, acc[2] * inv, acc[3] * inv);
    o4[1] = make_float4(acc[4] * inv, acc[5] * inv, acc[6] * inv, acc[7] * inv);
    if ((lane & 3) == 0) g_z[n * NHEAD + head] = zacc;
}

// ---------------- K6: att output (edge order, recompute exp) ----------------
__global__ void k_attout(const int* __restrict__ row,
                         const int* __restrict__ col,
                         const int* __restrict__ tp,
                         float* __restrict__ attOut) {
    int idx = blockIdx.x * blockDim.x + threadIdx.x;
    if (idx >= N_EDGES * NHEAD) return;
    int e = idx >> 3, h = idx & 7;
    int r = __ldg(&row[e]);
    int c = __ldg(&col[e]);
    int t = __ldg(&tp[e]);
    float ex = edge_ex(g_hl[r * NHEAD + h], g_hr[c * NHEAD + h],
                       g_he[t * NHEAD + h]);
    attOut[idx] = ex / g_z[c * NHEAD + h];
}

// ---------------- launch ---------------------------------------------------------
extern "C" void kernel_launch(void* const* d_in, const int* in_sizes, int n_in,
                              void* d_out, int out_size) {
    const float* x        = (const float*)d_in[0];
    const float* W        = (const float*)d_in[1];
    const float* W_e      = (const float*)d_in[2];
    const float* edge_emb = (const float*)d_in[3];
    const float* a_l      = (const float*)d_in[4];
    const float* a_r      = (const float*)d_in[5];
    const float* a_e      = (const float*)d_in[6];
    const int*   row      = (const int*)d_in[7];
    const int*   col      = (const int*)d_in[8];
    const int*   tp       = (const int*)d_in[9];

    float* out = (float*)d_out;
    float* attOut = (out_size >= OUT_ELEMS + ATT_ELEMS) ? out + OUT_ELEMS : nullptr;

    static int inited = 0;
    if (!inited) {
        cudaFuncSetAttribute(k_gemm_mma, cudaFuncAttributeMaxDynamicSharedMemorySize,
                             SM_HALVES * 2);
        inited = 1;
    }

    k_wprep<<<(HD * IN_F + 255) / 256, 256>>>(W, edge_emb, W_e, a_e);
    k_hist<<<(N_EDGES + 255) / 256, 256>>>(col);
    k_scan1<<<SCAN_NB, 1024>>>();
    k_scan23<<<SCAN_NB, 1024>>>();
    k_scatter<<<(N_EDGES + 255) / 256, 256>>>(col, row, tp);

    k_gemm_mma<<<(N_NODES + 127) / 128, 512, SM_HALVES * 2>>>(x, a_l, a_r);

    k_aggregate<<<(N_NODES + 7) / 8, 256>>>(out);
    if (attOut)
        k_attout<<<(N_EDGES * NHEAD + 255) / 256, 256>>>(row, col, tp, attOut);
}

// round 12
// speedup vs baseline: 1.9854x; 1.0215x over previous
#include <cuda_runtime.h>
#include <cuda_bf16.h>
#include <cuda_fp16.h>
#include <math.h>
#include <stdint.h>

#define N_NODES 50000
#define N_EDGES 800000
#define IN_F 256
#define OUT_F 32
#define NHEAD 8
#define EDGE_F 32
#define N_ETYPES 8
#define NEG_SLOPE 0.1f

#define HD (NHEAD * OUT_F)            // 256
#define OUT_ELEMS (N_NODES * HD)
#define ATT_ELEMS (N_EDGES * NHEAD)
#define SCAN_NB ((N_NODES + 1023) / 1024)
#define PACK_MASK 0xFFFFF

// ---------------- scratch ----------------
__device__ __half    g_h16[N_NODES * HD];
__device__ float     g_hl[N_NODES * NHEAD];
__device__ float     g_hr[N_NODES * NHEAD];
__device__ float     g_z[N_NODES * NHEAD];
__device__ float     g_he[N_ETYPES * NHEAD];
__device__ int       g_deg[N_NODES];
__device__ int       g_off[N_NODES];
__device__ int       g_wptr[N_NODES];
__device__ int       g_bsum[SCAN_NB];
__device__ int       g_spack[N_EDGES];         // sorted pos -> row | (tp<<20)
__device__ __nv_bfloat16 g_wh[HD * IN_F];
__device__ __nv_bfloat16 g_wl[HD * IN_F];

// ---------------- K_wprep (+ he) ----------------
__global__ void k_wprep(const float* __restrict__ W,
                        const float* __restrict__ edge_emb,
                        const float* __restrict__ W_e,
                        const float* __restrict__ a_e) {
    int idx = blockIdx.x * blockDim.x + threadIdx.x;
    if (blockIdx.x == 0 && threadIdx.x < N_ETYPES * NHEAD) {
        int t = threadIdx.x >> 3, h = threadIdx.x & 7;
        float acc = 0.0f;
        for (int f = 0; f < EDGE_F; f++) {
            float ev = 0.0f;
            for (int k = 0; k < EDGE_F; k++)
                ev += edge_emb[t * EDGE_F + k] * W_e[k * (EDGE_F * NHEAD) + h * EDGE_F + f];
            acc += a_e[h * EDGE_F + f] * ev;
        }
        g_he[t * NHEAD + h] = acc;
    }
    if (idx >= HD * IN_F) return;
    int n = idx >> 8, k = idx & 255;
    float w = W[k * HD + n];
    __nv_bfloat16 h = __float2bfloat16(w);
    float r = w - __bfloat162float(h);
    g_wh[n * IN_F + k] = h;
    g_wl[n * IN_F + k] = __float2bfloat16(r);
}

// ---------------- K2: bf16 split-precision mma.sync GEMM (M-tile 128) ----------
#define XPAD 40
#define WPAD 40
#define OFF_XH 0
#define OFF_XL (OFF_XH + 128 * XPAD)
#define OFF_WH (OFF_XL + 128 * XPAD)
#define OFF_WL (OFF_WH + 256 * WPAD)
#define SM_HALVES (OFF_WL + 256 * WPAD)   // 30720 halves = 61440 B

__device__ __forceinline__ void mma_bf16(float* d, uint32_t a0, uint32_t a1,
                                         uint32_t a2, uint32_t a3,
                                         uint32_t b0, uint32_t b1) {
    asm volatile(
        "mma.sync.aligned.m16n8k16.row.col.f32.bf16.bf16.f32 "
        "{%0,%1,%2,%3}, {%4,%5,%6,%7}, {%8,%9}, {%0,%1,%2,%3};"
        : "+f"(d[0]), "+f"(d[1]), "+f"(d[2]), "+f"(d[3])
        : "r"(a0), "r"(a1), "r"(a2), "r"(a3), "r"(b0), "r"(b1));
}
__device__ __forceinline__ float nanfix(float v) { return isnan(v) ? 0.0f : v; }
__device__ __forceinline__ uint32_t smem_u32(const void* p) {
    uint32_t a;
    asm("{ .reg .u64 t; cvta.to.shared.u64 t, %1; cvt.u32.u64 %0, t; }" : "=r"(a) : "l"(p));
    return a;
}
#define CP_ASYNC16(dst_u32, src_ptr) \
    asm volatile("cp.async.ca.shared.global [%0], [%1], 16;" :: "r"(dst_u32), "l"(src_ptr))
#define CP_COMMIT() asm volatile("cp.async.commit_group;")
#define CP_WAIT0()  asm volatile("cp.async.wait_group 0;")

__global__ __launch_bounds__(512) void k_gemm_mma(const float* __restrict__ x,
                                                  const float* __restrict__ a_l,
                                                  const float* __restrict__ a_r) {
    extern __shared__ __align__(16) uint16_t sm[];
    uint16_t* sXh = sm + OFF_XH;
    uint16_t* sXl = sm + OFF_XL;
    uint16_t* sWh = sm + OFF_WH;
    uint16_t* sWl = sm + OFF_WL;
    uint32_t sb = smem_u32(sm);

    int tid = threadIdx.x;
    int lane = tid & 31;
    int wid = tid >> 5;          // 0..15
    int warp_m = wid & 7;        // 8 M-slices of 16
    int warp_n = wid >> 3;       // 2 N-slices of 128
    int m0 = blockIdx.x * 128;

    float acc[16][4];
#pragma unroll
    for (int t = 0; t < 16; t++)
#pragma unroll
        for (int j = 0; j < 4; j++) acc[t][j] = 0.0f;

    for (int ks = 0; ks < 8; ks++) {
        int k0 = ks * 32;
        __syncthreads();
        {
            int n = tid >> 1;
            int j0 = (tid & 1) * 2;
            uint32_t dWh = sb + (OFF_WH + n * WPAD) * 2;
            uint32_t dWl = sb + (OFF_WL + n * WPAD) * 2;
            const __nv_bfloat16* srch = g_wh + n * IN_F + k0;
            const __nv_bfloat16* srcl = g_wl + n * IN_F + k0;
#pragma unroll
            for (int j = 0; j < 2; j++) {
                CP_ASYNC16(dWh + (j0 + j) * 16, srch + (j0 + j) * 8);
                CP_ASYNC16(dWl + (j0 + j) * 16, srcl + (j0 + j) * 8);
            }
            CP_COMMIT();
        }
        {
            int r = tid >> 2, q = tid & 3;
            int gm = m0 + r;
            float v[8];
            if (gm < N_NODES) {
                const float4* src = reinterpret_cast<const float4*>(x + gm * IN_F + k0 + q * 8);
                float4 f0 = src[0], f1 = src[1];
                v[0] = f0.x; v[1] = f0.y; v[2] = f0.z; v[3] = f0.w;
                v[4] = f1.x; v[5] = f1.y; v[6] = f1.z; v[7] = f1.w;
            } else {
#pragma unroll
                for (int j = 0; j < 8; j++) v[j] = 0.0f;
            }
            uint32_t hi[4], lo[4];
#pragma unroll
            for (int j = 0; j < 4; j++) {
                __nv_bfloat16 h0 = __float2bfloat16(v[2 * j]);
                __nv_bfloat16 h1 = __float2bfloat16(v[2 * j + 1]);
                hi[j] = (uint32_t)__bfloat16_as_ushort(h0) |
                        ((uint32_t)__bfloat16_as_ushort(h1) << 16);
                __nv_bfloat16 l0 = __float2bfloat16(v[2 * j] - __bfloat162float(h0));
                __nv_bfloat16 l1 = __float2bfloat16(v[2 * j + 1] - __bfloat162float(h1));
                lo[j] = (uint32_t)__bfloat16_as_ushort(l0) |
                        ((uint32_t)__bfloat16_as_ushort(l1) << 16);
            }
            *reinterpret_cast<uint4*>(&sXh[r * XPAD + q * 8]) = make_uint4(hi[0], hi[1], hi[2], hi[3]);
            *reinterpret_cast<uint4*>(&sXl[r * XPAD + q * 8]) = make_uint4(lo[0], lo[1], lo[2], lo[3]);
        }
        CP_WAIT0();
        __syncthreads();
#pragma unroll
        for (int kin = 0; kin < 32; kin += 16) {
            int c = (lane & 3) * 2 + kin;
            int ra = (warp_m * 16 + (lane >> 2)) * XPAD;
            uint32_t ah0 = *reinterpret_cast<uint32_t*>(&sXh[ra + c]);
            uint32_t ah1 = *reinterpret_cast<uint32_t*>(&sXh[ra + 8 * XPAD + c]);
            uint32_t ah2 = *reinterpret_cast<uint32_t*>(&sXh[ra + c + 8]);
            uint32_t ah3 = *reinterpret_cast<uint32_t*>(&sXh[ra + 8 * XPAD + c + 8]);
            uint32_t al0 = *reinterpret_cast<uint32_t*>(&sXl[ra + c]);
            uint32_t al1 = *reinterpret_cast<uint32_t*>(&sXl[ra + 8 * XPAD + c]);
            uint32_t al2 = *reinterpret_cast<uint32_t*>(&sXl[ra + c + 8]);
            uint32_t al3 = *reinterpret_cast<uint32_t*>(&sXl[ra + 8 * XPAD + c + 8]);
#pragma unroll
            for (int t = 0; t < 16; t++) {
                int nb = (warp_n * 128 + t * 8 + (lane >> 2)) * WPAD + (lane & 3) * 2 + kin;
                uint32_t bh0 = *reinterpret_cast<uint32_t*>(&sWh[nb]);
                uint32_t bh1 = *reinterpret_cast<uint32_t*>(&sWh[nb + 8]);
                uint32_t bl0 = *reinterpret_cast<uint32_t*>(&sWl[nb]);
                uint32_t bl1 = *reinterpret_cast<uint32_t*>(&sWl[nb + 8]);
                mma_bf16(acc[t], ah0, ah1, ah2, ah3, bh0, bh1);
                mma_bf16(acc[t], ah0, ah1, ah2, ah3, bl0, bl1);
                mma_bf16(acc[t], al0, al1, al2, al3, bh0, bh1);
            }
        }
    }

    int r = lane >> 2;
    int gr0 = m0 + warp_m * 16 + r;
    int gr1 = gr0 + 8;
    bool ok0 = (gr0 < N_NODES), ok1 = (gr1 < N_NODES);
    float dl0[4] = {0, 0, 0, 0}, dl1[4] = {0, 0, 0, 0};
    float dr0[4] = {0, 0, 0, 0}, dr1[4] = {0, 0, 0, 0};
#pragma unroll
    for (int t = 0; t < 16; t++) {
        int n = warp_n * 128 + t * 8 + (lane & 3) * 2;
        float v0 = nanfix(acc[t][0]), v1 = nanfix(acc[t][1]);
        float v2 = nanfix(acc[t][2]), v3 = nanfix(acc[t][3]);
        float alv0 = __ldg(&a_l[n]), alv1 = __ldg(&a_l[n + 1]);
        float arv0 = __ldg(&a_r[n]), arv1 = __ldg(&a_r[n + 1]);
        int hh = t >> 2;
        dl0[hh] += v0 * alv0 + v1 * alv1;
        dr0[hh] += v0 * arv0 + v1 * arv1;
        dl1[hh] += v2 * alv0 + v3 * alv1;
        dr1[hh] += v2 * arv0 + v3 * arv1;
        if (ok0) *reinterpret_cast<__half2*>(&g_h16[gr0 * HD + n]) = __floats2half2_rn(v0, v1);
        if (ok1) *reinterpret_cast<__half2*>(&g_h16[gr1 * HD + n]) = __floats2half2_rn(v2, v3);
    }
#pragma unroll
    for (int hh = 0; hh < 4; hh++) {
#pragma unroll
        for (int o = 1; o <= 2; o <<= 1) {
            dl0[hh] += __shfl_xor_sync(0xffffffffu, dl0[hh], o);
            dl1[hh] += __shfl_xor_sync(0xffffffffu, dl1[hh], o);
            dr0[hh] += __shfl_xor_sync(0xffffffffu, dr0[hh], o);
            dr1[hh] += __shfl_xor_sync(0xffffffffu, dr1[hh], o);
        }
    }
    if ((lane & 3) == 0) {
#pragma unroll
        for (int hh = 0; hh < 4; hh++) {
            int head = warp_n * 4 + hh;
            if (ok0) { g_hl[gr0 * NHEAD + head] = dl0[hh]; g_hr[gr0 * NHEAD + head] = dr0[hh]; }
            if (ok1) { g_hl[gr1 * NHEAD + head] = dl1[hh]; g_hr[gr1 * NHEAD + head] = dr1[hh]; }
        }
    }
}

// ---------------- CSR build ----------------
__global__ void k_zero_deg() {
    int i = blockIdx.x * blockDim.x + threadIdx.x;
    if (i < N_NODES) g_deg[i] = 0;
}
__global__ void k_hist(const int* __restrict__ col) {
    int e = blockIdx.x * blockDim.x + threadIdx.x;
    if (e < N_EDGES) atomicAdd(&g_deg[__ldg(&col[e])], 1);
}
__global__ __launch_bounds__(1024) void k_scan1() {
    __shared__ int sh[1024];
    int t = threadIdx.x;
    int idx = blockIdx.x * 1024 + t;
    int v = (idx < N_NODES) ? g_deg[idx] : 0;
    sh[t] = v;
    __syncthreads();
#pragma unroll
    for (int off = 1; off < 1024; off <<= 1) {
        int add = (t >= off) ? sh[t - off] : 0;
        __syncthreads();
        sh[t] += add;
        __syncthreads();
    }
    if (idx < N_NODES) g_off[idx] = sh[t] - v;
    if (t == 1023) g_bsum[blockIdx.x] = sh[t];
}
__global__ __launch_bounds__(1024) void k_scan23() {
    __shared__ int s_base;
    int t = threadIdx.x;
    int bid = blockIdx.x;
    if (t < 32) {
        int v = 0;
        for (int j = t; j < SCAN_NB; j += 32)
            if (j < bid) v += g_bsum[j];
#pragma unroll
        for (int o = 16; o; o >>= 1) v += __shfl_xor_sync(0xffffffffu, v, o);
        if (t == 0) s_base = v;
    }
    __syncthreads();
    int idx = bid * 1024 + t;
    if (idx < N_NODES) {
        int o = g_off[idx] + s_base;
        g_off[idx] = o;
        g_wptr[idx] = o;
    }
}
__global__ void k_scatter(const int* __restrict__ col, const int* __restrict__ row,
                          const int* __restrict__ tp) {
    int e = blockIdx.x * blockDim.x + threadIdx.x;
    if (e >= N_EDGES) return;
    int c = __ldg(&col[e]);
    int pos = atomicAdd(&g_wptr[c], 1);
    g_spack[pos] = __ldg(&row[e]) | (__ldg(&tp[e]) << 20);
}

// ---------------- K5: fused edge-softmax + gather, WARP per node ----------------
__device__ __forceinline__ float edge_ex(float hlv, float hrv, float hev) {
    float s = hlv + hrv + hev;
    s = (s > 0.0f) ? s : NEG_SLOPE * s;
    return __expf(s);
}

__global__ __launch_bounds__(256) void k_aggregate(float* __restrict__ out) {
    int tid = threadIdx.x;
    int lane = tid & 31;
    int n = blockIdx.x * 8 + (tid >> 5);
    if (n >= N_NODES) return;
    int head = lane >> 2;

    int base = g_off[n];
    int deg = g_deg[n];
    const uint4* h4 = reinterpret_cast<const uint4*>(g_h16);
    float hrv = g_hr[n * NHEAD + head];

    float acc[8];
#pragma unroll
    for (int j = 0; j < 8; j++) acc[j] = 0.0f;
    float zacc = 0.f;

    int k = 0;
    for (; k + 4 <= deg; k += 4) {
        int v[4];
#pragma unroll
        for (int j = 0; j < 4; j++) v[j] = __ldg(&g_spack[base + k + j]);
        int r[4];
#pragma unroll
        for (int j = 0; j < 4; j++) r[j] = v[j] & PACK_MASK;
        uint4 u[4];
#pragma unroll
        for (int j = 0; j < 4; j++) u[j] = h4[r[j] * 32 + lane];
        float hl[4];
#pragma unroll
        for (int j = 0; j < 4; j++) hl[j] = __ldg(&g_hl[r[j] * NHEAD + head]);
        float ex[4];
#pragma unroll
        for (int j = 0; j < 4; j++)
            ex[j] = edge_ex(hl[j], hrv, g_he[(v[j] >> 20) * NHEAD + head]);
#pragma unroll
        for (int j = 0; j < 4; j++) {
            float2 p0 = __half22float2(*reinterpret_cast<__half2*>(&u[j].x));
            float2 p1 = __half22float2(*reinterpret_cast<__half2*>(&u[j].y));
            float2 p2 = __half22float2(*reinterpret_cast<__half2*>(&u[j].z));
            float2 p3 = __half22float2(*reinterpret_cast<__half2*>(&u[j].w));
            acc[0] += ex[j] * p0.x; acc[1] += ex[j] * p0.y;
            acc[2] += ex[j] * p1.x; acc[3] += ex[j] * p1.y;
            acc[4] += ex[j] * p2.x; acc[5] += ex[j] * p2.y;
            acc[6] += ex[j] * p3.x; acc[7] += ex[j] * p3.y;
            zacc += ex[j];
        }
    }
    for (; k < deg; k++) {
        int v0 = __ldg(&g_spack[base + k]);
        int r0 = v0 & PACK_MASK;
        float ex0 = edge_ex(__ldg(&g_hl[r0 * NHEAD + head]), hrv,
                            g_he[(v0 >> 20) * NHEAD + head]);
        uint4 u0 = h4[r0 * 32 + lane];
        float2 p0 = __half22float2(*reinterpret_cast<__half2*>(&u0.x));
        float2 p1 = __half22float2(*reinterpret_cast<__half2*>(&u0.y));
        float2 p2 = __half22float2(*reinterpret_cast<__half2*>(&u0.z));
        float2 p3 = __half22float2(*reinterpret_cast<__half2*>(&u0.w));
        acc[0] += ex0 * p0.x; acc[1] += ex0 * p0.y;
        acc[2] += ex0 * p1.x; acc[3] += ex0 * p1.y;
        acc[4] += ex0 * p2.x; acc[5] += ex0 * p2.y;
        acc[6] += ex0 * p3.x; acc[7] += ex0 * p3.y;
        zacc += ex0;
    }
    float inv = (deg > 0) ? (1.0f / zacc) : 0.0f;
    float4* o4 = reinterpret_cast<float4*>(out) + n * 64 + lane * 2;
    o4[0] = make_float4(acc[0] * inv, acc[1] * inv, acc[2] * inv, acc[3] * inv);
    o4[1] = make_float4(acc[4] * inv, acc[5] * inv, acc[6] * inv, acc[7] * inv);
    if ((lane & 3) == 0) g_z[n * NHEAD + head] = zacc;
}

// ---------------- K6: att output (edge order, recompute exp) ----------------
__global__ void k_attout(const int* __restrict__ row,
                         const int* __restrict__ col,
                         const int* __restrict__ tp,
                         float* __restrict__ attOut) {
    int idx = blockIdx.x * blockDim.x + threadIdx.x;
    if (idx >= N_EDGES * NHEAD) return;
    int e = idx >> 3, h = idx & 7;
    int r = __ldg(&row[e]);
    int c = __ldg(&col[e]);
    int t = __ldg(&tp[e]);
    float ex = edge_ex(g_hl[r * NHEAD + h], g_hr[c * NHEAD + h],
                       g_he[t * NHEAD + h]);
    attOut[idx] = ex / g_z[c * NHEAD + h];
}

// ---------------- launch ---------------------------------------------------------
extern "C" void kernel_launch(void* const* d_in, const int* in_sizes, int n_in,
                              void* d_out, int out_size) {
    const float* x        = (const float*)d_in[0];
    const float* W        = (const float*)d_in[1];
    const float* W_e      = (const float*)d_in[2];
    const float* edge_emb = (const float*)d_in[3];
    const float* a_l      = (const float*)d_in[4];
    const float* a_r      = (const float*)d_in[5];
    const float* a_e      = (const float*)d_in[6];
    const int*   row      = (const int*)d_in[7];
    const int*   col      = (const int*)d_in[8];
    const int*   tp       = (const int*)d_in[9];

    float* out = (float*)d_out;
    float* attOut = (out_size >= OUT_ELEMS + ATT_ELEMS) ? out + OUT_ELEMS : nullptr;

    static cudaStream_t s1 = nullptr;
    static cudaEvent_t evFork = nullptr, evCsr = nullptr;
    static int inited = 0;
    if (!inited) {
        cudaFuncSetAttribute(k_gemm_mma, cudaFuncAttributeMaxDynamicSharedMemorySize,
                             SM_HALVES * 2);
        cudaStreamCreateWithFlags(&s1, cudaStreamNonBlocking);
        cudaEventCreateWithFlags(&evFork, cudaEventDisableTiming);
        cudaEventCreateWithFlags(&evCsr, cudaEventDisableTiming);
        inited = 1;
    }

    // fork: CSR build on s1, overlapping wprep+GEMM on the main stream
    cudaEventRecord(evFork, 0);
    cudaStreamWaitEvent(s1, evFork, 0);

    k_zero_deg<<<(N_NODES + 255) / 256, 256, 0, s1>>>();
    k_hist<<<(N_EDGES + 255) / 256, 256, 0, s1>>>(col);
    k_scan1<<<SCAN_NB, 1024, 0, s1>>>();
    k_scan23<<<SCAN_NB, 1024, 0, s1>>>();
    k_scatter<<<(N_EDGES + 255) / 256, 256, 0, s1>>>(col, row, tp);
    cudaEventRecord(evCsr, s1);

    k_wprep<<<(HD * IN_F + 255) / 256, 256>>>(W, edge_emb, W_e, a_e);
    k_gemm_mma<<<(N_NODES + 127) / 128, 512, SM_HALVES * 2>>>(x, a_l, a_r);

    // join: aggregate needs CSR + GEMM
    cudaStreamWaitEvent(0, evCsr, 0);
    k_aggregate<<<(N_NODES + 7) / 8, 256>>>(out);
    if (attOut)
        k_attout<<<(N_EDGES * NHEAD + 255) / 256, 256>>>(row, col, tp, attOut);
}

// round 14
// speedup vs baseline: 2.0795x; 1.0474x over previous
#include <cuda_runtime.h>
#include <cuda_bf16.h>
#include <cuda_fp16.h>
#include <math.h>
#include <stdint.h>

#define N_NODES 50000
#define N_EDGES 800000
#define IN_F 256
#define OUT_F 32
#define NHEAD 8
#define EDGE_F 32
#define N_ETYPES 8
#define NEG_SLOPE 0.1f

#define HD (NHEAD * OUT_F)            // 256
#define OUT_ELEMS (N_NODES * HD)
#define ATT_ELEMS (N_EDGES * NHEAD)
#define SCAN_NB ((N_NODES + 1023) / 1024)
#define PACK_MASK 0xFFFFF

// ---------------- scratch ----------------
__device__ __half    g_h16[N_NODES * HD];
__device__ float     g_hl[N_NODES * NHEAD];
__device__ float     g_hr[N_NODES * NHEAD];
__device__ float     g_z[N_NODES * NHEAD];
__device__ float     g_he[N_ETYPES * NHEAD];
__device__ int       g_deg[N_NODES];
__device__ int       g_off[N_NODES];
__device__ int       g_wptr[N_NODES];
__device__ int       g_bsum[SCAN_NB];
__device__ int       g_spack[N_EDGES];
__device__ __nv_bfloat16 g_wh[HD * IN_F];
__device__ __nv_bfloat16 g_wl[HD * IN_F];

// ---------------- K_wprep (+ he) ----------------
__global__ void k_wprep(const float* __restrict__ W,
                        const float* __restrict__ edge_emb,
                        const float* __restrict__ W_e,
                        const float* __restrict__ a_e) {
    int idx = blockIdx.x * blockDim.x + threadIdx.x;
    if (blockIdx.x == 0 && threadIdx.x < N_ETYPES * NHEAD) {
        int t = threadIdx.x >> 3, h = threadIdx.x & 7;
        float acc = 0.0f;
        for (int f = 0; f < EDGE_F; f++) {
            float ev = 0.0f;
            for (int k = 0; k < EDGE_F; k++)
                ev += edge_emb[t * EDGE_F + k] * W_e[k * (EDGE_F * NHEAD) + h * EDGE_F + f];
            acc += a_e[h * EDGE_F + f] * ev;
        }
        g_he[t * NHEAD + h] = acc;
    }
    if (idx >= HD * IN_F) return;
    int n = idx >> 8, k = idx & 255;
    float w = W[k * HD + n];
    __nv_bfloat16 h = __float2bfloat16(w);
    float r = w - __bfloat162float(h);
    g_wh[n * IN_F + k] = h;
    g_wl[n * IN_F + k] = __float2bfloat16(r);
}

// ---------------- K2: pipelined bf16 split-precision mma.sync GEMM --------------
#define XPAD 40
#define WPAD 40
#define OFF_XH 0
#define OFF_XL (OFF_XH + 128 * XPAD)      // 5120
#define OFF_WB (OFF_XL + 128 * XPAD)      // 10240: W double buffers
#define WBUF_HALVES (2 * 256 * WPAD)      // 20480 per buffer (WH + WL)
#define SM_HALVES (OFF_WB + 2 * WBUF_HALVES)  // 51200 halves = 102400 B

__device__ __forceinline__ void mma_bf16(float* d, uint32_t a0, uint32_t a1,
                                         uint32_t a2, uint32_t a3,
                                         uint32_t b0, uint32_t b1) {
    asm volatile(
        "mma.sync.aligned.m16n8k16.row.col.f32.bf16.bf16.f32 "
        "{%0,%1,%2,%3}, {%4,%5,%6,%7}, {%8,%9}, {%0,%1,%2,%3};"
        : "+f"(d[0]), "+f"(d[1]), "+f"(d[2]), "+f"(d[3])
        : "r"(a0), "r"(a1), "r"(a2), "r"(a3), "r"(b0), "r"(b1));
}
__device__ __forceinline__ float nanfix(float v) { return isnan(v) ? 0.0f : v; }
__device__ __forceinline__ uint32_t smem_u32(const void* p) {
    uint32_t a;
    asm("{ .reg .u64 t; cvta.to.shared.u64 t, %1; cvt.u32.u64 %0, t; }" : "=r"(a) : "l"(p));
    return a;
}
#define CP_ASYNC16(dst_u32, src_ptr) \
    asm volatile("cp.async.ca.shared.global [%0], [%1], 16;" :: "r"(dst_u32), "l"(src_ptr))
#define CP_COMMIT() asm volatile("cp.async.commit_group;")
#define CP_WAIT0()  asm volatile("cp.async.wait_group 0;")

__global__ __launch_bounds__(512) void k_gemm_mma(const float* __restrict__ x,
                                                  const float* __restrict__ a_l,
                                                  const float* __restrict__ a_r) {
    extern __shared__ __align__(16) uint16_t sm[];
    uint16_t* sXh = sm + OFF_XH;
    uint16_t* sXl = sm + OFF_XL;
    uint32_t sb = smem_u32(sm);

    int tid = threadIdx.x;
    int lane = tid & 31;
    int wid = tid >> 5;          // 0..15
    int warp_m = wid & 7;
    int warp_n = wid >> 3;
    int m0 = blockIdx.x * 128;

    float acc[16][4];
#pragma unroll
    for (int t = 0; t < 16; t++)
#pragma unroll
        for (int j = 0; j < 4; j++) acc[t][j] = 0.0f;

    // per-thread staging roles
    int wn = tid >> 1;                 // W: n index (0..255)
    int wj0 = (tid & 1) * 2;           // W: which 2 of 4 16B chunks
    int xr = tid >> 2, xq = tid & 3;   // x: row (0..127), quarter
    int gm = m0 + xr;
    const float4* xsrc = (gm < N_NODES)
        ? reinterpret_cast<const float4*>(x + gm * IN_F + xq * 8) : nullptr;

    float v[8];
    // ---- prologue: stage 0 ----
    {
        uint32_t dWh = sb + (OFF_WB + wn * WPAD) * 2;
        uint32_t dWl = dWh + 10240 * 2;
        const __nv_bfloat16* srch = g_wh + wn * IN_F;
        const __nv_bfloat16* srcl = g_wl + wn * IN_F;
#pragma unroll
        for (int j = 0; j < 2; j++) {
            CP_ASYNC16(dWh + (wj0 + j) * 16, srch + (wj0 + j) * 8);
            CP_ASYNC16(dWl + (wj0 + j) * 16, srcl + (wj0 + j) * 8);
        }
        CP_COMMIT();
        if (xsrc) {
            float4 f0 = xsrc[0], f1 = xsrc[1];
            v[0] = f0.x; v[1] = f0.y; v[2] = f0.z; v[3] = f0.w;
            v[4] = f1.x; v[5] = f1.y; v[6] = f1.z; v[7] = f1.w;
        } else {
#pragma unroll
            for (int j = 0; j < 8; j++) v[j] = 0.0f;
        }
        uint32_t hi[4], lo[4];
#pragma unroll
        for (int j = 0; j < 4; j++) {
            __nv_bfloat16 h0 = __float2bfloat16(v[2 * j]);
            __nv_bfloat16 h1 = __float2bfloat16(v[2 * j + 1]);
            hi[j] = (uint32_t)__bfloat16_as_ushort(h0) |
                    ((uint32_t)__bfloat16_as_ushort(h1) << 16);
            __nv_bfloat16 l0 = __float2bfloat16(v[2 * j] - __bfloat162float(h0));
            __nv_bfloat16 l1 = __float2bfloat16(v[2 * j + 1] - __bfloat162float(h1));
            lo[j] = (uint32_t)__bfloat16_as_ushort(l0) |
                    ((uint32_t)__bfloat16_as_ushort(l1) << 16);
        }
        *reinterpret_cast<uint4*>(&sXh[xr * XPAD + xq * 8]) = make_uint4(hi[0], hi[1], hi[2], hi[3]);
        *reinterpret_cast<uint4*>(&sXl[xr * XPAD + xq * 8]) = make_uint4(lo[0], lo[1], lo[2], lo[3]);
        CP_WAIT0();
        __syncthreads();
    }

    for (int ks = 0; ks < 8; ks++) {
        int buf = ks & 1;
        // prefetch next stage: W via cp.async (other buffer), x into registers
        if (ks < 7) {
            int k1 = (ks + 1) * 32;
            uint32_t dWh = sb + (OFF_WB + (1 - buf) * WBUF_HALVES + wn * WPAD) * 2;
            uint32_t dWl = dWh + 10240 * 2;
            const __nv_bfloat16* srch = g_wh + wn * IN_F + k1;
            const __nv_bfloat16* srcl = g_wl + wn * IN_F + k1;
#pragma unroll
            for (int j = 0; j < 2; j++) {
                CP_ASYNC16(dWh + (wj0 + j) * 16, srch + (wj0 + j) * 8);
                CP_ASYNC16(dWl + (wj0 + j) * 16, srcl + (wj0 + j) * 8);
            }
            CP_COMMIT();
            if (xsrc) {
                // each K-stage advances 32 floats = 8 float4s
                float4 f0 = xsrc[(ks + 1) * 8];
                float4 f1 = xsrc[(ks + 1) * 8 + 1];
                v[0] = f0.x; v[1] = f0.y; v[2] = f0.z; v[3] = f0.w;
                v[4] = f1.x; v[5] = f1.y; v[6] = f1.z; v[7] = f1.w;
            }
        }
        // compute current stage
        const uint16_t* sWh = sm + OFF_WB + buf * WBUF_HALVES;
        const uint16_t* sWl = sWh + 10240;
#pragma unroll
        for (int kin = 0; kin < 32; kin += 16) {
            int c = (lane & 3) * 2 + kin;
            int ra = (warp_m * 16 + (lane >> 2)) * XPAD;
            uint32_t ah0 = *reinterpret_cast<const uint32_t*>(&sXh[ra + c]);
            uint32_t ah1 = *reinterpret_cast<const uint32_t*>(&sXh[ra + 8 * XPAD + c]);
            uint32_t ah2 = *reinterpret_cast<const uint32_t*>(&sXh[ra + c + 8]);
            uint32_t ah3 = *reinterpret_cast<const uint32_t*>(&sXh[ra + 8 * XPAD + c + 8]);
            uint32_t al0 = *reinterpret_cast<const uint32_t*>(&sXl[ra + c]);
            uint32_t al1 = *reinterpret_cast<const uint32_t*>(&sXl[ra + 8 * XPAD + c]);
            uint32_t al2 = *reinterpret_cast<const uint32_t*>(&sXl[ra + c + 8]);
            uint32_t al3 = *reinterpret_cast<const uint32_t*>(&sXl[ra + 8 * XPAD + c + 8]);
#pragma unroll
            for (int t = 0; t < 16; t++) {
                int nb = (warp_n * 128 + t * 8 + (lane >> 2)) * WPAD + (lane & 3) * 2 + kin;
                uint32_t bh0 = *reinterpret_cast<const uint32_t*>(&sWh[nb]);
                uint32_t bh1 = *reinterpret_cast<const uint32_t*>(&sWh[nb + 8]);
                uint32_t bl0 = *reinterpret_cast<const uint32_t*>(&sWl[nb]);
                uint32_t bl1 = *reinterpret_cast<const uint32_t*>(&sWl[nb + 8]);
                mma_bf16(acc[t], ah0, ah1, ah2, ah3, bh0, bh1);
                mma_bf16(acc[t], ah0, ah1, ah2, ah3, bl0, bl1);
                mma_bf16(acc[t], al0, al1, al2, al3, bh0, bh1);
            }
        }
        if (ks < 7) {
            __syncthreads();       // everyone done reading sX for stage ks
            uint32_t hi[4], lo[4];
#pragma unroll
            for (int j = 0; j < 4; j++) {
                __nv_bfloat16 h0 = __float2bfloat16(v[2 * j]);
                __nv_bfloat16 h1 = __float2bfloat16(v[2 * j + 1]);
                hi[j] = (uint32_t)__bfloat16_as_ushort(h0) |
                        ((uint32_t)__bfloat16_as_ushort(h1) << 16);
                __nv_bfloat16 l0 = __float2bfloat16(v[2 * j] - __bfloat162float(h0));
                __nv_bfloat16 l1 = __float2bfloat16(v[2 * j + 1] - __bfloat162float(h1));
                lo[j] = (uint32_t)__bfloat16_as_ushort(l0) |
                        ((uint32_t)__bfloat16_as_ushort(l1) << 16);
            }
            *reinterpret_cast<uint4*>(&sXh[xr * XPAD + xq * 8]) = make_uint4(hi[0], hi[1], hi[2], hi[3]);
            *reinterpret_cast<uint4*>(&sXl[xr * XPAD + xq * 8]) = make_uint4(lo[0], lo[1], lo[2], lo[3]);
            CP_WAIT0();
            __syncthreads();
        }
    }

    int r = lane >> 2;
    int gr0 = m0 + warp_m * 16 + r;
    int gr1 = gr0 + 8;
    bool ok0 = (gr0 < N_NODES), ok1 = (gr1 < N_NODES);
    float dl0[4] = {0, 0, 0, 0}, dl1[4] = {0, 0, 0, 0};
    float dr0[4] = {0, 0, 0, 0}, dr1[4] = {0, 0, 0, 0};
#pragma unroll
    for (int t = 0; t < 16; t++) {
        int n = warp_n * 128 + t * 8 + (lane & 3) * 2;
        float v0 = nanfix(acc[t][0]), v1 = nanfix(acc[t][1]);
        float v2 = nanfix(acc[t][2]), v3 = nanfix(acc[t][3]);
        float alv0 = __ldg(&a_l[n]), alv1 = __ldg(&a_l[n + 1]);
        float arv0 = __ldg(&a_r[n]), arv1 = __ldg(&a_r[n + 1]);
        int hh = t >> 2;
        dl0[hh] += v0 * alv0 + v1 * alv1;
        dr0[hh] += v0 * arv0 + v1 * arv1;
        dl1[hh] += v2 * alv0 + v3 * alv1;
        dr1[hh] += v2 * arv0 + v3 * arv1;
        if (ok0) *reinterpret_cast<__half2*>(&g_h16[gr0 * HD + n]) = __floats2half2_rn(v0, v1);
        if (ok1) *reinterpret_cast<__half2*>(&g_h16[gr1 * HD + n]) = __floats2half2_rn(v2, v3);
    }
#pragma unroll
    for (int hh = 0; hh < 4; hh++) {
#pragma unroll
        for (int o = 1; o <= 2; o <<= 1) {
            dl0[hh] += __shfl_xor_sync(0xffffffffu, dl0[hh], o);
            dl1[hh] += __shfl_xor_sync(0xffffffffu, dl1[hh], o);
            dr0[hh] += __shfl_xor_sync(0xffffffffu, dr0[hh], o);
            dr1[hh] += __shfl_xor_sync(0xffffffffu, dr1[hh], o);
        }
    }
    if ((lane & 3) == 0) {
#pragma unroll
        for (int hh = 0; hh < 4; hh++) {
            int head = warp_n * 4 + hh;
            if (ok0) { g_hl[gr0 * NHEAD + head] = dl0[hh]; g_hr[gr0 * NHEAD + head] = dr0[hh]; }
            if (ok1) { g_hl[gr1 * NHEAD + head] = dl1[hh]; g_hr[gr1 * NHEAD + head] = dr1[hh]; }
        }
    }
}

// ---------------- CSR build ----------------
__global__ void k_zero_deg() {
    int i = blockIdx.x * blockDim.x + threadIdx.x;
    if (i < N_NODES) g_deg[i] = 0;
}
__global__ void k_hist(const int* __restrict__ col) {
    int e = blockIdx.x * blockDim.x + threadIdx.x;
    if (e < N_EDGES) atomicAdd(&g_deg[__ldg(&col[e])], 1);
}
__global__ __launch_bounds__(1024) void k_scan1() {
    __shared__ int sh[1024];
    int t = threadIdx.x;
    int idx = blockIdx.x * 1024 + t;
    int v = (idx < N_NODES) ? g_deg[idx] : 0;
    sh[t] = v;
    __syncthreads();
#pragma unroll
    for (int off = 1; off < 1024; off <<= 1) {
        int add = (t >= off) ? sh[t - off] : 0;
        __syncthreads();
        sh[t] += add;
        __syncthreads();
    }
    if (idx < N_NODES) g_off[idx] = sh[t] - v;
    if (t == 1023) g_bsum[blockIdx.x] = sh[t];
}
__global__ __launch_bounds__(1024) void k_scan23() {
    __shared__ int s_base;
    int t = threadIdx.x;
    int bid = blockIdx.x;
    if (t < 32) {
        int v = 0;
        for (int j = t; j < SCAN_NB; j += 32)
            if (j < bid) v += g_bsum[j];
#pragma unroll
        for (int o = 16; o; o >>= 1) v += __shfl_xor_sync(0xffffffffu, v, o);
        if (t == 0) s_base = v;
    }
    __syncthreads();
    int idx = bid * 1024 + t;
    if (idx < N_NODES) {
        int o = g_off[idx] + s_base;
        g_off[idx] = o;
        g_wptr[idx] = o;
    }
}
__global__ void k_scatter(const int* __restrict__ col, const int* __restrict__ row,
                          const int* __restrict__ tp) {
    int e = blockIdx.x * blockDim.x + threadIdx.x;
    if (e >= N_EDGES) return;
    int c = __ldg(&col[e]);
    int pos = atomicAdd(&g_wptr[c], 1);
    g_spack[pos] = __ldg(&row[e]) | (__ldg(&tp[e]) << 20);
}

// ---------------- K5: fused edge-softmax + gather, WARP per node ----------------
__device__ __forceinline__ float edge_ex(float hlv, float hrv, float hev) {
    float s = hlv + hrv + hev;
    s = (s > 0.0f) ? s : NEG_SLOPE * s;
    return __expf(s);
}

__global__ __launch_bounds__(256) void k_aggregate(float* __restrict__ out) {
    int tid = threadIdx.x;
    int lane = tid & 31;
    int n = blockIdx.x * 8 + (tid >> 5);
    if (n >= N_NODES) return;
    int head = lane >> 2;

    int base = g_off[n];
    int deg = g_deg[n];
    const uint4* h4 = reinterpret_cast<const uint4*>(g_h16);
    float hrv = g_hr[n * NHEAD + head];

    float acc[8];
#pragma unroll
    for (int j = 0; j < 8; j++) acc[j] = 0.0f;
    float zacc = 0.f;

    int k = 0;
    for (; k + 4 <= deg; k += 4) {
        int v[4];
#pragma unroll
        for (int j = 0; j < 4; j++) v[j] = __ldg(&g_spack[base + k + j]);
        int r[4];
#pragma unroll
        for (int j = 0; j < 4; j++) r[j] = v[j] & PACK_MASK;
        uint4 u[4];
#pragma unroll
        for (int j = 0; j < 4; j++) u[j] = h4[r[j] * 32 + lane];
        float hl[4];
#pragma unroll
        for (int j = 0; j < 4; j++) hl[j] = __ldg(&g_hl[r[j] * NHEAD + head]);
        float ex[4];
#pragma unroll
        for (int j = 0; j < 4; j++)
            ex[j] = edge_ex(hl[j], hrv, g_he[(v[j] >> 20) * NHEAD + head]);
#pragma unroll
        for (int j = 0; j < 4; j++) {
            float2 p0 = __half22float2(*reinterpret_cast<__half2*>(&u[j].x));
            float2 p1 = __half22float2(*reinterpret_cast<__half2*>(&u[j].y));
            float2 p2 = __half22float2(*reinterpret_cast<__half2*>(&u[j].z));
            float2 p3 = __half22float2(*reinterpret_cast<__half2*>(&u[j].w));
            acc[0] += ex[j] * p0.x; acc[1] += ex[j] * p0.y;
            acc[2] += ex[j] * p1.x; acc[3] += ex[j] * p1.y;
            acc[4] += ex[j] * p2.x; acc[5] += ex[j] * p2.y;
            acc[6] += ex[j] * p3.x; acc[7] += ex[j] * p3.y;
            zacc += ex[j];
        }
    }
    for (; k < deg; k++) {
        int v0 = __ldg(&g_spack[base + k]);
        int r0 = v0 & PACK_MASK;
        float ex0 = edge_ex(__ldg(&g_hl[r0 * NHEAD + head]), hrv,
                            g_he[(v0 >> 20) * NHEAD + head]);
        uint4 u0 = h4[r0 * 32 + lane];
        float2 p0 = __half22float2(*reinterpret_cast<__half2*>(&u0.x));
        float2 p1 = __half22float2(*reinterpret_cast<__half2*>(&u0.y));
        float2 p2 = __half22float2(*reinterpret_cast<__half2*>(&u0.z));
        float2 p3 = __half22float2(*reinterpret_cast<__half2*>(&u0.w));
        acc[0] += ex0 * p0.x; acc[1] += ex0 * p0.y;
        acc[2] += ex0 * p1.x; acc[3] += ex0 * p1.y;
        acc[4] += ex0 * p2.x; acc[5] += ex0 * p2.y;
        acc[6] += ex0 * p3.x; acc[7] += ex0 * p3.y;
        zacc += ex0;
    }
    float inv = (deg > 0) ? (1.0f / zacc) : 0.0f;
    float4* o4 = reinterpret_cast<float4*>(out) + n * 64 + lane * 2;
    o4[0] = make_float4(acc[0] * inv, acc[1] * inv, acc[2] * inv, acc[3] * inv);
    o4[1] = make_float4(acc[4] * inv, acc[5] * inv, acc[6] * inv, acc[7] * inv);
    if ((lane & 3) == 0) g_z[n * NHEAD + head] = zacc;
}

// ---------------- K6: att output — one thread per EDGE (8 heads) ----------------
__global__ void k_attout(const int* __restrict__ row,
                         const int* __restrict__ col,
                         const int* __restrict__ tp,
                         float* __restrict__ attOut) {
    int e = blockIdx.x * blockDim.x + threadIdx.x;
    if (e >= N_EDGES) return;
    int r = __ldg(&row[e]);
    int c = __ldg(&col[e]);
    int t = __ldg(&tp[e]);
    float4 hl0 = *reinterpret_cast<const float4*>(&g_hl[r * NHEAD]);
    float4 hl1 = *reinterpret_cast<const float4*>(&g_hl[r * NHEAD + 4]);
    float4 hr0 = *reinterpret_cast<const float4*>(&g_hr[c * NHEAD]);
    float4 hr1 = *reinterpret_cast<const float4*>(&g_hr[c * NHEAD + 4]);
    float4 z0  = *reinterpret_cast<const float4*>(&g_z[c * NHEAD]);
    float4 z1  = *reinterpret_cast<const float4*>(&g_z[c * NHEAD + 4]);
    const float* he = &g_he[t * NHEAD];
    float4 o0, o1;
    o0.x = edge_ex(hl0.x, hr0.x, he[0]) / z0.x;
    o0.y = edge_ex(hl0.y, hr0.y, he[1]) / z0.y;
    o0.z = edge_ex(hl0.z, hr0.z, he[2]) / z0.z;
    o0.w = edge_ex(hl0.w, hr0.w, he[3]) / z0.w;
    o1.x = edge_ex(hl1.x, hr1.x, he[4]) / z1.x;
    o1.y = edge_ex(hl1.y, hr1.y, he[5]) / z1.y;
    o1.z = edge_ex(hl1.z, hr1.z, he[6]) / z1.z;
    o1.w = edge_ex(hl1.w, hr1.w, he[7]) / z1.w;
    float4* dst = reinterpret_cast<float4*>(attOut + e * NHEAD);
    dst[0] = o0;
    dst[1] = o1;
}

// ---------------- launch ---------------------------------------------------------
extern "C" void kernel_launch(void* const* d_in, const int* in_sizes, int n_in,
                              void* d_out, int out_size) {
    const float* x        = (const float*)d_in[0];
    const float* W        = (const float*)d_in[1];
    const float* W_e      = (const float*)d_in[2];
    const float* edge_emb = (const float*)d_in[3];
    const float* a_l      = (const float*)d_in[4];
    const float* a_r      = (const float*)d_in[5];
    const float* a_e      = (const float*)d_in[6];
    const int*   row      = (const int*)d_in[7];
    const int*   col      = (const int*)d_in[8];
    const int*   tp       = (const int*)d_in[9];

    float* out = (float*)d_out;
    float* attOut = (out_size >= OUT_ELEMS + ATT_ELEMS) ? out + OUT_ELEMS : nullptr;

    static cudaStream_t s1 = nullptr;
    static cudaEvent_t evFork = nullptr, evCsr = nullptr;
    static int inited = 0;
    if (!inited) {
        cudaFuncSetAttribute(k_gemm_mma, cudaFuncAttributeMaxDynamicSharedMemorySize,
                             SM_HALVES * 2);
        cudaStreamCreateWithFlags(&s1, cudaStreamNonBlocking);
        cudaEventCreateWithFlags(&evFork, cudaEventDisableTiming);
        cudaEventCreateWithFlags(&evCsr, cudaEventDisableTiming);
        inited = 1;
    }

    cudaEventRecord(evFork, 0);
    cudaStreamWaitEvent(s1, evFork, 0);

    k_zero_deg<<<(N_NODES + 255) / 256, 256, 0, s1>>>();
    k_hist<<<(N_EDGES + 255) / 256, 256, 0, s1>>>(col);
    k_scan1<<<SCAN_NB, 1024, 0, s1>>>();
    k_scan23<<<SCAN_NB, 1024, 0, s1>>>();
    k_scatter<<<(N_EDGES + 255) / 256, 256, 0, s1>>>(col, row, tp);
    cudaEventRecord(evCsr, s1);

    k_wprep<<<(HD * IN_F + 255) / 256, 256>>>(W, edge_emb, W_e, a_e);
    k_gemm_mma<<<(N_NODES + 127) / 128, 512, SM_HALVES * 2>>>(x, a_l, a_r);

    cudaStreamWaitEvent(0, evCsr, 0);
    k_aggregate<<<(N_NODES + 7) / 8, 256>>>(out);
    if (attOut)
        k_attout<<<(N_EDGES + 255) / 256, 256>>>(row, col, tp, attOut);
}

// round 15
// speedup vs baseline: 2.2991x; 1.1056x over previous
#include <cuda_runtime.h>
#include <cuda_fp16.h>
#include <math.h>
#include <stdint.h>

#define N_NODES 50000
#define N_EDGES 800000
#define IN_F 256
#define OUT_F 32
#define NHEAD 8
#define EDGE_F 32
#define N_ETYPES 8
#define NEG_SLOPE 0.1f

#define HD (NHEAD * OUT_F)            // 256
#define OUT_ELEMS (N_NODES * HD)
#define ATT_ELEMS (N_EDGES * NHEAD)
#define SCAN_NB ((N_NODES + 1023) / 1024)
#define PACK_MASK 0xFFFFF

// ---------------- scratch ----------------
__device__ __half    g_h16[N_NODES * HD];
__device__ float     g_hl[N_NODES * NHEAD];
__device__ float     g_hr[N_NODES * NHEAD];
__device__ float     g_z[N_NODES * NHEAD];     // stores 1/z after aggregate
__device__ float     g_he[N_ETYPES * NHEAD];
__device__ int       g_deg[N_NODES];
__device__ int       g_off[N_NODES];
__device__ int       g_wptr[N_NODES];
__device__ int       g_bsum[SCAN_NB];
__device__ int       g_spack[N_EDGES];
__device__ __half    g_wh[HD * IN_F];          // [n][k] = fp16_hi(W[k][n])
__device__ __half    g_wl[HD * IN_F];          // [n][k] = fp16_lo residual

// ---------------- K_wprep (+ he) ----------------
__global__ void k_wprep(const float* __restrict__ W,
                        const float* __restrict__ edge_emb,
                        const float* __restrict__ W_e,
                        const float* __restrict__ a_e) {
    int idx = blockIdx.x * blockDim.x + threadIdx.x;
    if (blockIdx.x == 0 && threadIdx.x < N_ETYPES * NHEAD) {
        int t = threadIdx.x >> 3, h = threadIdx.x & 7;
        float acc = 0.0f;
        for (int f = 0; f < EDGE_F; f++) {
            float ev = 0.0f;
            for (int k = 0; k < EDGE_F; k++)
                ev += edge_emb[t * EDGE_F + k] * W_e[k * (EDGE_F * NHEAD) + h * EDGE_F + f];
            acc += a_e[h * EDGE_F + f] * ev;
        }
        g_he[t * NHEAD + h] = acc;
    }
    if (idx >= HD * IN_F) return;
    int n = idx >> 8, k = idx & 255;
    float w = W[k * HD + n];
    __half h = __float2half_rn(w);
    float r = w - __half2float(h);
    g_wh[n * IN_F + k] = h;
    g_wl[n * IN_F + k] = __float2half_rn(r);
}

// ---------------- K2: pipelined fp16 2-pass split mma.sync GEMM ------------------
#define XPAD 40
#define WPAD 40
#define OFF_XH 0
#define OFF_WB (OFF_XH + 128 * XPAD)      // 5120: W double buffers start
#define WBUF_HALVES (2 * 256 * WPAD)      // 20480 per buffer (WH + WL)
#define SM_HALVES (OFF_WB + 2 * WBUF_HALVES)  // 46080 halves = 92160 B

__device__ __forceinline__ void mma_fp16(float* d, uint32_t a0, uint32_t a1,
                                         uint32_t a2, uint32_t a3,
                                         uint32_t b0, uint32_t b1) {
    asm volatile(
        "mma.sync.aligned.m16n8k16.row.col.f32.f16.f16.f32 "
        "{%0,%1,%2,%3}, {%4,%5,%6,%7}, {%8,%9}, {%0,%1,%2,%3};"
        : "+f"(d[0]), "+f"(d[1]), "+f"(d[2]), "+f"(d[3])
        : "r"(a0), "r"(a1), "r"(a2), "r"(a3), "r"(b0), "r"(b1));
}
__device__ __forceinline__ float nanfix(float v) { return isnan(v) ? 0.0f : v; }
__device__ __forceinline__ uint32_t smem_u32(const void* p) {
    uint32_t a;
    asm("{ .reg .u64 t; cvta.to.shared.u64 t, %1; cvt.u32.u64 %0, t; }" : "=r"(a) : "l"(p));
    return a;
}
#define CP_ASYNC16(dst_u32, src_ptr) \
    asm volatile("cp.async.ca.shared.global [%0], [%1], 16;" :: "r"(dst_u32), "l"(src_ptr))
#define CP_COMMIT() asm volatile("cp.async.commit_group;")
#define CP_WAIT0()  asm volatile("cp.async.wait_group 0;")

__global__ __launch_bounds__(512) void k_gemm_mma(const float* __restrict__ x,
                                                  const float* __restrict__ a_l,
                                                  const float* __restrict__ a_r) {
    extern __shared__ __align__(16) uint16_t sm[];
    uint16_t* sXh = sm + OFF_XH;
    uint32_t sb = smem_u32(sm);

    int tid = threadIdx.x;
    int lane = tid & 31;
    int wid = tid >> 5;          // 0..15
    int warp_m = wid & 7;
    int warp_n = wid >> 3;
    int m0 = blockIdx.x * 128;

    float acc[16][4];
#pragma unroll
    for (int t = 0; t < 16; t++)
#pragma unroll
        for (int j = 0; j < 4; j++) acc[t][j] = 0.0f;

    // per-thread staging roles
    int wn = tid >> 1;                 // W: n index (0..255)
    int wj0 = (tid & 1) * 2;           // W: which 2 of 4 16B chunks
    int xr = tid >> 2, xq = tid & 3;   // x: row (0..127), quarter
    int gm = m0 + xr;
    const float4* xsrc = (gm < N_NODES)
        ? reinterpret_cast<const float4*>(x + gm * IN_F + xq * 8) : nullptr;

    float v[8];
    // ---- prologue: stage 0 ----
    {
        uint32_t dWh = sb + (OFF_WB + wn * WPAD) * 2;
        uint32_t dWl = dWh + 10240 * 2;
        const __half* srch = g_wh + wn * IN_F;
        const __half* srcl = g_wl + wn * IN_F;
#pragma unroll
        for (int j = 0; j < 2; j++) {
            CP_ASYNC16(dWh + (wj0 + j) * 16, srch + (wj0 + j) * 8);
            CP_ASYNC16(dWl + (wj0 + j) * 16, srcl + (wj0 + j) * 8);
        }
        CP_COMMIT();
        if (xsrc) {
            float4 f0 = xsrc[0], f1 = xsrc[1];
            v[0] = f0.x; v[1] = f0.y; v[2] = f0.z; v[3] = f0.w;
            v[4] = f1.x; v[5] = f1.y; v[6] = f1.z; v[7] = f1.w;
        } else {
#pragma unroll
            for (int j = 0; j < 8; j++) v[j] = 0.0f;
        }
        uint32_t hi[4];
#pragma unroll
        for (int j = 0; j < 4; j++) {
            __half2 p = __floats2half2_rn(v[2 * j], v[2 * j + 1]);
            hi[j] = *reinterpret_cast<uint32_t*>(&p);
        }
        *reinterpret_cast<uint4*>(&sXh[xr * XPAD + xq * 8]) = make_uint4(hi[0], hi[1], hi[2], hi[3]);
        CP_WAIT0();
        __syncthreads();
    }

    for (int ks = 0; ks < 8; ks++) {
        int buf = ks & 1;
        // prefetch next stage: W via cp.async (other buffer), x into registers
        if (ks < 7) {
            int k1 = (ks + 1) * 32;
            uint32_t dWh = sb + (OFF_WB + (1 - buf) * WBUF_HALVES + wn * WPAD) * 2;
            uint32_t dWl = dWh + 10240 * 2;
            const __half* srch = g_wh + wn * IN_F + k1;
            const __half* srcl = g_wl + wn * IN_F + k1;
#pragma unroll
            for (int j = 0; j < 2; j++) {
                CP_ASYNC16(dWh + (wj0 + j) * 16, srch + (wj0 + j) * 8);
                CP_ASYNC16(dWl + (wj0 + j) * 16, srcl + (wj0 + j) * 8);
            }
            CP_COMMIT();
            if (xsrc) {
                float4 f0 = xsrc[(ks + 1) * 8];
                float4 f1 = xsrc[(ks + 1) * 8 + 1];
                v[0] = f0.x; v[1] = f0.y; v[2] = f0.z; v[3] = f0.w;
                v[4] = f1.x; v[5] = f1.y; v[6] = f1.z; v[7] = f1.w;
            }
        }
        // compute current stage: two passes (W-hi, W-lo) with fp16 x
        const uint16_t* sWh = sm + OFF_WB + buf * WBUF_HALVES;
        const uint16_t* sWl = sWh + 10240;
#pragma unroll
        for (int kin = 0; kin < 32; kin += 16) {
            int c = (lane & 3) * 2 + kin;
            int ra = (warp_m * 16 + (lane >> 2)) * XPAD;
            uint32_t ah0 = *reinterpret_cast<const uint32_t*>(&sXh[ra + c]);
            uint32_t ah1 = *reinterpret_cast<const uint32_t*>(&sXh[ra + 8 * XPAD + c]);
            uint32_t ah2 = *reinterpret_cast<const uint32_t*>(&sXh[ra + c + 8]);
            uint32_t ah3 = *reinterpret_cast<const uint32_t*>(&sXh[ra + 8 * XPAD + c + 8]);
#pragma unroll
            for (int t = 0; t < 16; t++) {
                int nb = (warp_n * 128 + t * 8 + (lane >> 2)) * WPAD + (lane & 3) * 2 + kin;
                uint32_t bh0 = *reinterpret_cast<const uint32_t*>(&sWh[nb]);
                uint32_t bh1 = *reinterpret_cast<const uint32_t*>(&sWh[nb + 8]);
                uint32_t bl0 = *reinterpret_cast<const uint32_t*>(&sWl[nb]);
                uint32_t bl1 = *reinterpret_cast<const uint32_t*>(&sWl[nb + 8]);
                mma_fp16(acc[t], ah0, ah1, ah2, ah3, bh0, bh1);
                mma_fp16(acc[t], ah0, ah1, ah2, ah3, bl0, bl1);
            }
        }
        if (ks < 7) {
            __syncthreads();       // everyone done reading sX for stage ks
            uint32_t hi[4];
#pragma unroll
            for (int j = 0; j < 4; j++) {
                __half2 p = __floats2half2_rn(v[2 * j], v[2 * j + 1]);
                hi[j] = *reinterpret_cast<uint32_t*>(&p);
            }
            *reinterpret_cast<uint4*>(&sXh[xr * XPAD + xq * 8]) = make_uint4(hi[0], hi[1], hi[2], hi[3]);
            CP_WAIT0();
            __syncthreads();
        }
    }

    int r = lane >> 2;
    int gr0 = m0 + warp_m * 16 + r;
    int gr1 = gr0 + 8;
    bool ok0 = (gr0 < N_NODES), ok1 = (gr1 < N_NODES);
    float dl0[4] = {0, 0, 0, 0}, dl1[4] = {0, 0, 0, 0};
    float dr0[4] = {0, 0, 0, 0}, dr1[4] = {0, 0, 0, 0};
#pragma unroll
    for (int t = 0; t < 16; t++) {
        int n = warp_n * 128 + t * 8 + (lane & 3) * 2;
        float v0 = nanfix(acc[t][0]), v1 = nanfix(acc[t][1]);
        float v2 = nanfix(acc[t][2]), v3 = nanfix(acc[t][3]);
        float alv0 = __ldg(&a_l[n]), alv1 = __ldg(&a_l[n + 1]);
        float arv0 = __ldg(&a_r[n]), arv1 = __ldg(&a_r[n + 1]);
        int hh = t >> 2;
        dl0[hh] += v0 * alv0 + v1 * alv1;
        dr0[hh] += v0 * arv0 + v1 * arv1;
        dl1[hh] += v2 * alv0 + v3 * alv1;
        dr1[hh] += v2 * arv0 + v3 * arv1;
        if (ok0) *reinterpret_cast<__half2*>(&g_h16[gr0 * HD + n]) = __floats2half2_rn(v0, v1);
        if (ok1) *reinterpret_cast<__half2*>(&g_h16[gr1 * HD + n]) = __floats2half2_rn(v2, v3);
    }
#pragma unroll
    for (int hh = 0; hh < 4; hh++) {
#pragma unroll
        for (int o = 1; o <= 2; o <<= 1) {
            dl0[hh] += __shfl_xor_sync(0xffffffffu, dl0[hh], o);
            dl1[hh] += __shfl_xor_sync(0xffffffffu, dl1[hh], o);
            dr0[hh] += __shfl_xor_sync(0xffffffffu, dr0[hh], o);
            dr1[hh] += __shfl_xor_sync(0xffffffffu, dr1[hh], o);
        }
    }
    if ((lane & 3) == 0) {
#pragma unroll
        for (int hh = 0; hh < 4; hh++) {
            int head = warp_n * 4 + hh;
            if (ok0) { g_hl[gr0 * NHEAD + head] = dl0[hh]; g_hr[gr0 * NHEAD + head] = dr0[hh]; }
            if (ok1) { g_hl[gr1 * NHEAD + head] = dl1[hh]; g_hr[gr1 * NHEAD + head] = dr1[hh]; }
        }
    }
}

// ---------------- CSR build ----------------
__global__ void k_zero_deg() {
    int i = blockIdx.x * blockDim.x + threadIdx.x;
    if (i < N_NODES) g_deg[i] = 0;
}
__global__ void k_hist(const int* __restrict__ col) {
    int e = blockIdx.x * blockDim.x + threadIdx.x;
    if (e < N_EDGES) atomicAdd(&g_deg[__ldg(&col[e])], 1);
}
__global__ __launch_bounds__(1024) void k_scan1() {
    __shared__ int sh[1024];
    int t = threadIdx.x;
    int idx = blockIdx.x * 1024 + t;
    int v = (idx < N_NODES) ? g_deg[idx] : 0;
    sh[t] = v;
    __syncthreads();
#pragma unroll
    for (int off = 1; off < 1024; off <<= 1) {
        int add = (t >= off) ? sh[t - off] : 0;
        __syncthreads();
        sh[t] += add;
        __syncthreads();
    }
    if (idx < N_NODES) g_off[idx] = sh[t] - v;
    if (t == 1023) g_bsum[blockIdx.x] = sh[t];
}
__global__ __launch_bounds__(1024) void k_scan23() {
    __shared__ int s_base;
    int t = threadIdx.x;
    int bid = blockIdx.x;
    if (t < 32) {
        int v = 0;
        for (int j = t; j < SCAN_NB; j += 32)
            if (j < bid) v += g_bsum[j];
#pragma unroll
        for (int o = 16; o; o >>= 1) v += __shfl_xor_sync(0xffffffffu, v, o);
        if (t == 0) s_base = v;
    }
    __syncthreads();
    int idx = bid * 1024 + t;
    if (idx < N_NODES) {
        int o = g_off[idx] + s_base;
        g_off[idx] = o;
        g_wptr[idx] = o;
    }
}
__global__ void k_scatter(const int* __restrict__ col, const int* __restrict__ row,
                          const int* __restrict__ tp) {
    int e = blockIdx.x * blockDim.x + threadIdx.x;
    if (e >= N_EDGES) return;
    int c = __ldg(&col[e]);
    int pos = atomicAdd(&g_wptr[c], 1);
    g_spack[pos] = __ldg(&row[e]) | (__ldg(&tp[e]) << 20);
}

// ---------------- K5: fused edge-softmax + gather, WARP per node ----------------
__device__ __forceinline__ float edge_ex(float hlv, float hrv, float hev) {
    float s = hlv + hrv + hev;
    s = (s > 0.0f) ? s : NEG_SLOPE * s;
    return __expf(s);
}

__global__ __launch_bounds__(256) void k_aggregate(float* __restrict__ out) {
    int tid = threadIdx.x;
    int lane = tid & 31;
    int n = blockIdx.x * 8 + (tid >> 5);
    if (n >= N_NODES) return;
    int head = lane >> 2;

    int base = g_off[n];
    int deg = g_deg[n];
    const uint4* h4 = reinterpret_cast<const uint4*>(g_h16);
    float hrv = g_hr[n * NHEAD + head];

    float acc[8];
#pragma unroll
    for (int j = 0; j < 8; j++) acc[j] = 0.0f;
    float zacc = 0.f;

    int k = 0;
    for (; k + 4 <= deg; k += 4) {
        int v[4];
#pragma unroll
        for (int j = 0; j < 4; j++) v[j] = __ldg(&g_spack[base + k + j]);
        int r[4];
#pragma unroll
        for (int j = 0; j < 4; j++) r[j] = v[j] & PACK_MASK;
        uint4 u[4];
#pragma unroll
        for (int j = 0; j < 4; j++) u[j] = h4[r[j] * 32 + lane];
        float hl[4];
#pragma unroll
        for (int j = 0; j < 4; j++) hl[j] = __ldg(&g_hl[r[j] * NHEAD + head]);
        float ex[4];
#pragma unroll
        for (int j = 0; j < 4; j++)
            ex[j] = edge_ex(hl[j], hrv, g_he[(v[j] >> 20) * NHEAD + head]);
#pragma unroll
        for (int j = 0; j < 4; j++) {
            float2 p0 = __half22float2(*reinterpret_cast<__half2*>(&u[j].x));
            float2 p1 = __half22float2(*reinterpret_cast<__half2*>(&u[j].y));
            float2 p2 = __half22float2(*reinterpret_cast<__half2*>(&u[j].z));
            float2 p3 = __half22float2(*reinterpret_cast<__half2*>(&u[j].w));
            acc[0] += ex[j] * p0.x; acc[1] += ex[j] * p0.y;
            acc[2] += ex[j] * p1.x; acc[3] += ex[j] * p1.y;
            acc[4] += ex[j] * p2.x; acc[5] += ex[j] * p2.y;
            acc[6] += ex[j] * p3.x; acc[7] += ex[j] * p3.y;
            zacc += ex[j];
        }
    }
    for (; k < deg; k++) {
        int v0 = __ldg(&g_spack[base + k]);
        int r0 = v0 & PACK_MASK;
        float ex0 = edge_ex(__ldg(&g_hl[r0 * NHEAD + head]), hrv,
                            g_he[(v0 >> 20) * NHEAD + head]);
        uint4 u0 = h4[r0 * 32 + lane];
        float2 p0 = __half22float2(*reinterpret_cast<__half2*>(&u0.x));
        float2 p1 = __half22float2(*reinterpret_cast<__half2*>(&u0.y));
        float2 p2 = __half22float2(*reinterpret_cast<__half2*>(&u0.z));
        float2 p3 = __half22float2(*reinterpret_cast<__half2*>(&u0.w));
        acc[0] += ex0 * p0.x; acc[1] += ex0 * p0.y;
        acc[2] += ex0 * p1.x; acc[3] += ex0 * p1.y;
        acc[4] += ex0 * p2.x; acc[5] += ex0 * p2.y;
        acc[6] += ex0 * p3.x; acc[7] += ex0 * p3.y;
        zacc += ex0;
    }
    float inv = (deg > 0) ? (1.0f / zacc) : 0.0f;
    float4* o4 = reinterpret_cast<float4*>(out) + n * 64 + lane * 2;
    o4[0] = make_float4(acc[0] * inv, acc[1] * inv, acc[2] * inv, acc[3] * inv);
    o4[1] = make_float4(acc[4] * inv, acc[5] * inv, acc[6] * inv, acc[7] * inv);
    if ((lane & 3) == 0) g_z[n * NHEAD + head] = inv;   // store reciprocal
}

// ---------------- K6: att output — one thread per EDGE (8 heads) ----------------
__global__ void k_attout(const int* __restrict__ row,
                         const int* __restrict__ col,
                         const int* __restrict__ tp,
                         float* __restrict__ attOut) {
    int e = blockIdx.x * blockDim.x + threadIdx.x;
    if (e >= N_EDGES) return;
    int r = __ldg(&row[e]);
    int c = __ldg(&col[e]);
    int t = __ldg(&tp[e]);
    float4 hl0 = *reinterpret_cast<const float4*>(&g_hl[r * NHEAD]);
    float4 hl1 = *reinterpret_cast<const float4*>(&g_hl[r * NHEAD + 4]);
    float4 hr0 = *reinterpret_cast<const float4*>(&g_hr[c * NHEAD]);
    float4 hr1 = *reinterpret_cast<const float4*>(&g_hr[c * NHEAD + 4]);
    float4 z0  = *reinterpret_cast<const float4*>(&g_z[c * NHEAD]);
    float4 z1  = *reinterpret_cast<const float4*>(&g_z[c * NHEAD + 4]);
    const float* he = &g_he[t * NHEAD];
    float4 o0, o1;
    o0.x = edge_ex(hl0.x, hr0.x, he[0]) * z0.x;
    o0.y = edge_ex(hl0.y, hr0.y, he[1]) * z0.y;
    o0.z = edge_ex(hl0.z, hr0.z, he[2]) * z0.z;
    o0.w = edge_ex(hl0.w, hr0.w, he[3]) * z0.w;
    o1.x = edge_ex(hl1.x, hr1.x, he[4]) * z1.x;
    o1.y = edge_ex(hl1.y, hr1.y, he[5]) * z1.y;
    o1.z = edge_ex(hl1.z, hr1.z, he[6]) * z1.z;
    o1.w = edge_ex(hl1.w, hr1.w, he[7]) * z1.w;
    float4* dst = reinterpret_cast<float4*>(attOut + e * NHEAD);
    dst[0] = o0;
    dst[1] = o1;
}

// ---------------- launch ---------------------------------------------------------
extern "C" void kernel_launch(void* const* d_in, const int* in_sizes, int n_in,
                              void* d_out, int out_size) {
    const float* x        = (const float*)d_in[0];
    const float* W        = (const float*)d_in[1];
    const float* W_e      = (const float*)d_in[2];
    const float* edge_emb = (const float*)d_in[3];
    const float* a_l      = (const float*)d_in[4];
    const float* a_r      = (const float*)d_in[5];
    const float* a_e      = (const float*)d_in[6];
    const int*   row      = (const int*)d_in[7];
    const int*   col      = (const int*)d_in[8];
    const int*   tp       = (const int*)d_in[9];

    float* out = (float*)d_out;
    float* attOut = (out_size >= OUT_ELEMS + ATT_ELEMS) ? out + OUT_ELEMS : nullptr;

    static cudaStream_t s1 = nullptr;
    static cudaEvent_t evFork = nullptr, evCsr = nullptr;
    static int inited = 0;
    if (!inited) {
        cudaFuncSetAttribute(k_gemm_mma, cudaFuncAttributeMaxDynamicSharedMemorySize,
                             SM_HALVES * 2);
        cudaStreamCreateWithFlags(&s1, cudaStreamNonBlocking);
        cudaEventCreateWithFlags(&evFork, cudaEventDisableTiming);
        cudaEventCreateWithFlags(&evCsr, cudaEventDisableTiming);
        inited = 1;
    }

    cudaEventRecord(evFork, 0);
    cudaStreamWaitEvent(s1, evFork, 0);

    k_zero_deg<<<(N_NODES + 255) / 256, 256, 0, s1>>>();
    k_hist<<<(N_EDGES + 255) / 256, 256, 0, s1>>>(col);
    k_scan1<<<SCAN_NB, 1024, 0, s1>>>();
    k_scan23<<<SCAN_NB, 1024, 0, s1>>>();
    k_scatter<<<(N_EDGES + 255) / 256, 256, 0, s1>>>(col, row, tp);
    cudaEventRecord(evCsr, s1);

    k_wprep<<<(HD * IN_F + 255) / 256, 256>>>(W, edge_emb, W_e, a_e);
    k_gemm_mma<<<(N_NODES + 127) / 128, 512, SM_HALVES * 2>>>(x, a_l, a_r);

    cudaStreamWaitEvent(0, evCsr, 0);
    k_aggregate<<<(N_NODES + 7) / 8, 256>>>(out);
    if (attOut)
        k_attout<<<(N_EDGES + 255) / 256, 256>>>(row, col, tp, attOut);
}

// round 16
// speedup vs baseline: 2.5876x; 1.1255x over previous
#include <cuda_runtime.h>
#include <cuda_fp16.h>
#include <math.h>
#include <stdint.h>

#define N_NODES 50000
#define N_EDGES 800000
#define IN_F 256
#define OUT_F 32
#define NHEAD 8
#define EDGE_F 32
#define N_ETYPES 8
#define NEG_SLOPE 0.1f

#define HD (NHEAD * OUT_F)            // 256
#define OUT_ELEMS (N_NODES * HD)
#define ATT_ELEMS (N_EDGES * NHEAD)
#define SCAN_NB ((N_NODES + 1023) / 1024)
#define PACK_MASK 0xFFFFF

// ---------------- scratch ----------------
__device__ __half    g_h16[N_NODES * HD];
__device__ float     g_hl[N_NODES * NHEAD];
__device__ float     g_hr[N_NODES * NHEAD];
__device__ float     g_z[N_NODES * NHEAD];     // stores 1/z after aggregate
__device__ float     g_he[N_ETYPES * NHEAD];
__device__ int       g_deg[N_NODES];
__device__ int       g_off[N_NODES];
__device__ int       g_wptr[N_NODES];
__device__ int       g_bsum[SCAN_NB];
__device__ int       g_spack[N_EDGES];
__device__ __half    g_wh[HD * IN_F];          // [n][k] = fp16(W[k][n])

// ---------------- K_wprep (+ he) ----------------
__global__ void k_wprep(const float* __restrict__ W,
                        const float* __restrict__ edge_emb,
                        const float* __restrict__ W_e,
                        const float* __restrict__ a_e) {
    int idx = blockIdx.x * blockDim.x + threadIdx.x;
    if (blockIdx.x == 0 && threadIdx.x < N_ETYPES * NHEAD) {
        int t = threadIdx.x >> 3, h = threadIdx.x & 7;
        float acc = 0.0f;
        for (int f = 0; f < EDGE_F; f++) {
            float ev = 0.0f;
            for (int k = 0; k < EDGE_F; k++)
                ev += edge_emb[t * EDGE_F + k] * W_e[k * (EDGE_F * NHEAD) + h * EDGE_F + f];
            acc += a_e[h * EDGE_F + f] * ev;
        }
        g_he[t * NHEAD + h] = acc;
    }
    if (idx >= HD * IN_F) return;
    int n = idx >> 8, k = idx & 255;
    g_wh[n * IN_F + k] = __float2half_rn(W[k * HD + n]);
}

// ---------------- K2: pipelined single-pass fp16 mma.sync GEMM ------------------
#define XPAD 40
#define WPAD 40
#define OFF_XH 0
#define OFF_WB (OFF_XH + 128 * XPAD)      // 5120: W double buffers start
#define WBUF_HALVES (256 * WPAD)          // 10240 per buffer
#define SM_HALVES (OFF_WB + 2 * WBUF_HALVES)  // 25600 halves = 51200 B

__device__ __forceinline__ void mma_fp16(float* d, uint32_t a0, uint32_t a1,
                                         uint32_t a2, uint32_t a3,
                                         uint32_t b0, uint32_t b1) {
    asm volatile(
        "mma.sync.aligned.m16n8k16.row.col.f32.f16.f16.f32 "
        "{%0,%1,%2,%3}, {%4,%5,%6,%7}, {%8,%9}, {%0,%1,%2,%3};"
        : "+f"(d[0]), "+f"(d[1]), "+f"(d[2]), "+f"(d[3])
        : "r"(a0), "r"(a1), "r"(a2), "r"(a3), "r"(b0), "r"(b1));
}
__device__ __forceinline__ float nanfix(float v) { return isnan(v) ? 0.0f : v; }
__device__ __forceinline__ uint32_t smem_u32(const void* p) {
    uint32_t a;
    asm("{ .reg .u64 t; cvta.to.shared.u64 t, %1; cvt.u32.u64 %0, t; }" : "=r"(a) : "l"(p));
    return a;
}
#define CP_ASYNC16(dst_u32, src_ptr) \
    asm volatile("cp.async.ca.shared.global [%0], [%1], 16;" :: "r"(dst_u32), "l"(src_ptr))
#define CP_COMMIT() asm volatile("cp.async.commit_group;")
#define CP_WAIT0()  asm volatile("cp.async.wait_group 0;")

__global__ __launch_bounds__(512) void k_gemm_mma(const float* __restrict__ x,
                                                  const float* __restrict__ a_l,
                                                  const float* __restrict__ a_r) {
    extern __shared__ __align__(16) uint16_t sm[];
    uint16_t* sXh = sm + OFF_XH;
    uint32_t sb = smem_u32(sm);

    int tid = threadIdx.x;
    int lane = tid & 31;
    int wid = tid >> 5;          // 0..15
    int warp_m = wid & 7;
    int warp_n = wid >> 3;
    int m0 = blockIdx.x * 128;

    float acc[16][4];
#pragma unroll
    for (int t = 0; t < 16; t++)
#pragma unroll
        for (int j = 0; j < 4; j++) acc[t][j] = 0.0f;

    // per-thread staging roles
    int wn = tid >> 1;                 // W: n index (0..255)
    int wj0 = (tid & 1) * 2;           // W: which 2 of 4 16B chunks
    int xr = tid >> 2, xq = tid & 3;   // x: row (0..127), quarter
    int gm = m0 + xr;
    const float4* xsrc = (gm < N_NODES)
        ? reinterpret_cast<const float4*>(x + gm * IN_F + xq * 8) : nullptr;

    float v[8];
    // ---- prologue: stage 0 ----
    {
        uint32_t dWh = sb + (OFF_WB + wn * WPAD) * 2;
        const __half* srch = g_wh + wn * IN_F;
#pragma unroll
        for (int j = 0; j < 2; j++)
            CP_ASYNC16(dWh + (wj0 + j) * 16, srch + (wj0 + j) * 8);
        CP_COMMIT();
        if (xsrc) {
            float4 f0 = xsrc[0], f1 = xsrc[1];
            v[0] = f0.x; v[1] = f0.y; v[2] = f0.z; v[3] = f0.w;
            v[4] = f1.x; v[5] = f1.y; v[6] = f1.z; v[7] = f1.w;
        } else {
#pragma unroll
            for (int j = 0; j < 8; j++) v[j] = 0.0f;
        }
        uint32_t hi[4];
#pragma unroll
        for (int j = 0; j < 4; j++) {
            __half2 p = __floats2half2_rn(v[2 * j], v[2 * j + 1]);
            hi[j] = *reinterpret_cast<uint32_t*>(&p);
        }
        *reinterpret_cast<uint4*>(&sXh[xr * XPAD + xq * 8]) = make_uint4(hi[0], hi[1], hi[2], hi[3]);
        CP_WAIT0();
        __syncthreads();
    }

    for (int ks = 0; ks < 8; ks++) {
        int buf = ks & 1;
        // prefetch next stage: W via cp.async (other buffer), x into registers
        if (ks < 7) {
            int k1 = (ks + 1) * 32;
            uint32_t dWh = sb + (OFF_WB + (1 - buf) * WBUF_HALVES + wn * WPAD) * 2;
            const __half* srch = g_wh + wn * IN_F + k1;
#pragma unroll
            for (int j = 0; j < 2; j++)
                CP_ASYNC16(dWh + (wj0 + j) * 16, srch + (wj0 + j) * 8);
            CP_COMMIT();
            if (xsrc) {
                float4 f0 = xsrc[(ks + 1) * 8];
                float4 f1 = xsrc[(ks + 1) * 8 + 1];
                v[0] = f0.x; v[1] = f0.y; v[2] = f0.z; v[3] = f0.w;
                v[4] = f1.x; v[5] = f1.y; v[6] = f1.z; v[7] = f1.w;
            }
        }
        // compute current stage: single pass
        const uint16_t* sWh = sm + OFF_WB + buf * WBUF_HALVES;
#pragma unroll
        for (int kin = 0; kin < 32; kin += 16) {
            int c = (lane & 3) * 2 + kin;
            int ra = (warp_m * 16 + (lane >> 2)) * XPAD;
            uint32_t ah0 = *reinterpret_cast<const uint32_t*>(&sXh[ra + c]);
            uint32_t ah1 = *reinterpret_cast<const uint32_t*>(&sXh[ra + 8 * XPAD + c]);
            uint32_t ah2 = *reinterpret_cast<const uint32_t*>(&sXh[ra + c + 8]);
            uint32_t ah3 = *reinterpret_cast<const uint32_t*>(&sXh[ra + 8 * XPAD + c + 8]);
#pragma unroll
            for (int t = 0; t < 16; t++) {
                int nb = (warp_n * 128 + t * 8 + (lane >> 2)) * WPAD + (lane & 3) * 2 + kin;
                uint32_t bh0 = *reinterpret_cast<const uint32_t*>(&sWh[nb]);
                uint32_t bh1 = *reinterpret_cast<const uint32_t*>(&sWh[nb + 8]);
                mma_fp16(acc[t], ah0, ah1, ah2, ah3, bh0, bh1);
            }
        }
        if (ks < 7) {
            __syncthreads();       // everyone done reading sX for stage ks
            uint32_t hi[4];
#pragma unroll
            for (int j = 0; j < 4; j++) {
                __half2 p = __floats2half2_rn(v[2 * j], v[2 * j + 1]);
                hi[j] = *reinterpret_cast<uint32_t*>(&p);
            }
            *reinterpret_cast<uint4*>(&sXh[xr * XPAD + xq * 8]) = make_uint4(hi[0], hi[1], hi[2], hi[3]);
            CP_WAIT0();
            __syncthreads();
        }
    }

    int r = lane >> 2;
    int gr0 = m0 + warp_m * 16 + r;
    int gr1 = gr0 + 8;
    bool ok0 = (gr0 < N_NODES), ok1 = (gr1 < N_NODES);
    float dl0[4] = {0, 0, 0, 0}, dl1[4] = {0, 0, 0, 0};
    float dr0[4] = {0, 0, 0, 0}, dr1[4] = {0, 0, 0, 0};
#pragma unroll
    for (int t = 0; t < 16; t++) {
        int n = warp_n * 128 + t * 8 + (lane & 3) * 2;
        float v0 = nanfix(acc[t][0]), v1 = nanfix(acc[t][1]);
        float v2 = nanfix(acc[t][2]), v3 = nanfix(acc[t][3]);
        float alv0 = __ldg(&a_l[n]), alv1 = __ldg(&a_l[n + 1]);
        float arv0 = __ldg(&a_r[n]), arv1 = __ldg(&a_r[n + 1]);
        int hh = t >> 2;
        dl0[hh] += v0 * alv0 + v1 * alv1;
        dr0[hh] += v0 * arv0 + v1 * arv1;
        dl1[hh] += v2 * alv0 + v3 * alv1;
        dr1[hh] += v2 * arv0 + v3 * arv1;
        if (ok0) *reinterpret_cast<__half2*>(&g_h16[gr0 * HD + n]) = __floats2half2_rn(v0, v1);
        if (ok1) *reinterpret_cast<__half2*>(&g_h16[gr1 * HD + n]) = __floats2half2_rn(v2, v3);
    }
#pragma unroll
    for (int hh = 0; hh < 4; hh++) {
#pragma unroll
        for (int o = 1; o <= 2; o <<= 1) {
            dl0[hh] += __shfl_xor_sync(0xffffffffu, dl0[hh], o);
            dl1[hh] += __shfl_xor_sync(0xffffffffu, dl1[hh], o);
            dr0[hh] += __shfl_xor_sync(0xffffffffu, dr0[hh], o);
            dr1[hh] += __shfl_xor_sync(0xffffffffu, dr1[hh], o);
        }
    }
    if ((lane & 3) == 0) {
#pragma unroll
        for (int hh = 0; hh < 4; hh++) {
            int head = warp_n * 4 + hh;
            if (ok0) { g_hl[gr0 * NHEAD + head] = dl0[hh]; g_hr[gr0 * NHEAD + head] = dr0[hh]; }
            if (ok1) { g_hl[gr1 * NHEAD + head] = dl1[hh]; g_hr[gr1 * NHEAD + head] = dr1[hh]; }
        }
    }
}

// ---------------- CSR build ----------------
__global__ void k_zero_deg() {
    int i = blockIdx.x * blockDim.x + threadIdx.x;
    if (i < N_NODES) g_deg[i] = 0;
}
__global__ void k_hist(const int* __restrict__ col) {
    int e = blockIdx.x * blockDim.x + threadIdx.x;
    if (e < N_EDGES) atomicAdd(&g_deg[__ldg(&col[e])], 1);
}
__global__ __launch_bounds__(1024) void k_scan1() {
    __shared__ int sh[1024];
    int t = threadIdx.x;
    int idx = blockIdx.x * 1024 + t;
    int v = (idx < N_NODES) ? g_deg[idx] : 0;
    sh[t] = v;
    __syncthreads();
#pragma unroll
    for (int off = 1; off < 1024; off <<= 1) {
        int add = (t >= off) ? sh[t - off] : 0;
        __syncthreads();
        sh[t] += add;
        __syncthreads();
    }
    if (idx < N_NODES) g_off[idx] = sh[t] - v;
    if (t == 1023) g_bsum[blockIdx.x] = sh[t];
}
__global__ __launch_bounds__(1024) void k_scan23() {
    __shared__ int s_base;
    int t = threadIdx.x;
    int bid = blockIdx.x;
    if (t < 32) {
        int v = 0;
        for (int j = t; j < SCAN_NB; j += 32)
            if (j < bid) v += g_bsum[j];
#pragma unroll
        for (int o = 16; o; o >>= 1) v += __shfl_xor_sync(0xffffffffu, v, o);
        if (t == 0) s_base = v;
    }
    __syncthreads();
    int idx = bid * 1024 + t;
    if (idx < N_NODES) {
        int o = g_off[idx] + s_base;
        g_off[idx] = o;
        g_wptr[idx] = o;
    }
}
__global__ void k_scatter(const int* __restrict__ col, const int* __restrict__ row,
                          const int* __restrict__ tp) {
    int e = blockIdx.x * blockDim.x + threadIdx.x;
    if (e >= N_EDGES) return;
    int c = __ldg(&col[e]);
    int pos = atomicAdd(&g_wptr[c], 1);
    g_spack[pos] = __ldg(&row[e]) | (__ldg(&tp[e]) << 20);
}

// ---------------- K5: fused edge-softmax + gather, WARP per node ----------------
__device__ __forceinline__ float edge_ex(float hlv, float hrv, float hev) {
    float s = hlv + hrv + hev;
    s = (s > 0.0f) ? s : NEG_SLOPE * s;
    return __expf(s);
}

__global__ __launch_bounds__(256) void k_aggregate(float* __restrict__ out) {
    int tid = threadIdx.x;
    int lane = tid & 31;
    int n = blockIdx.x * 8 + (tid >> 5);
    if (n >= N_NODES) return;
    int head = lane >> 2;

    int base = g_off[n];
    int deg = g_deg[n];
    const uint4* h4 = reinterpret_cast<const uint4*>(g_h16);
    float hrv = g_hr[n * NHEAD + head];

    float acc[8];
#pragma unroll
    for (int j = 0; j < 8; j++) acc[j] = 0.0f;
    float zacc = 0.f;

    int k = 0;
    for (; k + 4 <= deg; k += 4) {
        int v[4];
#pragma unroll
        for (int j = 0; j < 4; j++) v[j] = __ldg(&g_spack[base + k + j]);
        int r[4];
#pragma unroll
        for (int j = 0; j < 4; j++) r[j] = v[j] & PACK_MASK;
        uint4 u[4];
#pragma unroll
        for (int j = 0; j < 4; j++) u[j] = h4[r[j] * 32 + lane];
        float hl[4];
#pragma unroll
        for (int j = 0; j < 4; j++) hl[j] = __ldg(&g_hl[r[j] * NHEAD + head]);
        float ex[4];
#pragma unroll
        for (int j = 0; j < 4; j++)
            ex[j] = edge_ex(hl[j], hrv, g_he[(v[j] >> 20) * NHEAD + head]);
#pragma unroll
        for (int j = 0; j < 4; j++) {
            float2 p0 = __half22float2(*reinterpret_cast<__half2*>(&u[j].x));
            float2 p1 = __half22float2(*reinterpret_cast<__half2*>(&u[j].y));
            float2 p2 = __half22float2(*reinterpret_cast<__half2*>(&u[j].z));
            float2 p3 = __half22float2(*reinterpret_cast<__half2*>(&u[j].w));
            acc[0] += ex[j] * p0.x; acc[1] += ex[j] * p0.y;
            acc[2] += ex[j] * p1.x; acc[3] += ex[j] * p1.y;
            acc[4] += ex[j] * p2.x; acc[5] += ex[j] * p2.y;
            acc[6] += ex[j] * p3.x; acc[7] += ex[j] * p3.y;
            zacc += ex[j];
        }
    }
    for (; k < deg; k++) {
        int v0 = __ldg(&g_spack[base + k]);
        int r0 = v0 & PACK_MASK;
        float ex0 = edge_ex(__ldg(&g_hl[r0 * NHEAD + head]), hrv,
                            g_he[(v0 >> 20) * NHEAD + head]);
        uint4 u0 = h4[r0 * 32 + lane];
        float2 p0 = __half22float2(*reinterpret_cast<__half2*>(&u0.x));
        float2 p1 = __half22float2(*reinterpret_cast<__half2*>(&u0.y));
        float2 p2 = __half22float2(*reinterpret_cast<__half2*>(&u0.z));
        float2 p3 = __half22float2(*reinterpret_cast<__half2*>(&u0.w));
        acc[0] += ex0 * p0.x; acc[1] += ex0 * p0.y;
        acc[2] += ex0 * p1.x; acc[3] += ex0 * p1.y;
        acc[4] += ex0 * p2.x; acc[5] += ex0 * p2.y;
        acc[6] += ex0 * p3.x; acc[7] += ex0 * p3.y;
        zacc += ex0;
    }
    float inv = (deg > 0) ? (1.0f / zacc) : 0.0f;
    float4* o4 = reinterpret_cast<float4*>(out) + n * 64 + lane * 2;
    o4[0] = make_float4(acc[0] * inv, acc[1] * inv, acc[2] * inv, acc[3] * inv);
    o4[1] = make_float4(acc[4] * inv, acc[5] * inv, acc[6] * inv, acc[7] * inv);
    if ((lane & 3) == 0) g_z[n * NHEAD + head] = inv;   // store reciprocal
}

// ---------------- K6: att output — one thread per EDGE (8 heads) ----------------
__global__ void k_attout(const int* __restrict__ row,
                         const int* __restrict__ col,
                         const int* __restrict__ tp,
                         float* __restrict__ attOut) {
    int e = blockIdx.x * blockDim.x + threadIdx.x;
    if (e >= N_EDGES) return;
    int r = __ldg(&row[e]);
    int c = __ldg(&col[e]);
    int t = __ldg(&tp[e]);
    float4 hl0 = *reinterpret_cast<const float4*>(&g_hl[r * NHEAD]);
    float4 hl1 = *reinterpret_cast<const float4*>(&g_hl[r * NHEAD + 4]);
    float4 hr0 = *reinterpret_cast<const float4*>(&g_hr[c * NHEAD]);
    float4 hr1 = *reinterpret_cast<const float4*>(&g_hr[c * NHEAD + 4]);
    float4 z0  = *reinterpret_cast<const float4*>(&g_z[c * NHEAD]);
    float4 z1  = *reinterpret_cast<const float4*>(&g_z[c * NHEAD + 4]);
    const float* he = &g_he[t * NHEAD];
    float4 o0, o1;
    o0.x = edge_ex(hl0.x, hr0.x, he[0]) * z0.x;
    o0.y = edge_ex(hl0.y, hr0.y, he[1]) * z0.y;
    o0.z = edge_ex(hl0.z, hr0.z, he[2]) * z0.z;
    o0.w = edge_ex(hl0.w, hr0.w, he[3]) * z0.w;
    o1.x = edge_ex(hl1.x, hr1.x, he[4]) * z1.x;
    o1.y = edge_ex(hl1.y, hr1.y, he[5]) * z1.y;
    o1.z = edge_ex(hl1.z, hr1.z, he[6]) * z1.z;
    o1.w = edge_ex(hl1.w, hr1.w, he[7]) * z1.w;
    float4* dst = reinterpret_cast<float4*>(attOut + e * NHEAD);
    dst[0] = o0;
    dst[1] = o1;
}

// ---------------- launch ---------------------------------------------------------
extern "C" void kernel_launch(void* const* d_in, const int* in_sizes, int n_in,
                              void* d_out, int out_size) {
    const float* x        = (const float*)d_in[0];
    const float* W        = (const float*)d_in[1];
    const float* W_e      = (const float*)d_in[2];
    const float* edge_emb = (const float*)d_in[3];
    const float* a_l      = (const float*)d_in[4];
    const float* a_r      = (const float*)d_in[5];
    const float* a_e      = (const float*)d_in[6];
    const int*   row      = (const int*)d_in[7];
    const int*   col      = (const int*)d_in[8];
    const int*   tp       = (const int*)d_in[9];

    float* out = (float*)d_out;
    float* attOut = (out_size >= OUT_ELEMS + ATT_ELEMS) ? out + OUT_ELEMS : nullptr;

    static cudaStream_t s1 = nullptr;
    static cudaEvent_t evFork = nullptr, evCsr = nullptr;
    static int inited = 0;
    if (!inited) {
        cudaFuncSetAttribute(k_gemm_mma, cudaFuncAttributeMaxDynamicSharedMemorySize,
                             SM_HALVES * 2);
        cudaStreamCreateWithFlags(&s1, cudaStreamNonBlocking);
        cudaEventCreateWithFlags(&evFork, cudaEventDisableTiming);
        cudaEventCreateWithFlags(&evCsr, cudaEventDisableTiming);
        inited = 1;
    }

    cudaEventRecord(evFork, 0);
    cudaStreamWaitEvent(s1, evFork, 0);

    k_zero_deg<<<(N_NODES + 255) / 256, 256, 0, s1>>>();
    k_hist<<<(N_EDGES + 255) / 256, 256, 0, s1>>>(col);
    k_scan1<<<SCAN_NB, 1024, 0, s1>>>();
    k_scan23<<<SCAN_NB, 1024, 0, s1>>>();
    k_scatter<<<(N_EDGES + 255) / 256, 256, 0, s1>>>(col, row, tp);
    cudaEventRecord(evCsr, s1);

    k_wprep<<<(HD * IN_F + 255) / 256, 256>>>(W, edge_emb, W_e, a_e);
    k_gemm_mma<<<(N_NODES + 127) / 128, 512, SM_HALVES * 2>>>(x, a_l, a_r);

    cudaStreamWaitEvent(0, evCsr, 0);
    k_aggregate<<<(N_NODES + 7) / 8, 256>>>(out);
    if (attOut)
        k_attout<<<(N_EDGES + 255) / 256, 256>>>(row, col, tp, attOut);
}